// round 7
// baseline (speedup 1.0000x reference)
#include <cuda_runtime.h>
#include <cuda_bf16.h>
#include <math.h>
#include <stdint.h>

#define Tn 4096
#define Hn 2048
#define En 32
#define Fn 768
#define TOPK 4
#define NSLOT (Tn * TOPK)

// ====================== asm helpers ======================
__device__ __forceinline__ uint32_t smem_u32(const void* p) {
    uint32_t a;
    asm("{ .reg .u64 t; cvta.to.shared.u64 t, %1; cvt.u32.u64 %0, t; }"
        : "=r"(a) : "l"(p));
    return a;
}
__device__ __forceinline__ void cpa16(uint32_t dst, const void* src) {
    asm volatile("cp.async.cg.shared.global [%0], [%1], 16;"
                 :: "r"(dst), "l"(src) : "memory");
}
#define CP_COMMIT() asm volatile("cp.async.commit_group;" ::: "memory")
#define CP_WAIT0()  asm volatile("cp.async.wait_group 0;" ::: "memory")

#define LDSM_X4(r0, r1, r2, r3, a) \
    asm volatile("ldmatrix.sync.aligned.m8n8.x4.shared.b16 {%0,%1,%2,%3}, [%4];" \
                 : "=r"(r0), "=r"(r1), "=r"(r2), "=r"(r3) : "r"(a))

#define MMA_BF16(d, a, b0, b1) \
    asm volatile("mma.sync.aligned.m16n8k16.row.col.f32.bf16.bf16.f32 " \
                 "{%0,%1,%2,%3}, {%4,%5,%6,%7}, {%8,%9}, {%0,%1,%2,%3};" \
                 : "+f"((d)[0]), "+f"((d)[1]), "+f"((d)[2]), "+f"((d)[3]) \
                 : "r"((a)[0]), "r"((a)[1]), "r"((a)[2]), "r"((a)[3]), \
                   "r"(b0), "r"(b1))

// ====================== device scratch (~215 MB) ======================
__device__ int   g_counts[En];
__device__ int   g_offsets[En];
__device__ int   g_cursor[En];
__device__ int   g_topk_idx[NSLOT];
__device__ float g_topk_w[NSLOT];
__device__ int   g_tok[NSLOT];
__device__ float g_tokw[NSLOT];
__device__ int   g_tslot[NSLOT];

__device__ __align__(256) __nv_bfloat16 g_xhi[(size_t)Tn * Hn];       // 16 MB
__device__ __align__(256) __nv_bfloat16 g_xlo[(size_t)Tn * Hn];       // 16 MB
__device__ __align__(256) __nv_bfloat16 g_hdnhi[(size_t)NSLOT * Fn];  // 24 MB
__device__ __align__(256) __nv_bfloat16 g_hdnlo[(size_t)NSLOT * Fn];  // 24 MB
__device__ __align__(256) float         g_slotout[(size_t)NSLOT * Hn]; // 134 MB

// ====================== small kernels ======================
__global__ void init_kernel() {
    if (threadIdx.x < En) { g_counts[threadIdx.x] = 0; g_cursor[threadIdx.x] = 0; }
}

__device__ __forceinline__ void split1(float f, __nv_bfloat16& h, __nv_bfloat16& l) {
    h = __float2bfloat16(f);
    l = __float2bfloat16(f - __bfloat162float(h));
}

__global__ __launch_bounds__(256) void convert_x_kernel(const float* __restrict__ x) {
    size_t i = ((size_t)blockIdx.x * 256 + threadIdx.x) * 4;
    float4 v = *(const float4*)(x + i);
    __nv_bfloat16 h0, l0, h1, l1, h2, l2, h3, l3;
    split1(v.x, h0, l0); split1(v.y, h1, l1);
    split1(v.z, h2, l2); split1(v.w, h3, l3);
    g_xhi[i] = h0; g_xhi[i+1] = h1; g_xhi[i+2] = h2; g_xhi[i+3] = h3;
    g_xlo[i] = l0; g_xlo[i+1] = l1; g_xlo[i+2] = l2; g_xlo[i+3] = l3;
}

// ====================== router / scan / scatter ======================
__global__ __launch_bounds__(256) void router_kernel(
    const float* __restrict__ x, const float* __restrict__ gw,
    float* __restrict__ logits_out)
{
    int t = blockIdx.x, tid = threadIdx.x;
    int warp = tid >> 5, lane = tid & 31;
    __shared__ float sx[Hn];
    __shared__ float slog[En];
    for (int i = tid; i < Hn; i += 256) sx[i] = x[(size_t)t * Hn + i];
    __syncthreads();
    for (int e = warp; e < En; e += 8) {
        const float* w = gw + (size_t)e * Hn;
        float acc = 0.f;
        for (int k = lane; k < Hn; k += 32) acc += sx[k] * w[k];
        #pragma unroll
        for (int o = 16; o > 0; o >>= 1) acc += __shfl_xor_sync(~0u, acc, o);
        if (lane == 0) slog[e] = acc;
    }
    __syncthreads();
    if (warp == 0) {
        float l = slog[lane];
        if (logits_out) logits_out[(size_t)t * En + lane] = l;
        float m = l;
        #pragma unroll
        for (int o = 16; o > 0; o >>= 1) m = fmaxf(m, __shfl_xor_sync(~0u, m, o));
        float p = __expf(l - m), s = p;
        #pragma unroll
        for (int o = 16; o > 0; o >>= 1) s += __shfl_xor_sync(~0u, s, o);
        p /= s;
        float myp = p, tw[TOPK]; int ti[TOPK]; float wsum = 0.f;
        #pragma unroll
        for (int j = 0; j < TOPK; j++) {
            float v = myp; int idx = lane;
            #pragma unroll
            for (int o = 16; o > 0; o >>= 1) {
                float ov = __shfl_xor_sync(~0u, v, o);
                int   oi = __shfl_xor_sync(~0u, idx, o);
                if (ov > v || (ov == v && oi < idx)) { v = ov; idx = oi; }
            }
            tw[j] = v; ti[j] = idx; wsum += v;
            if (lane == idx) myp = -1.f;
        }
        if (lane < TOPK) {
            int e = ti[lane];
            g_topk_idx[t * TOPK + lane] = e;
            g_topk_w[t * TOPK + lane] = tw[lane] / wsum;
            atomicAdd(&g_counts[e], 1);
        }
    }
}

__global__ void scan_kernel() {
    int lane = threadIdx.x;
    int c = g_counts[lane], inc = c;
    #pragma unroll
    for (int o = 1; o < 32; o <<= 1) {
        int nv = __shfl_up_sync(~0u, inc, o);
        if (lane >= o) inc += nv;
    }
    g_offsets[lane] = inc - c;
}

__global__ void scatter_kernel() {
    int i = blockIdx.x * blockDim.x + threadIdx.x;
    if (i >= NSLOT) return;
    int e = g_topk_idx[i];
    int pos = atomicAdd(&g_cursor[e], 1);
    int slot = g_offsets[e] + pos;
    g_tok[slot]  = i >> 2;
    g_tokw[slot] = g_topk_w[i];
    g_tslot[i]   = slot;
}

// ====================== GEMM1: 128x64 tile, BK=16, double-buffered =======
__global__ __launch_bounds__(256) void gemm1_kernel(
    const float* __restrict__ wg, const float* __restrict__ wu)
{
    __shared__ __align__(16) __nv_bfloat16 sAh[2][128 * 16], sAl[2][128 * 16];
    __shared__ __align__(16) __nv_bfloat16 sGh[2][64 * 16],  sGl[2][64 * 16];
    __shared__ __align__(16) __nv_bfloat16 sUh[2][64 * 16],  sUl[2][64 * 16];
    __shared__ int stok[128];

    int e = blockIdx.z;
    int cnt = g_counts[e];
    int m0 = blockIdx.y * 128;
    if (m0 >= cnt) return;
    int base = g_offsets[e];
    int n0 = blockIdx.x * 64;
    int tid = threadIdx.x, wid = tid >> 5, lane = tid & 31;

    if (tid < 128) {
        int idx = base + m0 + tid;
        stok[tid] = g_tok[idx < NSLOT ? idx : NSLOT - 1];
    }
    __syncthreads();

    // A: 2 threads/row, 16B each, via cp.async
    int arow = tid >> 1, acb = (tid & 1) * 8;
    const __nv_bfloat16* pAh = g_xhi + (size_t)stok[arow] * Hn + acb;
    const __nv_bfloat16* pAl = g_xlo + (size_t)stok[arow] * Hn + acb;
    uint32_t aDst = (uint32_t)(arow * 32 + acb * 2);
    uint32_t sAh_b = smem_u32(sAh), sAl_b = smem_u32(sAl);

    // B: fp32 [K,N] -> regs -> split -> transposed smem [N,K]
    int bk = tid >> 6;   // 0..3
    int bn = tid & 63;   // 0..63
    const float* pG = wg + (size_t)e * Hn * Fn + n0 + bn;
    const float* pU = wu + (size_t)e * Hn * Fn + n0 + bn;

    int wm = wid & 1, wn = wid >> 1;
    uint32_t sGh_b = smem_u32(sGh), sGl_b = smem_u32(sGl);
    uint32_t sUh_b = smem_u32(sUh), sUl_b = smem_u32(sUl);
    uint32_t aoff[4];
    {
        int r = wm * 64 + (lane & 15);
        uint32_t c = (uint32_t)(lane >> 4) * 16;
        #pragma unroll
        for (int mt = 0; mt < 4; mt++) aoff[mt] = (uint32_t)(r + mt * 16) * 32 + c;
    }
    uint32_t boff;
    {
        int r = wn * 16 + ((lane >> 4) << 3) + (lane & 7);
        boff = (uint32_t)r * 32 + (uint32_t)((lane >> 3) & 1) * 16;
    }

    float accG[4][2][4] = {}, accU[4][2][4] = {};
    float rg[4], ru[4];

    // ---- prologue: fill buffer 0 ----
    #pragma unroll
    for (int kq = 0; kq < 4; kq++) {
        int k = kq * 4 + bk;
        rg[kq] = pG[(size_t)k * Fn];
        ru[kq] = pU[(size_t)k * Fn];
    }
    cpa16(sAh_b + aDst, pAh);
    cpa16(sAl_b + aDst, pAl);
    CP_COMMIT();
    #pragma unroll
    for (int kq = 0; kq < 4; kq++) {
        int k = kq * 4 + bk;
        __nv_bfloat16 h, l;
        split1(rg[kq], h, l); sGh[0][bn * 16 + k] = h; sGl[0][bn * 16 + k] = l;
        split1(ru[kq], h, l); sUh[0][bn * 16 + k] = h; sUl[0][bn * 16 + k] = l;
    }
    CP_WAIT0();
    __syncthreads();

    const int nch = Hn / 16;  // 128
    for (int c = 0; c < nch; c++) {
        int s = c & 1;
        int sn = s ^ 1;
        if (c + 1 < nch) {
            int k0n = (c + 1) * 16;
            #pragma unroll
            for (int kq = 0; kq < 4; kq++) {
                int k = k0n + kq * 4 + bk;
                rg[kq] = pG[(size_t)k * Fn];
                ru[kq] = pU[(size_t)k * Fn];
            }
            cpa16(sAh_b + sn * 4096 + aDst, pAh + k0n);
            cpa16(sAl_b + sn * 4096 + aDst, pAl + k0n);
            CP_COMMIT();
        }

        // ---- compute from buffer s ----
        uint32_t sA = (uint32_t)s * 4096, sB = (uint32_t)s * 2048;
        uint32_t ah[4][4], al[4][4];
        #pragma unroll
        for (int mt = 0; mt < 4; mt++) {
            LDSM_X4(ah[mt][0], ah[mt][1], ah[mt][2], ah[mt][3], sAh_b + sA + aoff[mt]);
            LDSM_X4(al[mt][0], al[mt][1], al[mt][2], al[mt][3], sAl_b + sA + aoff[mt]);
        }
        uint32_t bgh[4], bgl[4], buh[4], bul[4];
        LDSM_X4(bgh[0], bgh[1], bgh[2], bgh[3], sGh_b + sB + boff);
        LDSM_X4(bgl[0], bgl[1], bgl[2], bgl[3], sGl_b + sB + boff);
        LDSM_X4(buh[0], buh[1], buh[2], buh[3], sUh_b + sB + boff);
        LDSM_X4(bul[0], bul[1], bul[2], bul[3], sUl_b + sB + boff);
        #pragma unroll
        for (int mt = 0; mt < 4; mt++) {
            #pragma unroll
            for (int nt = 0; nt < 2; nt++) {
                MMA_BF16(accG[mt][nt], ah[mt], bgh[nt * 2], bgh[nt * 2 + 1]);
                MMA_BF16(accG[mt][nt], ah[mt], bgl[nt * 2], bgl[nt * 2 + 1]);
                MMA_BF16(accG[mt][nt], al[mt], bgh[nt * 2], bgh[nt * 2 + 1]);
                MMA_BF16(accU[mt][nt], ah[mt], buh[nt * 2], buh[nt * 2 + 1]);
                MMA_BF16(accU[mt][nt], ah[mt], bul[nt * 2], bul[nt * 2 + 1]);
                MMA_BF16(accU[mt][nt], al[mt], buh[nt * 2], buh[nt * 2 + 1]);
            }
        }

        if (c + 1 < nch) {
            #pragma unroll
            for (int kq = 0; kq < 4; kq++) {
                int k = kq * 4 + bk;
                __nv_bfloat16 h, l;
                split1(rg[kq], h, l); sGh[sn][bn * 16 + k] = h; sGl[sn][bn * 16 + k] = l;
                split1(ru[kq], h, l); sUh[sn][bn * 16 + k] = h; sUl[sn][bn * 16 + k] = l;
            }
            CP_WAIT0();
        }
        __syncthreads();
    }

    // ---- epilogue: h = w * silu(g) * u -> hdn hi/lo ----
    int r = lane >> 2, cp2 = (lane & 3) * 2;
    #pragma unroll
    for (int mt = 0; mt < 4; mt++) {
        #pragma unroll
        for (int half = 0; half < 2; half++) {
            int grow = m0 + wm * 64 + mt * 16 + r + half * 8;
            if (grow >= cnt) continue;
            int slot = base + grow;
            float wgt = g_tokw[slot];
            size_t ob = (size_t)slot * Fn + n0 + wn * 16 + cp2;
            #pragma unroll
            for (int nt = 0; nt < 2; nt++) {
                float g0 = accG[mt][nt][half * 2 + 0];
                float g1 = accG[mt][nt][half * 2 + 1];
                float u0 = accU[mt][nt][half * 2 + 0];
                float u1 = accU[mt][nt][half * 2 + 1];
                float h0 = wgt * (g0 / (1.f + __expf(-g0))) * u0;
                float h1 = wgt * (g1 / (1.f + __expf(-g1))) * u1;
                __nv_bfloat16 bh, bl;
                split1(h0, bh, bl);
                g_hdnhi[ob + nt * 8]     = bh;
                g_hdnlo[ob + nt * 8]     = bl;
                split1(h1, bh, bl);
                g_hdnhi[ob + nt * 8 + 1] = bh;
                g_hdnlo[ob + nt * 8 + 1] = bl;
            }
        }
    }
}

// ====================== GEMM2: 128x128 tile, BK=16, double-buffered ======
__global__ __launch_bounds__(256) void gemm2_kernel(const float* __restrict__ wd) {
    __shared__ __align__(16) __nv_bfloat16 sAh[2][128 * 16], sAl[2][128 * 16];
    __shared__ __align__(16) __nv_bfloat16 sBh[2][128 * 16], sBl[2][128 * 16];

    int e = blockIdx.z;
    int cnt = g_counts[e];
    int m0 = blockIdx.y * 128;
    if (m0 >= cnt) return;
    int base = g_offsets[e];
    int n0 = blockIdx.x * 128;
    int tid = threadIdx.x, wid = tid >> 5, lane = tid & 31;

    int arow = tid >> 1, acb = (tid & 1) * 8;
    int sl = base + m0 + arow; if (sl >= NSLOT) sl = NSLOT - 1;
    const __nv_bfloat16* pAh = g_hdnhi + (size_t)sl * Fn + acb;
    const __nv_bfloat16* pAl = g_hdnlo + (size_t)sl * Fn + acb;
    uint32_t aDst = (uint32_t)(arow * 32 + acb * 2);
    uint32_t sAh_b = smem_u32(sAh), sAl_b = smem_u32(sAl);

    int bk = tid >> 7;    // 0..1
    int bn = tid & 127;   // 0..127
    const float* pB = wd + (size_t)e * Fn * Hn + n0 + bn;
    uint32_t sBh_b = smem_u32(sBh), sBl_b = smem_u32(sBl);

    int wm = wid & 1, wn = wid >> 1;
    uint32_t aoff[4];
    {
        int r = wm * 64 + (lane & 15);
        uint32_t c = (uint32_t)(lane >> 4) * 16;
        #pragma unroll
        for (int mt = 0; mt < 4; mt++) aoff[mt] = (uint32_t)(r + mt * 16) * 32 + c;
    }
    uint32_t boff[2];
    {
        int rb = ((lane >> 4) << 3) + (lane & 7);
        uint32_t c = (uint32_t)((lane >> 3) & 1) * 16;
        boff[0] = (uint32_t)(wn * 32 + rb) * 32 + c;
        boff[1] = (uint32_t)(wn * 32 + 16 + rb) * 32 + c;
    }

    float acc[4][4][4] = {};
    float rb8[8];

    // ---- prologue ----
    #pragma unroll
    for (int kq = 0; kq < 8; kq++)
        rb8[kq] = pB[(size_t)(kq * 2 + bk) * Hn];
    cpa16(sAh_b + aDst, pAh);
    cpa16(sAl_b + aDst, pAl);
    CP_COMMIT();
    #pragma unroll
    for (int kq = 0; kq < 8; kq++) {
        int k = kq * 2 + bk;
        __nv_bfloat16 h, l;
        split1(rb8[kq], h, l);
        sBh[0][bn * 16 + k] = h;
        sBl[0][bn * 16 + k] = l;
    }
    CP_WAIT0();
    __syncthreads();

    const int nch = Fn / 16;  // 48
    for (int c = 0; c < nch; c++) {
        int s = c & 1;
        int sn = s ^ 1;
        if (c + 1 < nch) {
            int k0n = (c + 1) * 16;
            #pragma unroll
            for (int kq = 0; kq < 8; kq++)
                rb8[kq] = pB[(size_t)(k0n + kq * 2 + bk) * Hn];
            cpa16(sAh_b + sn * 4096 + aDst, pAh + k0n);
            cpa16(sAl_b + sn * 4096 + aDst, pAl + k0n);
            CP_COMMIT();
        }

        uint32_t sA = (uint32_t)s * 4096;
        uint32_t ah[4][4], al[4][4];
        #pragma unroll
        for (int mt = 0; mt < 4; mt++) {
            LDSM_X4(ah[mt][0], ah[mt][1], ah[mt][2], ah[mt][3], sAh_b + sA + aoff[mt]);
            LDSM_X4(al[mt][0], al[mt][1], al[mt][2], al[mt][3], sAl_b + sA + aoff[mt]);
        }
        uint32_t bh[2][4], bl[2][4];
        #pragma unroll
        for (int p = 0; p < 2; p++) {
            LDSM_X4(bh[p][0], bh[p][1], bh[p][2], bh[p][3], sBh_b + sA + boff[p]);
            LDSM_X4(bl[p][0], bl[p][1], bl[p][2], bl[p][3], sBl_b + sA + boff[p]);
        }
        #pragma unroll
        for (int mt = 0; mt < 4; mt++) {
            #pragma unroll
            for (int nt = 0; nt < 4; nt++) {
                uint32_t* BH = &bh[nt >> 1][(nt & 1) * 2];
                uint32_t* BL = &bl[nt >> 1][(nt & 1) * 2];
                MMA_BF16(acc[mt][nt], ah[mt], BH[0], BH[1]);
                MMA_BF16(acc[mt][nt], ah[mt], BL[0], BL[1]);
                MMA_BF16(acc[mt][nt], al[mt], BH[0], BH[1]);
            }
        }

        if (c + 1 < nch) {
            #pragma unroll
            for (int kq = 0; kq < 8; kq++) {
                int k = kq * 2 + bk;
                __nv_bfloat16 h, l;
                split1(rb8[kq], h, l);
                sBh[sn][bn * 16 + k] = h;
                sBl[sn][bn * 16 + k] = l;
            }
            CP_WAIT0();
        }
        __syncthreads();
    }

    // ---- epilogue: stream fp32 to slot buffer (no atomics) ----
    int r = lane >> 2, cp2 = (lane & 3) * 2;
    #pragma unroll
    for (int mt = 0; mt < 4; mt++) {
        #pragma unroll
        for (int half = 0; half < 2; half++) {
            int grow = m0 + wm * 64 + mt * 16 + r + half * 8;
            if (grow >= cnt) continue;
            size_t ob = (size_t)(base + grow) * Hn + n0 + wn * 32 + cp2;
            #pragma unroll
            for (int nt = 0; nt < 4; nt++) {
                float v0 = acc[mt][nt][half * 2 + 0];
                float v1 = acc[mt][nt][half * 2 + 1];
                *(float2*)(g_slotout + ob + nt * 8) = make_float2(v0, v1);
            }
        }
    }
}

// ====================== reduce: sum 4 slots per token ======================
__global__ __launch_bounds__(256) void reduce_kernel(float* __restrict__ out) {
    int t = blockIdx.x;
    int s0 = g_tslot[t * 4 + 0], s1 = g_tslot[t * 4 + 1];
    int s2 = g_tslot[t * 4 + 2], s3 = g_tslot[t * 4 + 3];
    const float* p0 = g_slotout + (size_t)s0 * Hn;
    const float* p1 = g_slotout + (size_t)s1 * Hn;
    const float* p2 = g_slotout + (size_t)s2 * Hn;
    const float* p3 = g_slotout + (size_t)s3 * Hn;
    float* o = out + (size_t)t * Hn;
    for (int i = threadIdx.x * 4; i < Hn; i += 256 * 4) {
        float4 a = *(const float4*)(p0 + i);
        float4 b = *(const float4*)(p1 + i);
        float4 c = *(const float4*)(p2 + i);
        float4 d = *(const float4*)(p3 + i);
        *(float4*)(o + i) = make_float4(a.x + b.x + c.x + d.x,
                                        a.y + b.y + c.y + d.y,
                                        a.z + b.z + c.z + d.z,
                                        a.w + b.w + c.w + d.w);
    }
}

// ====================== launcher ======================
extern "C" void kernel_launch(void* const* d_in, const int* in_sizes, int n_in,
                              void* d_out, int out_size) {
    const float* x  = (const float*)d_in[0];  // hidden_states
    const float* gw = (const float*)d_in[1];  // gate_w [E,H]
    const float* wg = (const float*)d_in[2];  // w_gate [E,H,F]
    const float* wu = (const float*)d_in[3];  // w_up   [E,H,F]
    const float* wd = (const float*)d_in[4];  // w_down [E,F,H]
    float* out = (float*)d_out;

    float* logits_out = nullptr;
    if (out_size >= Tn * Hn + Tn * En) logits_out = out + (size_t)Tn * Hn;

    init_kernel<<<1, 32>>>();
    convert_x_kernel<<<(Tn * Hn) / 1024, 256>>>(x);
    router_kernel<<<Tn, 256>>>(x, gw, logits_out);
    scan_kernel<<<1, 32>>>();
    scatter_kernel<<<(NSLOT + 255) / 256, 256>>>();
    gemm1_kernel<<<dim3(Fn / 64, NSLOT / 128, En), 256>>>(wg, wu);
    gemm2_kernel<<<dim3(Hn / 128, NSLOT / 128, En), 256>>>(wd);
    reduce_kernel<<<Tn, 256>>>(out);
}

// round 8
// speedup vs baseline: 1.9213x; 1.9213x over previous
#include <cuda_runtime.h>
#include <cuda_bf16.h>
#include <math.h>
#include <stdint.h>

#define Tn 4096
#define Hn 2048
#define En 32
#define Fn 768
#define TOPK 4
#define NSLOT (Tn * TOPK)

// ====================== asm helpers ======================
__device__ __forceinline__ uint32_t smem_u32(const void* p) {
    uint32_t a;
    asm("{ .reg .u64 t; cvta.to.shared.u64 t, %1; cvt.u32.u64 %0, t; }"
        : "=r"(a) : "l"(p));
    return a;
}
__device__ __forceinline__ void cpa16(uint32_t dst, const void* src) {
    asm volatile("cp.async.cg.shared.global [%0], [%1], 16;"
                 :: "r"(dst), "l"(src) : "memory");
}
#define CP_COMMIT() asm volatile("cp.async.commit_group;" ::: "memory")
#define CP_WAIT0()  asm volatile("cp.async.wait_group 0;" ::: "memory")

#define LDSM_X4(r0, r1, r2, r3, a) \
    asm volatile("ldmatrix.sync.aligned.m8n8.x4.shared.b16 {%0,%1,%2,%3}, [%4];" \
                 : "=r"(r0), "=r"(r1), "=r"(r2), "=r"(r3) : "r"(a))
#define LDSM_X4_T(r0, r1, r2, r3, a) \
    asm volatile("ldmatrix.sync.aligned.m8n8.x4.trans.shared.b16 {%0,%1,%2,%3}, [%4];" \
                 : "=r"(r0), "=r"(r1), "=r"(r2), "=r"(r3) : "r"(a))

#define MMA_BF16(d, a, b0, b1) \
    asm volatile("mma.sync.aligned.m16n8k16.row.col.f32.bf16.bf16.f32 " \
                 "{%0,%1,%2,%3}, {%4,%5,%6,%7}, {%8,%9}, {%0,%1,%2,%3};" \
                 : "+f"((d)[0]), "+f"((d)[1]), "+f"((d)[2]), "+f"((d)[3]) \
                 : "r"((a)[0]), "r"((a)[1]), "r"((a)[2]), "r"((a)[3]), \
                   "r"(b0), "r"(b1))

// ====================== device scratch (~215 MB) ======================
__device__ int   g_counts[En];
__device__ int   g_offsets[En];
__device__ int   g_cursor[En];
__device__ int   g_topk_idx[NSLOT];
__device__ float g_topk_w[NSLOT];
__device__ int   g_tok[NSLOT];
__device__ float g_tokw[NSLOT];
__device__ int   g_tslot[NSLOT];

__device__ __align__(256) __nv_bfloat16 g_xhi[(size_t)Tn * Hn];
__device__ __align__(256) __nv_bfloat16 g_xlo[(size_t)Tn * Hn];
__device__ __align__(256) __nv_bfloat16 g_hdnhi[(size_t)NSLOT * Fn];
__device__ __align__(256) __nv_bfloat16 g_hdnlo[(size_t)NSLOT * Fn];
__device__ __align__(256) float         g_slotout[(size_t)NSLOT * Hn];

// ====================== small kernels ======================
__global__ void init_kernel() {
    if (threadIdx.x < En) { g_counts[threadIdx.x] = 0; g_cursor[threadIdx.x] = 0; }
}

__device__ __forceinline__ void split1(float f, __nv_bfloat16& h, __nv_bfloat16& l) {
    h = __float2bfloat16(f);
    l = __float2bfloat16(f - __bfloat162float(h));
}
__device__ __forceinline__ void split2(float a, float b, uint32_t& hp, uint32_t& lp) {
    __nv_bfloat162 h = __floats2bfloat162_rn(a, b);
    float r0 = a - __bfloat162float(__low2bfloat16(h));
    float r1 = b - __bfloat162float(__high2bfloat16(h));
    __nv_bfloat162 l = __floats2bfloat162_rn(r0, r1);
    hp = *(uint32_t*)&h; lp = *(uint32_t*)&l;
}
// split float4 -> hi/lo pairs, vectorized STS.32 (conflict-free: consecutive n)
__device__ __forceinline__ void stsplit4(__nv_bfloat16* ph, __nv_bfloat16* pl,
                                         uint32_t idx, float4 v) {
    uint32_t h0, l0, h1, l1;
    split2(v.x, v.y, h0, l0);
    split2(v.z, v.w, h1, l1);
    *(uint32_t*)(ph + idx)     = h0;
    *(uint32_t*)(ph + idx + 2) = h1;
    *(uint32_t*)(pl + idx)     = l0;
    *(uint32_t*)(pl + idx + 2) = l1;
}

__global__ __launch_bounds__(256) void convert_x_kernel(const float* __restrict__ x) {
    size_t i = ((size_t)blockIdx.x * 256 + threadIdx.x) * 4;
    float4 v = *(const float4*)(x + i);
    __nv_bfloat16 h0, l0, h1, l1, h2, l2, h3, l3;
    split1(v.x, h0, l0); split1(v.y, h1, l1);
    split1(v.z, h2, l2); split1(v.w, h3, l3);
    g_xhi[i] = h0; g_xhi[i+1] = h1; g_xhi[i+2] = h2; g_xhi[i+3] = h3;
    g_xlo[i] = l0; g_xlo[i+1] = l1; g_xlo[i+2] = l2; g_xlo[i+3] = l3;
}

// ====================== router / scan / scatter ======================
__global__ __launch_bounds__(256) void router_kernel(
    const float* __restrict__ x, const float* __restrict__ gw,
    float* __restrict__ logits_out)
{
    int t = blockIdx.x, tid = threadIdx.x;
    int warp = tid >> 5, lane = tid & 31;
    __shared__ float sx[Hn];
    __shared__ float slog[En];
    for (int i = tid; i < Hn; i += 256) sx[i] = x[(size_t)t * Hn + i];
    __syncthreads();
    for (int e = warp; e < En; e += 8) {
        const float* w = gw + (size_t)e * Hn;
        float acc = 0.f;
        for (int k = lane; k < Hn; k += 32) acc += sx[k] * w[k];
        #pragma unroll
        for (int o = 16; o > 0; o >>= 1) acc += __shfl_xor_sync(~0u, acc, o);
        if (lane == 0) slog[e] = acc;
    }
    __syncthreads();
    if (warp == 0) {
        float l = slog[lane];
        if (logits_out) logits_out[(size_t)t * En + lane] = l;
        float m = l;
        #pragma unroll
        for (int o = 16; o > 0; o >>= 1) m = fmaxf(m, __shfl_xor_sync(~0u, m, o));
        float p = __expf(l - m), s = p;
        #pragma unroll
        for (int o = 16; o > 0; o >>= 1) s += __shfl_xor_sync(~0u, s, o);
        p /= s;
        float myp = p, tw[TOPK]; int ti[TOPK]; float wsum = 0.f;
        #pragma unroll
        for (int j = 0; j < TOPK; j++) {
            float v = myp; int idx = lane;
            #pragma unroll
            for (int o = 16; o > 0; o >>= 1) {
                float ov = __shfl_xor_sync(~0u, v, o);
                int   oi = __shfl_xor_sync(~0u, idx, o);
                if (ov > v || (ov == v && oi < idx)) { v = ov; idx = oi; }
            }
            tw[j] = v; ti[j] = idx; wsum += v;
            if (lane == idx) myp = -1.f;
        }
        if (lane < TOPK) {
            int e = ti[lane];
            g_topk_idx[t * TOPK + lane] = e;
            g_topk_w[t * TOPK + lane] = tw[lane] / wsum;
            atomicAdd(&g_counts[e], 1);
        }
    }
}

__global__ void scan_kernel() {
    int lane = threadIdx.x;
    int c = g_counts[lane], inc = c;
    #pragma unroll
    for (int o = 1; o < 32; o <<= 1) {
        int nv = __shfl_up_sync(~0u, inc, o);
        if (lane >= o) inc += nv;
    }
    g_offsets[lane] = inc - c;
}

__global__ void scatter_kernel() {
    int i = blockIdx.x * blockDim.x + threadIdx.x;
    if (i >= NSLOT) return;
    int e = g_topk_idx[i];
    int pos = atomicAdd(&g_cursor[e], 1);
    int slot = g_offsets[e] + pos;
    g_tok[slot]  = i >> 2;
    g_tokw[slot] = g_topk_w[i];
    g_tslot[i]   = slot;
}

// A rows padded to 48B (24 bf16): banks r*12 mod 32 all distinct for r mod 8
#define A_ROWE 24
#define A_PLANE (128 * A_ROWE)       // elements per plane per buffer
// gemm1 B rows padded to 144B (72 bf16)
#define B1_ROWE 72
#define B1_PLANE (16 * B1_ROWE)
// gemm2 B rows padded to 272B (136 bf16)
#define B2_ROWE 136
#define B2_PLANE (16 * B2_ROWE)

// ====================== GEMM1: 128x64 tile, BK=16 ======================
__global__ __launch_bounds__(256) void gemm1_kernel(
    const float* __restrict__ wg, const float* __restrict__ wu)
{
    __shared__ __align__(16) __nv_bfloat16 sAh[2][A_PLANE], sAl[2][A_PLANE];
    __shared__ __align__(16) __nv_bfloat16 sGh[2][B1_PLANE], sGl[2][B1_PLANE];
    __shared__ __align__(16) __nv_bfloat16 sUh[2][B1_PLANE], sUl[2][B1_PLANE];
    __shared__ int stok[128];

    int e = blockIdx.z;
    int cnt = g_counts[e];
    int m0 = blockIdx.y * 128;
    if (m0 >= cnt) return;
    int base = g_offsets[e];
    int n0 = blockIdx.x * 64;
    int tid = threadIdx.x, wid = tid >> 5, lane = tid & 31;

    if (tid < 128) {
        int idx = base + m0 + tid;
        stok[tid] = g_tok[idx < NSLOT ? idx : NSLOT - 1];
    }
    __syncthreads();

    // ---- A loader: 2 threads/row, 16B cp.async each ----
    int arow = tid >> 1, acs = tid & 1;
    const __nv_bfloat16* pAh = g_xhi + (size_t)stok[arow] * Hn + acs * 8;
    const __nv_bfloat16* pAl = g_xlo + (size_t)stok[arow] * Hn + acs * 8;
    uint32_t aDst = (uint32_t)(arow * 48 + acs * 16);
    uint32_t sAh_b = smem_u32(sAh), sAl_b = smem_u32(sAl);

    // ---- B loader: [K][N] direct, float4 per thread per matrix ----
    int bkr = tid >> 4, bn4 = (tid & 15) * 4;
    const float* pG = wg + (size_t)e * Hn * Fn + n0 + bn4;
    const float* pU = wu + (size_t)e * Hn * Fn + n0 + bn4;
    uint32_t bIdx = (uint32_t)(bkr * B1_ROWE + bn4);

    // ---- compute maps ----
    int wm = wid & 1, wn = wid >> 1;   // 2x4 warps: 64 m-rows x 16 n-cols
    uint32_t aoff[4];
    {
        int r = wm * 64 + (lane & 15);
        uint32_t c = (uint32_t)(lane >> 4) * 16;
        #pragma unroll
        for (int mt = 0; mt < 4; mt++) aoff[mt] = (uint32_t)(r + mt * 16) * 48 + c;
    }
    uint32_t boff = (uint32_t)(lane & 15) * 144 + (uint32_t)wn * 32 +
                    (uint32_t)(lane >> 4) * 16;
    uint32_t sGh_b = smem_u32(sGh), sGl_b = smem_u32(sGl);
    uint32_t sUh_b = smem_u32(sUh), sUl_b = smem_u32(sUl);

    float accG[4][2][4] = {}, accU[4][2][4] = {};

    // ---- prologue: buffer 0 ----
    {
        float4 vg = *(const float4*)(pG + (size_t)bkr * Fn);
        float4 vu = *(const float4*)(pU + (size_t)bkr * Fn);
        cpa16(sAh_b + aDst, pAh);
        cpa16(sAl_b + aDst, pAl);
        CP_COMMIT();
        stsplit4(sGh[0], sGl[0], bIdx, vg);
        stsplit4(sUh[0], sUl[0], bIdx, vu);
        CP_WAIT0();
    }
    __syncthreads();

    const int nch = Hn / 16;  // 128
    for (int c = 0; c < nch; c++) {
        int s = c & 1, sn = s ^ 1;
        bool more = (c + 1 < nch);
        float4 vg, vu;
        if (more) {
            size_t ko = (size_t)((c + 1) * 16 + bkr) * Fn;
            vg = *(const float4*)(pG + ko);
            vu = *(const float4*)(pU + ko);
            cpa16(sAh_b + sn * (A_PLANE * 2) + aDst, pAh + (c + 1) * 16);
            cpa16(sAl_b + sn * (A_PLANE * 2) + aDst, pAl + (c + 1) * 16);
            CP_COMMIT();
        }

        // ---- compute buffer s ----
        uint32_t sAo = (uint32_t)s * (A_PLANE * 2);
        uint32_t sBo = (uint32_t)s * (B1_PLANE * 2);
        uint32_t bgh[4], bgl[4], buh[4], bul[4];
        LDSM_X4_T(bgh[0], bgh[1], bgh[2], bgh[3], sGh_b + sBo + boff);
        LDSM_X4_T(bgl[0], bgl[1], bgl[2], bgl[3], sGl_b + sBo + boff);
        LDSM_X4_T(buh[0], buh[1], buh[2], buh[3], sUh_b + sBo + boff);
        LDSM_X4_T(bul[0], bul[1], bul[2], bul[3], sUl_b + sBo + boff);
        #pragma unroll
        for (int mt = 0; mt < 4; mt++) {
            uint32_t ah[4], al[4];
            LDSM_X4(ah[0], ah[1], ah[2], ah[3], sAh_b + sAo + aoff[mt]);
            LDSM_X4(al[0], al[1], al[2], al[3], sAl_b + sAo + aoff[mt]);
            #pragma unroll
            for (int nt = 0; nt < 2; nt++) {
                MMA_BF16(accG[mt][nt], ah, bgh[nt * 2], bgh[nt * 2 + 1]);
                MMA_BF16(accG[mt][nt], ah, bgl[nt * 2], bgl[nt * 2 + 1]);
                MMA_BF16(accG[mt][nt], al, bgh[nt * 2], bgh[nt * 2 + 1]);
                MMA_BF16(accU[mt][nt], ah, buh[nt * 2], buh[nt * 2 + 1]);
                MMA_BF16(accU[mt][nt], ah, bul[nt * 2], bul[nt * 2 + 1]);
                MMA_BF16(accU[mt][nt], al, buh[nt * 2], buh[nt * 2 + 1]);
            }
        }

        if (more) {
            stsplit4(sGh[sn], sGl[sn], bIdx, vg);
            stsplit4(sUh[sn], sUl[sn], bIdx, vu);
            CP_WAIT0();
        }
        __syncthreads();
    }

    // ---- epilogue: h = w * silu(g) * u -> hdn hi/lo ----
    int r = lane >> 2, cp2 = (lane & 3) * 2;
    #pragma unroll
    for (int mt = 0; mt < 4; mt++) {
        #pragma unroll
        for (int half = 0; half < 2; half++) {
            int grow = m0 + wm * 64 + mt * 16 + r + half * 8;
            if (grow >= cnt) continue;
            int slot = base + grow;
            float wgt = g_tokw[slot];
            size_t ob = (size_t)slot * Fn + n0 + wn * 16 + cp2;
            #pragma unroll
            for (int nt = 0; nt < 2; nt++) {
                float g0 = accG[mt][nt][half * 2 + 0];
                float g1 = accG[mt][nt][half * 2 + 1];
                float u0 = accU[mt][nt][half * 2 + 0];
                float u1 = accU[mt][nt][half * 2 + 1];
                float h0 = wgt * (g0 / (1.f + __expf(-g0))) * u0;
                float h1 = wgt * (g1 / (1.f + __expf(-g1))) * u1;
                __nv_bfloat16 bh, bl;
                split1(h0, bh, bl);
                g_hdnhi[ob + nt * 8]     = bh;
                g_hdnlo[ob + nt * 8]     = bl;
                split1(h1, bh, bl);
                g_hdnhi[ob + nt * 8 + 1] = bh;
                g_hdnlo[ob + nt * 8 + 1] = bl;
            }
        }
    }
}

// ====================== GEMM2: 128x128 tile, BK=16 ======================
__global__ __launch_bounds__(256) void gemm2_kernel(const float* __restrict__ wd) {
    __shared__ __align__(16) __nv_bfloat16 sAh[2][A_PLANE], sAl[2][A_PLANE];
    __shared__ __align__(16) __nv_bfloat16 sBh[2][B2_PLANE], sBl[2][B2_PLANE];

    int e = blockIdx.z;
    int cnt = g_counts[e];
    int m0 = blockIdx.y * 128;
    if (m0 >= cnt) return;
    int base = g_offsets[e];
    int n0 = blockIdx.x * 128;
    int tid = threadIdx.x, wid = tid >> 5, lane = tid & 31;

    int arow = tid >> 1, acs = tid & 1;
    int sl = base + m0 + arow; if (sl >= NSLOT) sl = NSLOT - 1;
    const __nv_bfloat16* pAh = g_hdnhi + (size_t)sl * Fn + acs * 8;
    const __nv_bfloat16* pAl = g_hdnlo + (size_t)sl * Fn + acs * 8;
    uint32_t aDst = (uint32_t)(arow * 48 + acs * 16);
    uint32_t sAh_b = smem_u32(sAh), sAl_b = smem_u32(sAl);

    int bkr = tid >> 4, bn4 = (tid & 15) * 4;
    const float* pB = wd + (size_t)e * Fn * Hn + n0 + bn4;
    uint32_t bIdx = (uint32_t)(bkr * B2_ROWE + bn4);
    uint32_t sBh_b = smem_u32(sBh), sBl_b = smem_u32(sBl);

    int wm = wid & 1, wn = wid >> 1;   // 64 m-rows x 32 n-cols per warp
    uint32_t aoff[4];
    {
        int r = wm * 64 + (lane & 15);
        uint32_t c = (uint32_t)(lane >> 4) * 16;
        #pragma unroll
        for (int mt = 0; mt < 4; mt++) aoff[mt] = (uint32_t)(r + mt * 16) * 48 + c;
    }
    uint32_t boff[2];
    {
        uint32_t rb = (uint32_t)(lane & 15) * 272 + (uint32_t)(lane >> 4) * 16;
        boff[0] = rb + (uint32_t)wn * 64;
        boff[1] = rb + (uint32_t)wn * 64 + 32;
    }

    float acc[4][4][4] = {};

    // ---- prologue ----
    {
        size_t ko = (size_t)bkr * Hn;
        float4 v0 = *(const float4*)(pB + ko);
        float4 v1 = *(const float4*)(pB + ko + 64);
        cpa16(sAh_b + aDst, pAh);
        cpa16(sAl_b + aDst, pAl);
        CP_COMMIT();
        stsplit4(sBh[0], sBl[0], bIdx, v0);
        stsplit4(sBh[0], sBl[0], bIdx + 64, v1);
        CP_WAIT0();
    }
    __syncthreads();

    const int nch = Fn / 16;  // 48
    for (int c = 0; c < nch; c++) {
        int s = c & 1, sn = s ^ 1;
        bool more = (c + 1 < nch);
        float4 v0, v1;
        if (more) {
            size_t ko = (size_t)((c + 1) * 16 + bkr) * Hn;
            v0 = *(const float4*)(pB + ko);
            v1 = *(const float4*)(pB + ko + 64);
            cpa16(sAh_b + sn * (A_PLANE * 2) + aDst, pAh + (c + 1) * 16);
            cpa16(sAl_b + sn * (A_PLANE * 2) + aDst, pAl + (c + 1) * 16);
            CP_COMMIT();
        }

        uint32_t sAo = (uint32_t)s * (A_PLANE * 2);
        uint32_t sBo = (uint32_t)s * (B2_PLANE * 2);
        uint32_t bh[2][4], bl[2][4];
        #pragma unroll
        for (int p = 0; p < 2; p++) {
            LDSM_X4_T(bh[p][0], bh[p][1], bh[p][2], bh[p][3], sBh_b + sBo + boff[p]);
            LDSM_X4_T(bl[p][0], bl[p][1], bl[p][2], bl[p][3], sBl_b + sBo + boff[p]);
        }
        #pragma unroll
        for (int mt = 0; mt < 4; mt++) {
            uint32_t ah[4], al[4];
            LDSM_X4(ah[0], ah[1], ah[2], ah[3], sAh_b + sAo + aoff[mt]);
            LDSM_X4(al[0], al[1], al[2], al[3], sAl_b + sAo + aoff[mt]);
            #pragma unroll
            for (int nt = 0; nt < 4; nt++) {
                uint32_t* BH = &bh[nt >> 1][(nt & 1) * 2];
                uint32_t* BL = &bl[nt >> 1][(nt & 1) * 2];
                MMA_BF16(acc[mt][nt], ah, BH[0], BH[1]);
                MMA_BF16(acc[mt][nt], ah, BL[0], BL[1]);
                MMA_BF16(acc[mt][nt], al, BH[0], BH[1]);
            }
        }

        if (more) {
            stsplit4(sBh[sn], sBl[sn], bIdx, v0);
            stsplit4(sBh[sn], sBl[sn], bIdx + 64, v1);
            CP_WAIT0();
        }
        __syncthreads();
    }

    // ---- epilogue: stream fp32 to slot buffer ----
    int r = lane >> 2, cp2 = (lane & 3) * 2;
    #pragma unroll
    for (int mt = 0; mt < 4; mt++) {
        #pragma unroll
        for (int half = 0; half < 2; half++) {
            int grow = m0 + wm * 64 + mt * 16 + r + half * 8;
            if (grow >= cnt) continue;
            size_t ob = (size_t)(base + grow) * Hn + n0 + wn * 32 + cp2;
            #pragma unroll
            for (int nt = 0; nt < 4; nt++) {
                float v0 = acc[mt][nt][half * 2 + 0];
                float v1 = acc[mt][nt][half * 2 + 1];
                *(float2*)(g_slotout + ob + nt * 8) = make_float2(v0, v1);
            }
        }
    }
}

// ====================== reduce: sum 4 slots per token ======================
__global__ __launch_bounds__(256) void reduce_kernel(float* __restrict__ out) {
    int t = blockIdx.x;
    int s0 = g_tslot[t * 4 + 0], s1 = g_tslot[t * 4 + 1];
    int s2 = g_tslot[t * 4 + 2], s3 = g_tslot[t * 4 + 3];
    const float* p0 = g_slotout + (size_t)s0 * Hn;
    const float* p1 = g_slotout + (size_t)s1 * Hn;
    const float* p2 = g_slotout + (size_t)s2 * Hn;
    const float* p3 = g_slotout + (size_t)s3 * Hn;
    float* o = out + (size_t)t * Hn;
    for (int i = threadIdx.x * 4; i < Hn; i += 256 * 4) {
        float4 a = *(const float4*)(p0 + i);
        float4 b = *(const float4*)(p1 + i);
        float4 c = *(const float4*)(p2 + i);
        float4 d = *(const float4*)(p3 + i);
        *(float4*)(o + i) = make_float4(a.x + b.x + c.x + d.x,
                                        a.y + b.y + c.y + d.y,
                                        a.z + b.z + c.z + d.z,
                                        a.w + b.w + c.w + d.w);
    }
}

// ====================== launcher ======================
extern "C" void kernel_launch(void* const* d_in, const int* in_sizes, int n_in,
                              void* d_out, int out_size) {
    const float* x  = (const float*)d_in[0];
    const float* gw = (const float*)d_in[1];
    const float* wg = (const float*)d_in[2];
    const float* wu = (const float*)d_in[3];
    const float* wd = (const float*)d_in[4];
    float* out = (float*)d_out;

    float* logits_out = nullptr;
    if (out_size >= Tn * Hn + Tn * En) logits_out = out + (size_t)Tn * Hn;

    init_kernel<<<1, 32>>>();
    convert_x_kernel<<<(Tn * Hn) / 1024, 256>>>(x);
    router_kernel<<<Tn, 256>>>(x, gw, logits_out);
    scan_kernel<<<1, 32>>>();
    scatter_kernel<<<(NSLOT + 255) / 256, 256>>>();
    gemm1_kernel<<<dim3(Fn / 64, NSLOT / 128, En), 256>>>(wg, wu);
    gemm2_kernel<<<dim3(Hn / 128, NSLOT / 128, En), 256>>>(wd);
    reduce_kernel<<<Tn, 256>>>(out);
}

// round 9
// speedup vs baseline: 1.9633x; 1.0219x over previous
#include <cuda_runtime.h>
#include <cuda_bf16.h>
#include <math.h>
#include <stdint.h>

#define Tn 4096
#define Hn 2048
#define En 32
#define Fn 768
#define TOPK 4
#define NSLOT (Tn * TOPK)

// ====================== asm helpers ======================
__device__ __forceinline__ uint32_t smem_u32(const void* p) {
    uint32_t a;
    asm("{ .reg .u64 t; cvta.to.shared.u64 t, %1; cvt.u32.u64 %0, t; }"
        : "=r"(a) : "l"(p));
    return a;
}
__device__ __forceinline__ void cpa16(uint32_t dst, const void* src) {
    asm volatile("cp.async.cg.shared.global [%0], [%1], 16;"
                 :: "r"(dst), "l"(src) : "memory");
}
#define CP_COMMIT() asm volatile("cp.async.commit_group;" ::: "memory")
#define CP_WAIT0()  asm volatile("cp.async.wait_group 0;" ::: "memory")

#define LDSM_X4(r0, r1, r2, r3, a) \
    asm volatile("ldmatrix.sync.aligned.m8n8.x4.shared.b16 {%0,%1,%2,%3}, [%4];" \
                 : "=r"(r0), "=r"(r1), "=r"(r2), "=r"(r3) : "r"(a))
#define LDSM_X4_T(r0, r1, r2, r3, a) \
    asm volatile("ldmatrix.sync.aligned.m8n8.x4.trans.shared.b16 {%0,%1,%2,%3}, [%4];" \
                 : "=r"(r0), "=r"(r1), "=r"(r2), "=r"(r3) : "r"(a))

#define MMA_BF16(d, a, b0, b1) \
    asm volatile("mma.sync.aligned.m16n8k16.row.col.f32.bf16.bf16.f32 " \
                 "{%0,%1,%2,%3}, {%4,%5,%6,%7}, {%8,%9}, {%0,%1,%2,%3};" \
                 : "+f"((d)[0]), "+f"((d)[1]), "+f"((d)[2]), "+f"((d)[3]) \
                 : "r"((a)[0]), "r"((a)[1]), "r"((a)[2]), "r"((a)[3]), \
                   "r"(b0), "r"(b1))

// ====================== device scratch (~215 MB) ======================
__device__ int   g_counts[En];
__device__ int   g_offsets[En];
__device__ int   g_cursor[En];
__device__ int   g_topk_idx[NSLOT];
__device__ float g_topk_w[NSLOT];
__device__ int   g_tok[NSLOT];
__device__ float g_tokw[NSLOT];
__device__ int   g_tslot[NSLOT];

__device__ __align__(256) __nv_bfloat16 g_xhi[(size_t)Tn * Hn];
__device__ __align__(256) __nv_bfloat16 g_xlo[(size_t)Tn * Hn];
__device__ __align__(256) __nv_bfloat16 g_hdnhi[(size_t)NSLOT * Fn];
__device__ __align__(256) __nv_bfloat16 g_hdnlo[(size_t)NSLOT * Fn];
__device__ __align__(256) float         g_slotout[(size_t)NSLOT * Hn];

// ====================== small kernels ======================
__device__ __forceinline__ void split1(float f, __nv_bfloat16& h, __nv_bfloat16& l) {
    h = __float2bfloat16(f);
    l = __float2bfloat16(f - __bfloat162float(h));
}
__device__ __forceinline__ void split2(float a, float b, uint32_t& hp, uint32_t& lp) {
    __nv_bfloat162 h = __floats2bfloat162_rn(a, b);
    float r0 = a - __bfloat162float(__low2bfloat16(h));
    float r1 = b - __bfloat162float(__high2bfloat16(h));
    __nv_bfloat162 l = __floats2bfloat162_rn(r0, r1);
    hp = *(uint32_t*)&h; lp = *(uint32_t*)&l;
}
__device__ __forceinline__ void stsplit4(__nv_bfloat16* ph, __nv_bfloat16* pl,
                                         uint32_t idx, float4 v) {
    uint32_t h0, l0, h1, l1;
    split2(v.x, v.y, h0, l0);
    split2(v.z, v.w, h1, l1);
    *(uint32_t*)(ph + idx)     = h0;
    *(uint32_t*)(ph + idx + 2) = h1;
    *(uint32_t*)(pl + idx)     = l0;
    *(uint32_t*)(pl + idx + 2) = l1;
}

// also clears routing counters (block 0)
__global__ __launch_bounds__(256) void convert_x_kernel(const float* __restrict__ x) {
    if (blockIdx.x == 0 && threadIdx.x < En) {
        g_counts[threadIdx.x] = 0;
        g_cursor[threadIdx.x] = 0;
    }
    size_t i = ((size_t)blockIdx.x * 256 + threadIdx.x) * 4;
    float4 v = *(const float4*)(x + i);
    __nv_bfloat16 h0, l0, h1, l1, h2, l2, h3, l3;
    split1(v.x, h0, l0); split1(v.y, h1, l1);
    split1(v.z, h2, l2); split1(v.w, h3, l3);
    g_xhi[i] = h0; g_xhi[i+1] = h1; g_xhi[i+2] = h2; g_xhi[i+3] = h3;
    g_xlo[i] = l0; g_xlo[i+1] = l1; g_xlo[i+2] = l2; g_xlo[i+3] = l3;
}

// ====================== router / scan / scatter ======================
__global__ __launch_bounds__(256) void router_kernel(
    const float* __restrict__ x, const float* __restrict__ gw,
    float* __restrict__ logits_out)
{
    int t = blockIdx.x, tid = threadIdx.x;
    int warp = tid >> 5, lane = tid & 31;
    __shared__ float sx[Hn];
    __shared__ float slog[En];
    for (int i = tid; i < Hn; i += 256) sx[i] = x[(size_t)t * Hn + i];
    __syncthreads();
    for (int e = warp; e < En; e += 8) {
        const float* w = gw + (size_t)e * Hn;
        float acc = 0.f;
        for (int k = lane; k < Hn; k += 32) acc += sx[k] * w[k];
        #pragma unroll
        for (int o = 16; o > 0; o >>= 1) acc += __shfl_xor_sync(~0u, acc, o);
        if (lane == 0) slog[e] = acc;
    }
    __syncthreads();
    if (warp == 0) {
        float l = slog[lane];
        if (logits_out) logits_out[(size_t)t * En + lane] = l;
        float m = l;
        #pragma unroll
        for (int o = 16; o > 0; o >>= 1) m = fmaxf(m, __shfl_xor_sync(~0u, m, o));
        float p = __expf(l - m), s = p;
        #pragma unroll
        for (int o = 16; o > 0; o >>= 1) s += __shfl_xor_sync(~0u, s, o);
        p /= s;
        float myp = p, tw[TOPK]; int ti[TOPK]; float wsum = 0.f;
        #pragma unroll
        for (int j = 0; j < TOPK; j++) {
            float v = myp; int idx = lane;
            #pragma unroll
            for (int o = 16; o > 0; o >>= 1) {
                float ov = __shfl_xor_sync(~0u, v, o);
                int   oi = __shfl_xor_sync(~0u, idx, o);
                if (ov > v || (ov == v && oi < idx)) { v = ov; idx = oi; }
            }
            tw[j] = v; ti[j] = idx; wsum += v;
            if (lane == idx) myp = -1.f;
        }
        if (lane < TOPK) {
            int e = ti[lane];
            g_topk_idx[t * TOPK + lane] = e;
            g_topk_w[t * TOPK + lane] = tw[lane] / wsum;
            atomicAdd(&g_counts[e], 1);
        }
    }
}

__global__ void scan_kernel() {
    int lane = threadIdx.x;
    int c = g_counts[lane], inc = c;
    #pragma unroll
    for (int o = 1; o < 32; o <<= 1) {
        int nv = __shfl_up_sync(~0u, inc, o);
        if (lane >= o) inc += nv;
    }
    g_offsets[lane] = inc - c;
}

__global__ void scatter_kernel() {
    int i = blockIdx.x * blockDim.x + threadIdx.x;
    if (i >= NSLOT) return;
    int e = g_topk_idx[i];
    int pos = atomicAdd(&g_cursor[e], 1);
    int slot = g_offsets[e] + pos;
    g_tok[slot]  = i >> 2;
    g_tokw[slot] = g_topk_w[i];
    g_tslot[i]   = slot;
}

// A rows padded to 48B (24 bf16): banks r*12 mod 32 all distinct for r mod 8
#define A_ROWE 24
#define A_PLANE (128 * A_ROWE)
// gemm1 B rows padded to 144B (72 bf16)
#define B1_ROWE 72
#define B1_PLANE (16 * B1_ROWE)
// gemm2 B rows padded to 272B (136 bf16)
#define B2_ROWE 136
#define B2_PLANE (16 * B2_ROWE)

// ====================== GEMM1: 128x64 tile, BK=16 ======================
__global__ __launch_bounds__(256, 2) void gemm1_kernel(
    const float* __restrict__ wg, const float* __restrict__ wu)
{
    __shared__ __align__(16) __nv_bfloat16 sAh[2][A_PLANE], sAl[2][A_PLANE];
    __shared__ __align__(16) __nv_bfloat16 sGh[2][B1_PLANE], sGl[2][B1_PLANE];
    __shared__ __align__(16) __nv_bfloat16 sUh[2][B1_PLANE], sUl[2][B1_PLANE];
    __shared__ int stok[128];

    int e = blockIdx.z;
    int cnt = g_counts[e];
    int m0 = blockIdx.y * 128;
    if (m0 >= cnt) return;
    int base = g_offsets[e];
    int n0 = blockIdx.x * 64;
    int tid = threadIdx.x, wid = tid >> 5, lane = tid & 31;

    if (tid < 128) {
        int idx = base + m0 + tid;
        stok[tid] = g_tok[idx < NSLOT ? idx : NSLOT - 1];
    }
    __syncthreads();

    // ---- A loader: 2 threads/row, 16B cp.async each ----
    int arow = tid >> 1, acs = tid & 1;
    const __nv_bfloat16* pAh = g_xhi + (size_t)stok[arow] * Hn + acs * 8;
    const __nv_bfloat16* pAl = g_xlo + (size_t)stok[arow] * Hn + acs * 8;
    uint32_t aDst = (uint32_t)(arow * 48 + acs * 16);
    uint32_t sAh_b = smem_u32(sAh), sAl_b = smem_u32(sAl);

    // ---- B loader: [K][N] direct, float4 per thread per matrix ----
    int bkr = tid >> 4, bn4 = (tid & 15) * 4;
    const float* pG = wg + (size_t)e * Hn * Fn + n0 + bn4;
    const float* pU = wu + (size_t)e * Hn * Fn + n0 + bn4;
    uint32_t bIdx = (uint32_t)(bkr * B1_ROWE + bn4);

    // ---- compute maps ----
    int wm = wid & 1, wn = wid >> 1;
    uint32_t aoff[4];
    {
        int r = wm * 64 + (lane & 15);
        uint32_t c = (uint32_t)(lane >> 4) * 16;
        #pragma unroll
        for (int mt = 0; mt < 4; mt++) aoff[mt] = (uint32_t)(r + mt * 16) * 48 + c;
    }
    uint32_t boff = (uint32_t)(lane & 15) * 144 + (uint32_t)wn * 32 +
                    (uint32_t)(lane >> 4) * 16;
    uint32_t sGh_b = smem_u32(sGh), sGl_b = smem_u32(sGl);
    uint32_t sUh_b = smem_u32(sUh), sUl_b = smem_u32(sUl);

    float accG[4][2][4] = {}, accU[4][2][4] = {};

    // ---- prologue ----
    {
        float4 vg = *(const float4*)(pG + (size_t)bkr * Fn);
        float4 vu = *(const float4*)(pU + (size_t)bkr * Fn);
        cpa16(sAh_b + aDst, pAh);
        cpa16(sAl_b + aDst, pAl);
        CP_COMMIT();
        stsplit4(sGh[0], sGl[0], bIdx, vg);
        stsplit4(sUh[0], sUl[0], bIdx, vu);
        CP_WAIT0();
    }
    __syncthreads();

    const int nch = Hn / 16;  // 128
    for (int c = 0; c < nch; c++) {
        int s = c & 1, sn = s ^ 1;
        bool more = (c + 1 < nch);
        float4 vg, vu;
        if (more) {
            size_t ko = (size_t)((c + 1) * 16 + bkr) * Fn;
            vg = *(const float4*)(pG + ko);
            vu = *(const float4*)(pU + ko);
            cpa16(sAh_b + sn * (A_PLANE * 2) + aDst, pAh + (c + 1) * 16);
            cpa16(sAl_b + sn * (A_PLANE * 2) + aDst, pAl + (c + 1) * 16);
            CP_COMMIT();
        }

        uint32_t sAo = (uint32_t)s * (A_PLANE * 2);
        uint32_t sBo = (uint32_t)s * (B1_PLANE * 2);
        uint32_t bgh[4], bgl[4], buh[4], bul[4];
        LDSM_X4_T(bgh[0], bgh[1], bgh[2], bgh[3], sGh_b + sBo + boff);
        LDSM_X4_T(bgl[0], bgl[1], bgl[2], bgl[3], sGl_b + sBo + boff);
        LDSM_X4_T(buh[0], buh[1], buh[2], buh[3], sUh_b + sBo + boff);
        LDSM_X4_T(bul[0], bul[1], bul[2], bul[3], sUl_b + sBo + boff);
        #pragma unroll
        for (int mt = 0; mt < 4; mt++) {
            uint32_t ah[4], al[4];
            LDSM_X4(ah[0], ah[1], ah[2], ah[3], sAh_b + sAo + aoff[mt]);
            LDSM_X4(al[0], al[1], al[2], al[3], sAl_b + sAo + aoff[mt]);
            #pragma unroll
            for (int nt = 0; nt < 2; nt++) {
                MMA_BF16(accG[mt][nt], ah, bgh[nt * 2], bgh[nt * 2 + 1]);
                MMA_BF16(accG[mt][nt], ah, bgl[nt * 2], bgl[nt * 2 + 1]);
                MMA_BF16(accG[mt][nt], al, bgh[nt * 2], bgh[nt * 2 + 1]);
                MMA_BF16(accU[mt][nt], ah, buh[nt * 2], buh[nt * 2 + 1]);
                MMA_BF16(accU[mt][nt], ah, bul[nt * 2], bul[nt * 2 + 1]);
                MMA_BF16(accU[mt][nt], al, buh[nt * 2], buh[nt * 2 + 1]);
            }
        }

        if (more) {
            stsplit4(sGh[sn], sGl[sn], bIdx, vg);
            stsplit4(sUh[sn], sUl[sn], bIdx, vu);
            CP_WAIT0();
        }
        __syncthreads();
    }

    // ---- epilogue: h = w * silu(g) * u -> hdn hi/lo ----
    int r = lane >> 2, cp2 = (lane & 3) * 2;
    #pragma unroll
    for (int mt = 0; mt < 4; mt++) {
        #pragma unroll
        for (int half = 0; half < 2; half++) {
            int grow = m0 + wm * 64 + mt * 16 + r + half * 8;
            if (grow >= cnt) continue;
            int slot = base + grow;
            float wgt = g_tokw[slot];
            size_t ob = (size_t)slot * Fn + n0 + wn * 16 + cp2;
            #pragma unroll
            for (int nt = 0; nt < 2; nt++) {
                float g0 = accG[mt][nt][half * 2 + 0];
                float g1 = accG[mt][nt][half * 2 + 1];
                float u0 = accU[mt][nt][half * 2 + 0];
                float u1 = accU[mt][nt][half * 2 + 1];
                float h0 = wgt * (g0 / (1.f + __expf(-g0))) * u0;
                float h1 = wgt * (g1 / (1.f + __expf(-g1))) * u1;
                __nv_bfloat16 bh, bl;
                split1(h0, bh, bl);
                g_hdnhi[ob + nt * 8]     = bh;
                g_hdnlo[ob + nt * 8]     = bl;
                split1(h1, bh, bl);
                g_hdnhi[ob + nt * 8 + 1] = bh;
                g_hdnlo[ob + nt * 8 + 1] = bl;
            }
        }
    }
}

// ====================== GEMM2: 128x128 tile, BK=16 ======================
__global__ __launch_bounds__(256, 2) void gemm2_kernel(const float* __restrict__ wd) {
    __shared__ __align__(16) __nv_bfloat16 sAh[2][A_PLANE], sAl[2][A_PLANE];
    __shared__ __align__(16) __nv_bfloat16 sBh[2][B2_PLANE], sBl[2][B2_PLANE];

    int e = blockIdx.z;
    int cnt = g_counts[e];
    int m0 = blockIdx.y * 128;
    if (m0 >= cnt) return;
    int base = g_offsets[e];
    int n0 = blockIdx.x * 128;
    int tid = threadIdx.x, wid = tid >> 5, lane = tid & 31;

    int arow = tid >> 1, acs = tid & 1;
    int sl = base + m0 + arow; if (sl >= NSLOT) sl = NSLOT - 1;
    const __nv_bfloat16* pAh = g_hdnhi + (size_t)sl * Fn + acs * 8;
    const __nv_bfloat16* pAl = g_hdnlo + (size_t)sl * Fn + acs * 8;
    uint32_t aDst = (uint32_t)(arow * 48 + acs * 16);
    uint32_t sAh_b = smem_u32(sAh), sAl_b = smem_u32(sAl);

    int bkr = tid >> 4, bn4 = (tid & 15) * 4;
    const float* pB = wd + (size_t)e * Fn * Hn + n0 + bn4;
    uint32_t bIdx = (uint32_t)(bkr * B2_ROWE + bn4);
    uint32_t sBh_b = smem_u32(sBh), sBl_b = smem_u32(sBl);

    int wm = wid & 1, wn = wid >> 1;
    uint32_t aoff[4];
    {
        int r = wm * 64 + (lane & 15);
        uint32_t c = (uint32_t)(lane >> 4) * 16;
        #pragma unroll
        for (int mt = 0; mt < 4; mt++) aoff[mt] = (uint32_t)(r + mt * 16) * 48 + c;
    }
    uint32_t boff[2];
    {
        uint32_t rb = (uint32_t)(lane & 15) * 272 + (uint32_t)(lane >> 4) * 16;
        boff[0] = rb + (uint32_t)wn * 64;
        boff[1] = rb + (uint32_t)wn * 64 + 32;
    }

    float acc[4][4][4] = {};

    // ---- prologue ----
    {
        size_t ko = (size_t)bkr * Hn;
        float4 v0 = *(const float4*)(pB + ko);
        float4 v1 = *(const float4*)(pB + ko + 64);
        cpa16(sAh_b + aDst, pAh);
        cpa16(sAl_b + aDst, pAl);
        CP_COMMIT();
        stsplit4(sBh[0], sBl[0], bIdx, v0);
        stsplit4(sBh[0], sBl[0], bIdx + 64, v1);
        CP_WAIT0();
    }
    __syncthreads();

    const int nch = Fn / 16;  // 48
    for (int c = 0; c < nch; c++) {
        int s = c & 1, sn = s ^ 1;
        bool more = (c + 1 < nch);
        float4 v0, v1;
        if (more) {
            size_t ko = (size_t)((c + 1) * 16 + bkr) * Hn;
            v0 = *(const float4*)(pB + ko);
            v1 = *(const float4*)(pB + ko + 64);
            cpa16(sAh_b + sn * (A_PLANE * 2) + aDst, pAh + (c + 1) * 16);
            cpa16(sAl_b + sn * (A_PLANE * 2) + aDst, pAl + (c + 1) * 16);
            CP_COMMIT();
        }

        uint32_t sAo = (uint32_t)s * (A_PLANE * 2);
        uint32_t sBo = (uint32_t)s * (B2_PLANE * 2);
        uint32_t bh[2][4], bl[2][4];
        #pragma unroll
        for (int p = 0; p < 2; p++) {
            LDSM_X4_T(bh[p][0], bh[p][1], bh[p][2], bh[p][3], sBh_b + sBo + boff[p]);
            LDSM_X4_T(bl[p][0], bl[p][1], bl[p][2], bl[p][3], sBl_b + sBo + boff[p]);
        }
        #pragma unroll
        for (int mt = 0; mt < 4; mt++) {
            uint32_t ah[4], al[4];
            LDSM_X4(ah[0], ah[1], ah[2], ah[3], sAh_b + sAo + aoff[mt]);
            LDSM_X4(al[0], al[1], al[2], al[3], sAl_b + sAo + aoff[mt]);
            #pragma unroll
            for (int nt = 0; nt < 4; nt++) {
                uint32_t* BH = &bh[nt >> 1][(nt & 1) * 2];
                uint32_t* BL = &bl[nt >> 1][(nt & 1) * 2];
                MMA_BF16(acc[mt][nt], ah, BH[0], BH[1]);
                MMA_BF16(acc[mt][nt], ah, BL[0], BL[1]);
                MMA_BF16(acc[mt][nt], al, BH[0], BH[1]);
            }
        }

        if (more) {
            stsplit4(sBh[sn], sBl[sn], bIdx, v0);
            stsplit4(sBh[sn], sBl[sn], bIdx + 64, v1);
            CP_WAIT0();
        }
        __syncthreads();
    }

    // ---- epilogue: stream fp32 to slot buffer ----
    int r = lane >> 2, cp2 = (lane & 3) * 2;
    #pragma unroll
    for (int mt = 0; mt < 4; mt++) {
        #pragma unroll
        for (int half = 0; half < 2; half++) {
            int grow = m0 + wm * 64 + mt * 16 + r + half * 8;
            if (grow >= cnt) continue;
            size_t ob = (size_t)(base + grow) * Hn + n0 + wn * 32 + cp2;
            #pragma unroll
            for (int nt = 0; nt < 4; nt++) {
                float v0 = acc[mt][nt][half * 2 + 0];
                float v1 = acc[mt][nt][half * 2 + 1];
                *(float2*)(g_slotout + ob + nt * 8) = make_float2(v0, v1);
            }
        }
    }
}

// ====================== reduce: sum 4 slots per token ======================
__global__ __launch_bounds__(256) void reduce_kernel(float* __restrict__ out) {
    int t = blockIdx.x;
    int s0 = g_tslot[t * 4 + 0], s1 = g_tslot[t * 4 + 1];
    int s2 = g_tslot[t * 4 + 2], s3 = g_tslot[t * 4 + 3];
    const float* p0 = g_slotout + (size_t)s0 * Hn;
    const float* p1 = g_slotout + (size_t)s1 * Hn;
    const float* p2 = g_slotout + (size_t)s2 * Hn;
    const float* p3 = g_slotout + (size_t)s3 * Hn;
    float* o = out + (size_t)t * Hn;
    for (int i = threadIdx.x * 4; i < Hn; i += 256 * 4) {
        float4 a = *(const float4*)(p0 + i);
        float4 b = *(const float4*)(p1 + i);
        float4 c = *(const float4*)(p2 + i);
        float4 d = *(const float4*)(p3 + i);
        *(float4*)(o + i) = make_float4(a.x + b.x + c.x + d.x,
                                        a.y + b.y + c.y + d.y,
                                        a.z + b.z + c.z + d.z,
                                        a.w + b.w + c.w + d.w);
    }
}

// ====================== launcher ======================
extern "C" void kernel_launch(void* const* d_in, const int* in_sizes, int n_in,
                              void* d_out, int out_size) {
    const float* x  = (const float*)d_in[0];
    const float* gw = (const float*)d_in[1];
    const float* wg = (const float*)d_in[2];
    const float* wu = (const float*)d_in[3];
    const float* wd = (const float*)d_in[4];
    float* out = (float*)d_out;

    float* logits_out = nullptr;
    if (out_size >= Tn * Hn + Tn * En) logits_out = out + (size_t)Tn * Hn;

    convert_x_kernel<<<(Tn * Hn) / 1024, 256>>>(x);
    router_kernel<<<Tn, 256>>>(x, gw, logits_out);
    scan_kernel<<<1, 32>>>();
    scatter_kernel<<<(NSLOT + 255) / 256, 256>>>();
    gemm1_kernel<<<dim3(Fn / 64, NSLOT / 128, En), 256>>>(wg, wu);
    gemm2_kernel<<<dim3(Hn / 128, NSLOT / 128, En), 256>>>(wd);
    reduce_kernel<<<Tn, 256>>>(out);
}

// round 10
// speedup vs baseline: 2.1558x; 1.0980x over previous
#include <cuda_runtime.h>
#include <cuda_bf16.h>
#include <math.h>
#include <stdint.h>

#define Tn 4096
#define Hn 2048
#define En 32
#define Fn 768
#define TOPK 4
#define NSLOT (Tn * TOPK)
#define MAXTILE 160

// ====================== asm helpers ======================
__device__ __forceinline__ uint32_t smem_u32(const void* p) {
    uint32_t a;
    asm("{ .reg .u64 t; cvta.to.shared.u64 t, %1; cvt.u32.u64 %0, t; }"
        : "=r"(a) : "l"(p));
    return a;
}

#define LDSM_X4(r0, r1, r2, r3, a) \
    asm volatile("ldmatrix.sync.aligned.m8n8.x4.shared.b16 {%0,%1,%2,%3}, [%4];" \
                 : "=r"(r0), "=r"(r1), "=r"(r2), "=r"(r3) : "r"(a))
#define LDSM_X4_T(r0, r1, r2, r3, a) \
    asm volatile("ldmatrix.sync.aligned.m8n8.x4.trans.shared.b16 {%0,%1,%2,%3}, [%4];" \
                 : "=r"(r0), "=r"(r1), "=r"(r2), "=r"(r3) : "r"(a))

#define MMA_BF16(d, a, b0, b1) \
    asm volatile("mma.sync.aligned.m16n8k16.row.col.f32.bf16.bf16.f32 " \
                 "{%0,%1,%2,%3}, {%4,%5,%6,%7}, {%8,%9}, {%0,%1,%2,%3};" \
                 : "+f"((d)[0]), "+f"((d)[1]), "+f"((d)[2]), "+f"((d)[3]) \
                 : "r"((a)[0]), "r"((a)[1]), "r"((a)[2]), "r"((a)[3]), \
                   "r"(b0), "r"(b1))

// ====================== device scratch (~215 MB) ======================
__device__ int   g_counts[En];
__device__ int   g_offsets[En];
__device__ int   g_cursor[En];
__device__ int   g_topk_idx[NSLOT];
__device__ float g_topk_w[NSLOT];
__device__ int   g_tok[NSLOT];
__device__ float g_tokw[NSLOT];
__device__ int   g_tslot[NSLOT];
__device__ int   g_ntiles;
__device__ int   g_tile_e[MAXTILE];
__device__ int   g_tile_m[MAXTILE];

__device__ __align__(256) __nv_bfloat16 g_xhi[(size_t)Tn * Hn];
__device__ __align__(256) __nv_bfloat16 g_xlo[(size_t)Tn * Hn];
__device__ __align__(256) __nv_bfloat16 g_hdnhi[(size_t)NSLOT * Fn];
__device__ __align__(256) __nv_bfloat16 g_hdnlo[(size_t)NSLOT * Fn];
__device__ __align__(256) float         g_slotout[(size_t)NSLOT * Hn];

// ====================== helpers ======================
__device__ __forceinline__ void split1(float f, __nv_bfloat16& h, __nv_bfloat16& l) {
    h = __float2bfloat16(f);
    l = __float2bfloat16(f - __bfloat162float(h));
}
__device__ __forceinline__ void split2(float a, float b, uint32_t& hp, uint32_t& lp) {
    __nv_bfloat162 h = __floats2bfloat162_rn(a, b);
    float r0 = a - __bfloat162float(__low2bfloat16(h));
    float r1 = b - __bfloat162float(__high2bfloat16(h));
    __nv_bfloat162 l = __floats2bfloat162_rn(r0, r1);
    hp = *(uint32_t*)&h; lp = *(uint32_t*)&l;
}
__device__ __forceinline__ void stsplit4(__nv_bfloat16* ph, __nv_bfloat16* pl,
                                         uint32_t idx, float4 v) {
    uint32_t h0, l0, h1, l1;
    split2(v.x, v.y, h0, l0);
    split2(v.z, v.w, h1, l1);
    *(uint32_t*)(ph + idx)     = h0;
    *(uint32_t*)(ph + idx + 2) = h1;
    *(uint32_t*)(pl + idx)     = l0;
    *(uint32_t*)(pl + idx + 2) = l1;
}

// also clears routing counters (block 0)
__global__ __launch_bounds__(256) void convert_x_kernel(const float* __restrict__ x) {
    if (blockIdx.x == 0 && threadIdx.x < En) {
        g_counts[threadIdx.x] = 0;
        g_cursor[threadIdx.x] = 0;
    }
    size_t i = ((size_t)blockIdx.x * 256 + threadIdx.x) * 4;
    float4 v = *(const float4*)(x + i);
    __nv_bfloat16 h0, l0, h1, l1, h2, l2, h3, l3;
    split1(v.x, h0, l0); split1(v.y, h1, l1);
    split1(v.z, h2, l2); split1(v.w, h3, l3);
    g_xhi[i] = h0; g_xhi[i+1] = h1; g_xhi[i+2] = h2; g_xhi[i+3] = h3;
    g_xlo[i] = l0; g_xlo[i+1] = l1; g_xlo[i+2] = l2; g_xlo[i+3] = l3;
}

// ====================== router: 4 tokens per block ======================
__global__ __launch_bounds__(256) void router_kernel(
    const float* __restrict__ x, const float* __restrict__ gw,
    float* __restrict__ logits_out)
{
    int tb = blockIdx.x * 4;
    int tid = threadIdx.x;
    int warp = tid >> 5, lane = tid & 31;
    __shared__ float sx[4][Hn];
    __shared__ float slog[4][En];

    for (int i = tid; i < 4 * Hn; i += 256)
        ((float*)sx)[i] = x[(size_t)tb * Hn + i];
    __syncthreads();

    // 8 warps x 4 experts each; each gw row read once serves 4 tokens
    for (int e = warp; e < En; e += 8) {
        const float* w = gw + (size_t)e * Hn;
        float a0 = 0.f, a1 = 0.f, a2 = 0.f, a3 = 0.f;
        for (int k = lane; k < Hn; k += 32) {
            float wv = w[k];
            a0 += sx[0][k] * wv;
            a1 += sx[1][k] * wv;
            a2 += sx[2][k] * wv;
            a3 += sx[3][k] * wv;
        }
        #pragma unroll
        for (int o = 16; o > 0; o >>= 1) {
            a0 += __shfl_xor_sync(~0u, a0, o);
            a1 += __shfl_xor_sync(~0u, a1, o);
            a2 += __shfl_xor_sync(~0u, a2, o);
            a3 += __shfl_xor_sync(~0u, a3, o);
        }
        if (lane == 0) {
            slog[0][e] = a0; slog[1][e] = a1;
            slog[2][e] = a2; slog[3][e] = a3;
        }
    }
    __syncthreads();

    if (warp < 4) {
        int t = tb + warp;
        float l = slog[warp][lane];
        if (logits_out) logits_out[(size_t)t * En + lane] = l;
        float m = l;
        #pragma unroll
        for (int o = 16; o > 0; o >>= 1) m = fmaxf(m, __shfl_xor_sync(~0u, m, o));
        float p = __expf(l - m), s = p;
        #pragma unroll
        for (int o = 16; o > 0; o >>= 1) s += __shfl_xor_sync(~0u, s, o);
        p /= s;
        float myp = p, tw[TOPK]; int ti[TOPK]; float wsum = 0.f;
        #pragma unroll
        for (int j = 0; j < TOPK; j++) {
            float v = myp; int idx = lane;
            #pragma unroll
            for (int o = 16; o > 0; o >>= 1) {
                float ov = __shfl_xor_sync(~0u, v, o);
                int   oi = __shfl_xor_sync(~0u, idx, o);
                if (ov > v || (ov == v && oi < idx)) { v = ov; idx = oi; }
            }
            tw[j] = v; ti[j] = idx; wsum += v;
            if (lane == idx) myp = -1.f;
        }
        if (lane < TOPK) {
            int e = ti[lane];
            g_topk_idx[t * TOPK + lane] = e;
            g_topk_w[t * TOPK + lane] = tw[lane] / wsum;
            atomicAdd(&g_counts[e], 1);
        }
    }
}

// ====================== scan + tile worklist ======================
__global__ void scan_kernel() {
    int lane = threadIdx.x;
    int c = g_counts[lane], inc = c;
    #pragma unroll
    for (int o = 1; o < 32; o <<= 1) {
        int nv = __shfl_up_sync(~0u, inc, o);
        if (lane >= o) inc += nv;
    }
    g_offsets[lane] = inc - c;
    if (lane == 0) {
        int nt = 0;
        for (int e = 0; e < En; e++) {
            int cc = g_counts[e];
            for (int m0 = 0; m0 < cc; m0 += 128) {
                g_tile_e[nt] = e;
                g_tile_m[nt] = m0;
                nt++;
            }
        }
        g_ntiles = nt;
    }
}

__global__ void scatter_kernel() {
    int i = blockIdx.x * blockDim.x + threadIdx.x;
    if (i >= NSLOT) return;
    int e = g_topk_idx[i];
    int pos = atomicAdd(&g_cursor[e], 1);
    int slot = g_offsets[e] + pos;
    g_tok[slot]  = i >> 2;
    g_tokw[slot] = g_topk_w[i];
    g_tslot[i]   = slot;
}

// A rows padded to 48B (24 bf16): banks r*12 mod 32 distinct per 8 rows
#define A_ROWE 24
#define A_PLANE (128 * A_ROWE)
// gemm1 B rows padded to 144B (72 bf16)
#define B1_ROWE 72
#define B1_PLANE (16 * B1_ROWE)
// gemm2 B rows padded to 272B (136 bf16)
#define B2_ROWE 136
#define B2_PLANE (16 * B2_ROWE)

// ====================== GEMM1: 128x64 tile, BK=16 ======================
__global__ __launch_bounds__(256, 2) void gemm1_kernel(
    const float* __restrict__ wg, const float* __restrict__ wu)
{
    __shared__ __align__(16) __nv_bfloat16 sAh[2][A_PLANE], sAl[2][A_PLANE];
    __shared__ __align__(16) __nv_bfloat16 sGh[2][B1_PLANE], sGl[2][B1_PLANE];
    __shared__ __align__(16) __nv_bfloat16 sUh[2][B1_PLANE], sUl[2][B1_PLANE];
    __shared__ int stok[128];

    int ty = blockIdx.y;
    if (ty >= g_ntiles) return;
    int e = g_tile_e[ty];
    int m0 = g_tile_m[ty];
    int cnt = g_counts[e];
    int base = g_offsets[e];
    int n0 = blockIdx.x * 64;
    int tid = threadIdx.x, wid = tid >> 5, lane = tid & 31;

    if (tid < 128) {
        int idx = base + m0 + tid;
        stok[tid] = g_tok[idx < NSLOT ? idx : NSLOT - 1];
    }
    __syncthreads();

    // ---- A loader: 2 threads/row, 16B LDG -> regs -> STS.128 ----
    int arow = tid >> 1, acs = tid & 1;
    const __nv_bfloat16* pAh = g_xhi + (size_t)stok[arow] * Hn + acs * 8;
    const __nv_bfloat16* pAl = g_xlo + (size_t)stok[arow] * Hn + acs * 8;
    uint32_t aElem = (uint32_t)(arow * A_ROWE + acs * 8);

    // ---- B loader: [K][N] direct, float4 per thread per matrix ----
    int bkr = tid >> 4, bn4 = (tid & 15) * 4;
    const float* pG = wg + (size_t)e * Hn * Fn + n0 + bn4;
    const float* pU = wu + (size_t)e * Hn * Fn + n0 + bn4;
    uint32_t bIdx = (uint32_t)(bkr * B1_ROWE + bn4);

    // ---- compute maps ----
    int wm = wid & 1, wn = wid >> 1;
    uint32_t sAh_b = smem_u32(sAh), sAl_b = smem_u32(sAl);
    uint32_t sGh_b = smem_u32(sGh), sGl_b = smem_u32(sGl);
    uint32_t sUh_b = smem_u32(sUh), sUl_b = smem_u32(sUl);
    uint32_t aoff[4];
    {
        int r = wm * 64 + (lane & 15);
        uint32_t c = (uint32_t)(lane >> 4) * 16;
        #pragma unroll
        for (int mt = 0; mt < 4; mt++) aoff[mt] = (uint32_t)(r + mt * 16) * 48 + c;
    }
    uint32_t boff = (uint32_t)(lane & 15) * 144 + (uint32_t)wn * 32 +
                    (uint32_t)(lane >> 4) * 16;

    float accG[4][2][4] = {}, accU[4][2][4] = {};

    // ---- prologue: fill buffer 0 via registers ----
    {
        uint4 ah = *(const uint4*)pAh;
        uint4 al = *(const uint4*)pAl;
        float4 vg = *(const float4*)(pG + (size_t)bkr * Fn);
        float4 vu = *(const float4*)(pU + (size_t)bkr * Fn);
        *(uint4*)(sAh[0] + aElem) = ah;
        *(uint4*)(sAl[0] + aElem) = al;
        stsplit4(sGh[0], sGl[0], bIdx, vg);
        stsplit4(sUh[0], sUl[0], bIdx, vu);
    }
    __syncthreads();

    const int nch = Hn / 16;  // 128
    for (int c = 0; c < nch; c++) {
        int s = c & 1, sn = s ^ 1;
        bool more = (c + 1 < nch);
        uint4 nah, nal;
        float4 vg, vu;
        if (more) {
            int k0n = (c + 1) * 16;
            nah = *(const uint4*)(pAh + k0n);
            nal = *(const uint4*)(pAl + k0n);
            size_t ko = (size_t)(k0n + bkr) * Fn;
            vg = *(const float4*)(pG + ko);
            vu = *(const float4*)(pU + ko);
        }

        uint32_t sAo = (uint32_t)s * (A_PLANE * 2);
        uint32_t sBo = (uint32_t)s * (B1_PLANE * 2);
        uint32_t bgh[4], bgl[4], buh[4], bul[4];
        LDSM_X4_T(bgh[0], bgh[1], bgh[2], bgh[3], sGh_b + sBo + boff);
        LDSM_X4_T(bgl[0], bgl[1], bgl[2], bgl[3], sGl_b + sBo + boff);
        LDSM_X4_T(buh[0], buh[1], buh[2], buh[3], sUh_b + sBo + boff);
        LDSM_X4_T(bul[0], bul[1], bul[2], bul[3], sUl_b + sBo + boff);
        #pragma unroll
        for (int mt = 0; mt < 4; mt++) {
            uint32_t ah[4], al[4];
            LDSM_X4(ah[0], ah[1], ah[2], ah[3], sAh_b + sAo + aoff[mt]);
            LDSM_X4(al[0], al[1], al[2], al[3], sAl_b + sAo + aoff[mt]);
            #pragma unroll
            for (int nt = 0; nt < 2; nt++) {
                MMA_BF16(accG[mt][nt], ah, bgh[nt * 2], bgh[nt * 2 + 1]);
                MMA_BF16(accG[mt][nt], ah, bgl[nt * 2], bgl[nt * 2 + 1]);
                MMA_BF16(accG[mt][nt], al, bgh[nt * 2], bgh[nt * 2 + 1]);
                MMA_BF16(accU[mt][nt], ah, buh[nt * 2], buh[nt * 2 + 1]);
                MMA_BF16(accU[mt][nt], ah, bul[nt * 2], bul[nt * 2 + 1]);
                MMA_BF16(accU[mt][nt], al, buh[nt * 2], buh[nt * 2 + 1]);
            }
        }

        if (more) {
            *(uint4*)(sAh[sn] + aElem) = nah;
            *(uint4*)(sAl[sn] + aElem) = nal;
            stsplit4(sGh[sn], sGl[sn], bIdx, vg);
            stsplit4(sUh[sn], sUl[sn], bIdx, vu);
        }
        __syncthreads();
    }

    // ---- epilogue: h = w * silu(g) * u -> hdn hi/lo ----
    int r = lane >> 2, cp2 = (lane & 3) * 2;
    #pragma unroll
    for (int mt = 0; mt < 4; mt++) {
        #pragma unroll
        for (int half = 0; half < 2; half++) {
            int grow = m0 + wm * 64 + mt * 16 + r + half * 8;
            if (grow >= cnt) continue;
            int slot = base + grow;
            float wgt = g_tokw[slot];
            size_t ob = (size_t)slot * Fn + n0 + wn * 16 + cp2;
            #pragma unroll
            for (int nt = 0; nt < 2; nt++) {
                float g0 = accG[mt][nt][half * 2 + 0];
                float g1 = accG[mt][nt][half * 2 + 1];
                float u0 = accU[mt][nt][half * 2 + 0];
                float u1 = accU[mt][nt][half * 2 + 1];
                float h0 = wgt * (g0 / (1.f + __expf(-g0))) * u0;
                float h1 = wgt * (g1 / (1.f + __expf(-g1))) * u1;
                __nv_bfloat16 bh, bl;
                split1(h0, bh, bl);
                g_hdnhi[ob + nt * 8]     = bh;
                g_hdnlo[ob + nt * 8]     = bl;
                split1(h1, bh, bl);
                g_hdnhi[ob + nt * 8 + 1] = bh;
                g_hdnlo[ob + nt * 8 + 1] = bl;
            }
        }
    }
}

// ====================== GEMM2: 128x128 tile, BK=16 ======================
__global__ __launch_bounds__(256, 2) void gemm2_kernel(const float* __restrict__ wd) {
    __shared__ __align__(16) __nv_bfloat16 sAh[2][A_PLANE], sAl[2][A_PLANE];
    __shared__ __align__(16) __nv_bfloat16 sBh[2][B2_PLANE], sBl[2][B2_PLANE];

    int ty = blockIdx.y;
    if (ty >= g_ntiles) return;
    int e = g_tile_e[ty];
    int m0 = g_tile_m[ty];
    int cnt = g_counts[e];
    int base = g_offsets[e];
    int n0 = blockIdx.x * 128;
    int tid = threadIdx.x, wid = tid >> 5, lane = tid & 31;

    int arow = tid >> 1, acs = tid & 1;
    int sl = base + m0 + arow; if (sl >= NSLOT) sl = NSLOT - 1;
    const __nv_bfloat16* pAh = g_hdnhi + (size_t)sl * Fn + acs * 8;
    const __nv_bfloat16* pAl = g_hdnlo + (size_t)sl * Fn + acs * 8;
    uint32_t aElem = (uint32_t)(arow * A_ROWE + acs * 8);

    int bkr = tid >> 4, bn4 = (tid & 15) * 4;
    const float* pB = wd + (size_t)e * Fn * Hn + n0 + bn4;
    uint32_t bIdx = (uint32_t)(bkr * B2_ROWE + bn4);

    int wm = wid & 1, wn = wid >> 1;
    uint32_t sAh_b = smem_u32(sAh), sAl_b = smem_u32(sAl);
    uint32_t sBh_b = smem_u32(sBh), sBl_b = smem_u32(sBl);
    uint32_t aoff[4];
    {
        int r = wm * 64 + (lane & 15);
        uint32_t c = (uint32_t)(lane >> 4) * 16;
        #pragma unroll
        for (int mt = 0; mt < 4; mt++) aoff[mt] = (uint32_t)(r + mt * 16) * 48 + c;
    }
    uint32_t boff[2];
    {
        uint32_t rb = (uint32_t)(lane & 15) * 272 + (uint32_t)(lane >> 4) * 16;
        boff[0] = rb + (uint32_t)wn * 64;
        boff[1] = rb + (uint32_t)wn * 64 + 32;
    }

    float acc[4][4][4] = {};

    // ---- prologue ----
    {
        uint4 ah = *(const uint4*)pAh;
        uint4 al = *(const uint4*)pAl;
        size_t ko = (size_t)bkr * Hn;
        float4 v0 = *(const float4*)(pB + ko);
        float4 v1 = *(const float4*)(pB + ko + 64);
        *(uint4*)(sAh[0] + aElem) = ah;
        *(uint4*)(sAl[0] + aElem) = al;
        stsplit4(sBh[0], sBl[0], bIdx, v0);
        stsplit4(sBh[0], sBl[0], bIdx + 64, v1);
    }
    __syncthreads();

    const int nch = Fn / 16;  // 48
    for (int c = 0; c < nch; c++) {
        int s = c & 1, sn = s ^ 1;
        bool more = (c + 1 < nch);
        uint4 nah, nal;
        float4 v0, v1;
        if (more) {
            int k0n = (c + 1) * 16;
            nah = *(const uint4*)(pAh + k0n);
            nal = *(const uint4*)(pAl + k0n);
            size_t ko = (size_t)(k0n + bkr) * Hn;
            v0 = *(const float4*)(pB + ko);
            v1 = *(const float4*)(pB + ko + 64);
        }

        uint32_t sAo = (uint32_t)s * (A_PLANE * 2);
        uint32_t sBo = (uint32_t)s * (B2_PLANE * 2);
        uint32_t bh[2][4], bl[2][4];
        #pragma unroll
        for (int p = 0; p < 2; p++) {
            LDSM_X4_T(bh[p][0], bh[p][1], bh[p][2], bh[p][3], sBh_b + sBo + boff[p]);
            LDSM_X4_T(bl[p][0], bl[p][1], bl[p][2], bl[p][3], sBl_b + sBo + boff[p]);
        }
        #pragma unroll
        for (int mt = 0; mt < 4; mt++) {
            uint32_t ah[4], al[4];
            LDSM_X4(ah[0], ah[1], ah[2], ah[3], sAh_b + sAo + aoff[mt]);
            LDSM_X4(al[0], al[1], al[2], al[3], sAl_b + sAo + aoff[mt]);
            #pragma unroll
            for (int nt = 0; nt < 4; nt++) {
                uint32_t* BH = &bh[nt >> 1][(nt & 1) * 2];
                uint32_t* BL = &bl[nt >> 1][(nt & 1) * 2];
                MMA_BF16(acc[mt][nt], ah, BH[0], BH[1]);
                MMA_BF16(acc[mt][nt], ah, BL[0], BL[1]);
                MMA_BF16(acc[mt][nt], al, BH[0], BH[1]);
            }
        }

        if (more) {
            *(uint4*)(sAh[sn] + aElem) = nah;
            *(uint4*)(sAl[sn] + aElem) = nal;
            stsplit4(sBh[sn], sBl[sn], bIdx, v0);
            stsplit4(sBh[sn], sBl[sn], bIdx + 64, v1);
        }
        __syncthreads();
    }

    // ---- epilogue: stream fp32 to slot buffer ----
    int r = lane >> 2, cp2 = (lane & 3) * 2;
    #pragma unroll
    for (int mt = 0; mt < 4; mt++) {
        #pragma unroll
        for (int half = 0; half < 2; half++) {
            int grow = m0 + wm * 64 + mt * 16 + r + half * 8;
            if (grow >= cnt) continue;
            size_t ob = (size_t)(base + grow) * Hn + n0 + wn * 32 + cp2;
            #pragma unroll
            for (int nt = 0; nt < 4; nt++) {
                float v0 = acc[mt][nt][half * 2 + 0];
                float v1 = acc[mt][nt][half * 2 + 1];
                *(float2*)(g_slotout + ob + nt * 8) = make_float2(v0, v1);
            }
        }
    }
}

// ====================== reduce: sum 4 slots per token ======================
__global__ __launch_bounds__(256) void reduce_kernel(float* __restrict__ out) {
    int t = blockIdx.x;
    int s0 = g_tslot[t * 4 + 0], s1 = g_tslot[t * 4 + 1];
    int s2 = g_tslot[t * 4 + 2], s3 = g_tslot[t * 4 + 3];
    const float* p0 = g_slotout + (size_t)s0 * Hn;
    const float* p1 = g_slotout + (size_t)s1 * Hn;
    const float* p2 = g_slotout + (size_t)s2 * Hn;
    const float* p3 = g_slotout + (size_t)s3 * Hn;
    float* o = out + (size_t)t * Hn;
    for (int i = threadIdx.x * 4; i < Hn; i += 256 * 4) {
        float4 a = *(const float4*)(p0 + i);
        float4 b = *(const float4*)(p1 + i);
        float4 c = *(const float4*)(p2 + i);
        float4 d = *(const float4*)(p3 + i);
        *(float4*)(o + i) = make_float4(a.x + b.x + c.x + d.x,
                                        a.y + b.y + c.y + d.y,
                                        a.z + b.z + c.z + d.z,
                                        a.w + b.w + c.w + d.w);
    }
}

// ====================== launcher ======================
extern "C" void kernel_launch(void* const* d_in, const int* in_sizes, int n_in,
                              void* d_out, int out_size) {
    const float* x  = (const float*)d_in[0];
    const float* gw = (const float*)d_in[1];
    const float* wg = (const float*)d_in[2];
    const float* wu = (const float*)d_in[3];
    const float* wd = (const float*)d_in[4];
    float* out = (float*)d_out;

    float* logits_out = nullptr;
    if (out_size >= Tn * Hn + Tn * En) logits_out = out + (size_t)Tn * Hn;

    convert_x_kernel<<<(Tn * Hn) / 1024, 256>>>(x);
    router_kernel<<<Tn / 4, 256>>>(x, gw, logits_out);
    scan_kernel<<<1, 32>>>();
    scatter_kernel<<<(NSLOT + 255) / 256, 256>>>();
    gemm1_kernel<<<dim3(Fn / 64, MAXTILE), 256>>>(wg, wu);
    gemm2_kernel<<<dim3(Hn / 128, MAXTILE), 256>>>(wd);
    reduce_kernel<<<Tn, 256>>>(out);
}

// round 11
// speedup vs baseline: 2.1822x; 1.0123x over previous
#include <cuda_runtime.h>
#include <cuda_bf16.h>
#include <math.h>
#include <stdint.h>

#define Tn 4096
#define Hn 2048
#define En 32
#define Fn 768
#define TOPK 4
#define NSLOT (Tn * TOPK)
#define MAXTILE 160

// ====================== asm helpers ======================
__device__ __forceinline__ uint32_t smem_u32(const void* p) {
    uint32_t a;
    asm("{ .reg .u64 t; cvta.to.shared.u64 t, %1; cvt.u32.u64 %0, t; }"
        : "=r"(a) : "l"(p));
    return a;
}

#define LDSM_X4(r0, r1, r2, r3, a) \
    asm volatile("ldmatrix.sync.aligned.m8n8.x4.shared.b16 {%0,%1,%2,%3}, [%4];" \
                 : "=r"(r0), "=r"(r1), "=r"(r2), "=r"(r3) : "r"(a))
#define LDSM_X4_T(r0, r1, r2, r3, a) \
    asm volatile("ldmatrix.sync.aligned.m8n8.x4.trans.shared.b16 {%0,%1,%2,%3}, [%4];" \
                 : "=r"(r0), "=r"(r1), "=r"(r2), "=r"(r3) : "r"(a))

#define MMA_BF16(d, a, b0, b1) \
    asm volatile("mma.sync.aligned.m16n8k16.row.col.f32.bf16.bf16.f32 " \
                 "{%0,%1,%2,%3}, {%4,%5,%6,%7}, {%8,%9}, {%0,%1,%2,%3};" \
                 : "+f"((d)[0]), "+f"((d)[1]), "+f"((d)[2]), "+f"((d)[3]) \
                 : "r"((a)[0]), "r"((a)[1]), "r"((a)[2]), "r"((a)[3]), \
                   "r"(b0), "r"(b1))

// ====================== device scratch (~215 MB) ======================
__device__ int   g_counts[En];
__device__ int   g_offsets[En];
__device__ int   g_cursor[En];
__device__ int   g_topk_idx[NSLOT];
__device__ float g_topk_w[NSLOT];
__device__ int   g_tok[NSLOT];
__device__ float g_tokw[NSLOT];
__device__ int   g_tslot[NSLOT];
__device__ int   g_ntiles;
__device__ int   g_tile_e[MAXTILE];
__device__ int   g_tile_m[MAXTILE];

__device__ __align__(256) __nv_bfloat16 g_xhi[(size_t)Tn * Hn];
__device__ __align__(256) __nv_bfloat16 g_xlo[(size_t)Tn * Hn];
__device__ __align__(256) __nv_bfloat16 g_hdnhi[(size_t)NSLOT * Fn];
__device__ __align__(256) __nv_bfloat16 g_hdnlo[(size_t)NSLOT * Fn];
__device__ __align__(256) float         g_slotout[(size_t)NSLOT * Hn];

// ====================== helpers ======================
__device__ __forceinline__ void split1(float f, __nv_bfloat16& h, __nv_bfloat16& l) {
    h = __float2bfloat16(f);
    l = __float2bfloat16(f - __bfloat162float(h));
}
__device__ __forceinline__ void split2(float a, float b, uint32_t& hp, uint32_t& lp) {
    __nv_bfloat162 h = __floats2bfloat162_rn(a, b);
    float r0 = a - __bfloat162float(__low2bfloat16(h));
    float r1 = b - __bfloat162float(__high2bfloat16(h));
    __nv_bfloat162 l = __floats2bfloat162_rn(r0, r1);
    hp = *(uint32_t*)&h; lp = *(uint32_t*)&l;
}
__device__ __forceinline__ void stsplit4(__nv_bfloat16* ph, __nv_bfloat16* pl,
                                         uint32_t idx, float4 v) {
    uint32_t h0, l0, h1, l1;
    split2(v.x, v.y, h0, l0);
    split2(v.z, v.w, h1, l1);
    *(uint32_t*)(ph + idx)     = h0;
    *(uint32_t*)(ph + idx + 2) = h1;
    *(uint32_t*)(pl + idx)     = l0;
    *(uint32_t*)(pl + idx + 2) = l1;
}

// also clears routing counters (block 0)
__global__ __launch_bounds__(256) void convert_x_kernel(const float* __restrict__ x) {
    if (blockIdx.x == 0 && threadIdx.x < En) {
        g_counts[threadIdx.x] = 0;
        g_cursor[threadIdx.x] = 0;
    }
    size_t i = ((size_t)blockIdx.x * 256 + threadIdx.x) * 4;
    float4 v = *(const float4*)(x + i);
    __nv_bfloat16 h0, l0, h1, l1, h2, l2, h3, l3;
    split1(v.x, h0, l0); split1(v.y, h1, l1);
    split1(v.z, h2, l2); split1(v.w, h3, l3);
    g_xhi[i] = h0; g_xhi[i+1] = h1; g_xhi[i+2] = h2; g_xhi[i+3] = h3;
    g_xlo[i] = l0; g_xlo[i+1] = l1; g_xlo[i+2] = l2; g_xlo[i+3] = l3;
}

// ====================== router: 4 tokens per block ======================
__global__ __launch_bounds__(256) void router_kernel(
    const float* __restrict__ x, const float* __restrict__ gw,
    float* __restrict__ logits_out)
{
    int tb = blockIdx.x * 4;
    int tid = threadIdx.x;
    int warp = tid >> 5, lane = tid & 31;
    __shared__ float sx[4][Hn];
    __shared__ float slog[4][En];

    for (int i = tid; i < 4 * Hn; i += 256)
        ((float*)sx)[i] = x[(size_t)tb * Hn + i];
    __syncthreads();

    for (int e = warp; e < En; e += 8) {
        const float* w = gw + (size_t)e * Hn;
        float a0 = 0.f, a1 = 0.f, a2 = 0.f, a3 = 0.f;
        for (int k = lane; k < Hn; k += 32) {
            float wv = w[k];
            a0 += sx[0][k] * wv;
            a1 += sx[1][k] * wv;
            a2 += sx[2][k] * wv;
            a3 += sx[3][k] * wv;
        }
        #pragma unroll
        for (int o = 16; o > 0; o >>= 1) {
            a0 += __shfl_xor_sync(~0u, a0, o);
            a1 += __shfl_xor_sync(~0u, a1, o);
            a2 += __shfl_xor_sync(~0u, a2, o);
            a3 += __shfl_xor_sync(~0u, a3, o);
        }
        if (lane == 0) {
            slog[0][e] = a0; slog[1][e] = a1;
            slog[2][e] = a2; slog[3][e] = a3;
        }
    }
    __syncthreads();

    if (warp < 4) {
        int t = tb + warp;
        float l = slog[warp][lane];
        if (logits_out) logits_out[(size_t)t * En + lane] = l;
        float m = l;
        #pragma unroll
        for (int o = 16; o > 0; o >>= 1) m = fmaxf(m, __shfl_xor_sync(~0u, m, o));
        float p = __expf(l - m), s = p;
        #pragma unroll
        for (int o = 16; o > 0; o >>= 1) s += __shfl_xor_sync(~0u, s, o);
        p /= s;
        float myp = p, tw[TOPK]; int ti[TOPK]; float wsum = 0.f;
        #pragma unroll
        for (int j = 0; j < TOPK; j++) {
            float v = myp; int idx = lane;
            #pragma unroll
            for (int o = 16; o > 0; o >>= 1) {
                float ov = __shfl_xor_sync(~0u, v, o);
                int   oi = __shfl_xor_sync(~0u, idx, o);
                if (ov > v || (ov == v && oi < idx)) { v = ov; idx = oi; }
            }
            tw[j] = v; ti[j] = idx; wsum += v;
            if (lane == idx) myp = -1.f;
        }
        if (lane < TOPK) {
            int e = ti[lane];
            g_topk_idx[t * TOPK + lane] = e;
            g_topk_w[t * TOPK + lane] = tw[lane] / wsum;
            atomicAdd(&g_counts[e], 1);
        }
    }
}

// ====================== fused scan + scatter (single block) ==============
__global__ __launch_bounds__(1024) void scan_scatter_kernel() {
    __shared__ int soff[En];
    int tid = threadIdx.x;
    if (tid < 32) {
        int c = g_counts[tid], inc = c;
        #pragma unroll
        for (int o = 1; o < 32; o <<= 1) {
            int nv = __shfl_up_sync(~0u, inc, o);
            if (tid >= o) inc += nv;
        }
        g_offsets[tid] = inc - c;
        soff[tid] = inc - c;
        if (tid == 0) {
            int nt = 0;
            for (int e = 0; e < En; e++) {
                int cc = g_counts[e];
                for (int m0 = 0; m0 < cc; m0 += 128) {
                    g_tile_e[nt] = e;
                    g_tile_m[nt] = m0;
                    nt++;
                }
            }
            g_ntiles = nt;
        }
    }
    __syncthreads();
    for (int i = tid; i < NSLOT; i += 1024) {
        int e = g_topk_idx[i];
        int pos = atomicAdd(&g_cursor[e], 1);
        int slot = soff[e] + pos;
        g_tok[slot]  = i >> 2;
        g_tokw[slot] = g_topk_w[i];
        g_tslot[i]   = slot;
    }
}

// A rows padded to 48B (24 bf16): banks r*12 mod 32 distinct per 8 rows
#define A_ROWE 24
#define A_PLANE (128 * A_ROWE)
// gemm1 B rows padded to 144B (72 bf16)
#define B1_ROWE 72
#define B1_PLANE (16 * B1_ROWE)
// gemm2 B rows padded to 272B (136 bf16)
#define B2_ROWE 136
#define B2_PLANE (16 * B2_ROWE)

// ====================== GEMM1: 128x64 tile, BK=16 ======================
__global__ __launch_bounds__(256, 2) void gemm1_kernel(
    const float* __restrict__ wg, const float* __restrict__ wu)
{
    __shared__ __align__(16) __nv_bfloat16 sAh[2][A_PLANE], sAl[2][A_PLANE];
    __shared__ __align__(16) __nv_bfloat16 sGh[2][B1_PLANE], sGl[2][B1_PLANE];
    __shared__ __align__(16) __nv_bfloat16 sUh[2][B1_PLANE], sUl[2][B1_PLANE];
    __shared__ int stok[128];

    int ty = blockIdx.y;
    if (ty >= g_ntiles) return;
    int e = g_tile_e[ty];
    int m0 = g_tile_m[ty];
    int cnt = g_counts[e];
    int base = g_offsets[e];
    int n0 = blockIdx.x * 64;
    int tid = threadIdx.x, wid = tid >> 5, lane = tid & 31;

    if (tid < 128) {
        int idx = base + m0 + tid;
        stok[tid] = g_tok[idx < NSLOT ? idx : NSLOT - 1];
    }
    __syncthreads();

    // ---- A loader: 2 threads/row, 16B LDG -> regs -> STS.128 ----
    int arow = tid >> 1, acs = tid & 1;
    const __nv_bfloat16* pAh = g_xhi + (size_t)stok[arow] * Hn + acs * 8;
    const __nv_bfloat16* pAl = g_xlo + (size_t)stok[arow] * Hn + acs * 8;
    uint32_t aElem = (uint32_t)(arow * A_ROWE + acs * 8);

    // ---- B loader: [K][N] direct, float4 per thread per matrix ----
    int bkr = tid >> 4, bn4 = (tid & 15) * 4;
    const float* pG = wg + (size_t)e * Hn * Fn + n0 + bn4;
    const float* pU = wu + (size_t)e * Hn * Fn + n0 + bn4;
    uint32_t bIdx = (uint32_t)(bkr * B1_ROWE + bn4);

    // ---- compute maps ----
    int wm = wid & 1, wn = wid >> 1;
    uint32_t sAh_b = smem_u32(sAh), sAl_b = smem_u32(sAl);
    uint32_t sGh_b = smem_u32(sGh), sGl_b = smem_u32(sGl);
    uint32_t sUh_b = smem_u32(sUh), sUl_b = smem_u32(sUl);
    uint32_t aoff[4];
    {
        int r = wm * 64 + (lane & 15);
        uint32_t c = (uint32_t)(lane >> 4) * 16;
        #pragma unroll
        for (int mt = 0; mt < 4; mt++) aoff[mt] = (uint32_t)(r + mt * 16) * 48 + c;
    }
    uint32_t boff = (uint32_t)(lane & 15) * 144 + (uint32_t)wn * 32 +
                    (uint32_t)(lane >> 4) * 16;

    float accG[4][2][4] = {}, accU[4][2][4] = {};

    // ---- prologue: fill buffer 0 via registers ----
    {
        uint4 ah = *(const uint4*)pAh;
        uint4 al = *(const uint4*)pAl;
        float4 vg = *(const float4*)(pG + (size_t)bkr * Fn);
        float4 vu = *(const float4*)(pU + (size_t)bkr * Fn);
        *(uint4*)(sAh[0] + aElem) = ah;
        *(uint4*)(sAl[0] + aElem) = al;
        stsplit4(sGh[0], sGl[0], bIdx, vg);
        stsplit4(sUh[0], sUl[0], bIdx, vu);
    }
    __syncthreads();

    const int nch = Hn / 16;  // 128
    for (int c = 0; c < nch; c++) {
        int s = c & 1, sn = s ^ 1;
        bool more = (c + 1 < nch);
        uint4 nah, nal;
        float4 vg, vu;
        if (more) {
            int k0n = (c + 1) * 16;
            nah = *(const uint4*)(pAh + k0n);
            nal = *(const uint4*)(pAl + k0n);
            size_t ko = (size_t)(k0n + bkr) * Fn;
            vg = *(const float4*)(pG + ko);
            vu = *(const float4*)(pU + ko);
        }

        uint32_t sAo = (uint32_t)s * (A_PLANE * 2);
        uint32_t sBo = (uint32_t)s * (B1_PLANE * 2);
        uint32_t bgh[4], bgl[4], buh[4], bul[4];
        LDSM_X4_T(bgh[0], bgh[1], bgh[2], bgh[3], sGh_b + sBo + boff);
        LDSM_X4_T(bgl[0], bgl[1], bgl[2], bgl[3], sGl_b + sBo + boff);
        LDSM_X4_T(buh[0], buh[1], buh[2], buh[3], sUh_b + sBo + boff);
        LDSM_X4_T(bul[0], bul[1], bul[2], bul[3], sUl_b + sBo + boff);
        #pragma unroll
        for (int mt = 0; mt < 4; mt++) {
            uint32_t ah[4], al[4];
            LDSM_X4(ah[0], ah[1], ah[2], ah[3], sAh_b + sAo + aoff[mt]);
            LDSM_X4(al[0], al[1], al[2], al[3], sAl_b + sAo + aoff[mt]);
            #pragma unroll
            for (int nt = 0; nt < 2; nt++) {
                MMA_BF16(accG[mt][nt], ah, bgh[nt * 2], bgh[nt * 2 + 1]);
                MMA_BF16(accG[mt][nt], ah, bgl[nt * 2], bgl[nt * 2 + 1]);
                MMA_BF16(accG[mt][nt], al, bgh[nt * 2], bgh[nt * 2 + 1]);
                MMA_BF16(accU[mt][nt], ah, buh[nt * 2], buh[nt * 2 + 1]);
                MMA_BF16(accU[mt][nt], ah, bul[nt * 2], bul[nt * 2 + 1]);
                MMA_BF16(accU[mt][nt], al, buh[nt * 2], buh[nt * 2 + 1]);
            }
        }

        if (more) {
            *(uint4*)(sAh[sn] + aElem) = nah;
            *(uint4*)(sAl[sn] + aElem) = nal;
            stsplit4(sGh[sn], sGl[sn], bIdx, vg);
            stsplit4(sUh[sn], sUl[sn], bIdx, vu);
        }
        __syncthreads();
    }

    // ---- epilogue: h = w * silu(g) * u -> hdn hi/lo (bf16x2 stores) ----
    int r = lane >> 2, cp2 = (lane & 3) * 2;
    #pragma unroll
    for (int mt = 0; mt < 4; mt++) {
        #pragma unroll
        for (int half = 0; half < 2; half++) {
            int grow = m0 + wm * 64 + mt * 16 + r + half * 8;
            if (grow >= cnt) continue;
            int slot = base + grow;
            float wgt = g_tokw[slot];
            size_t ob = (size_t)slot * Fn + n0 + wn * 16 + cp2;
            #pragma unroll
            for (int nt = 0; nt < 2; nt++) {
                float g0 = accG[mt][nt][half * 2 + 0];
                float g1 = accG[mt][nt][half * 2 + 1];
                float u0 = accU[mt][nt][half * 2 + 0];
                float u1 = accU[mt][nt][half * 2 + 1];
                float h0 = wgt * (g0 / (1.f + __expf(-g0))) * u0;
                float h1 = wgt * (g1 / (1.f + __expf(-g1))) * u1;
                uint32_t hp, lp;
                split2(h0, h1, hp, lp);
                *(uint32_t*)(g_hdnhi + ob + nt * 8) = hp;
                *(uint32_t*)(g_hdnlo + ob + nt * 8) = lp;
            }
        }
    }
}

// ====================== GEMM2: 128x128 tile, BK=16 ======================
__global__ __launch_bounds__(256, 2) void gemm2_kernel(const float* __restrict__ wd) {
    __shared__ __align__(16) __nv_bfloat16 sAh[2][A_PLANE], sAl[2][A_PLANE];
    __shared__ __align__(16) __nv_bfloat16 sBh[2][B2_PLANE], sBl[2][B2_PLANE];

    int ty = blockIdx.y;
    if (ty >= g_ntiles) return;
    int e = g_tile_e[ty];
    int m0 = g_tile_m[ty];
    int cnt = g_counts[e];
    int base = g_offsets[e];
    int n0 = blockIdx.x * 128;
    int tid = threadIdx.x, wid = tid >> 5, lane = tid & 31;

    int arow = tid >> 1, acs = tid & 1;
    int sl = base + m0 + arow; if (sl >= NSLOT) sl = NSLOT - 1;
    const __nv_bfloat16* pAh = g_hdnhi + (size_t)sl * Fn + acs * 8;
    const __nv_bfloat16* pAl = g_hdnlo + (size_t)sl * Fn + acs * 8;
    uint32_t aElem = (uint32_t)(arow * A_ROWE + acs * 8);

    int bkr = tid >> 4, bn4 = (tid & 15) * 4;
    const float* pB = wd + (size_t)e * Fn * Hn + n0 + bn4;
    uint32_t bIdx = (uint32_t)(bkr * B2_ROWE + bn4);

    int wm = wid & 1, wn = wid >> 1;
    uint32_t sAh_b = smem_u32(sAh), sAl_b = smem_u32(sAl);
    uint32_t sBh_b = smem_u32(sBh), sBl_b = smem_u32(sBl);
    uint32_t aoff[4];
    {
        int r = wm * 64 + (lane & 15);
        uint32_t c = (uint32_t)(lane >> 4) * 16;
        #pragma unroll
        for (int mt = 0; mt < 4; mt++) aoff[mt] = (uint32_t)(r + mt * 16) * 48 + c;
    }
    uint32_t boff[2];
    {
        uint32_t rb = (uint32_t)(lane & 15) * 272 + (uint32_t)(lane >> 4) * 16;
        boff[0] = rb + (uint32_t)wn * 64;
        boff[1] = rb + (uint32_t)wn * 64 + 32;
    }

    float acc[4][4][4] = {};

    // ---- prologue ----
    {
        uint4 ah = *(const uint4*)pAh;
        uint4 al = *(const uint4*)pAl;
        size_t ko = (size_t)bkr * Hn;
        float4 v0 = *(const float4*)(pB + ko);
        float4 v1 = *(const float4*)(pB + ko + 64);
        *(uint4*)(sAh[0] + aElem) = ah;
        *(uint4*)(sAl[0] + aElem) = al;
        stsplit4(sBh[0], sBl[0], bIdx, v0);
        stsplit4(sBh[0], sBl[0], bIdx + 64, v1);
    }
    __syncthreads();

    const int nch = Fn / 16;  // 48
    for (int c = 0; c < nch; c++) {
        int s = c & 1, sn = s ^ 1;
        bool more = (c + 1 < nch);
        uint4 nah, nal;
        float4 v0, v1;
        if (more) {
            int k0n = (c + 1) * 16;
            nah = *(const uint4*)(pAh + k0n);
            nal = *(const uint4*)(pAl + k0n);
            size_t ko = (size_t)(k0n + bkr) * Hn;
            v0 = *(const float4*)(pB + ko);
            v1 = *(const float4*)(pB + ko + 64);
        }

        uint32_t sAo = (uint32_t)s * (A_PLANE * 2);
        uint32_t sBo = (uint32_t)s * (B2_PLANE * 2);
        uint32_t bh[2][4], bl[2][4];
        #pragma unroll
        for (int p = 0; p < 2; p++) {
            LDSM_X4_T(bh[p][0], bh[p][1], bh[p][2], bh[p][3], sBh_b + sBo + boff[p]);
            LDSM_X4_T(bl[p][0], bl[p][1], bl[p][2], bl[p][3], sBl_b + sBo + boff[p]);
        }
        #pragma unroll
        for (int mt = 0; mt < 4; mt++) {
            uint32_t ah[4], al[4];
            LDSM_X4(ah[0], ah[1], ah[2], ah[3], sAh_b + sAo + aoff[mt]);
            LDSM_X4(al[0], al[1], al[2], al[3], sAl_b + sAo + aoff[mt]);
            #pragma unroll
            for (int nt = 0; nt < 4; nt++) {
                uint32_t* BH = &bh[nt >> 1][(nt & 1) * 2];
                uint32_t* BL = &bl[nt >> 1][(nt & 1) * 2];
                MMA_BF16(acc[mt][nt], ah, BH[0], BH[1]);
                MMA_BF16(acc[mt][nt], ah, BL[0], BL[1]);
                MMA_BF16(acc[mt][nt], al, BH[0], BH[1]);
            }
        }

        if (more) {
            *(uint4*)(sAh[sn] + aElem) = nah;
            *(uint4*)(sAl[sn] + aElem) = nal;
            stsplit4(sBh[sn], sBl[sn], bIdx, v0);
            stsplit4(sBh[sn], sBl[sn], bIdx + 64, v1);
        }
        __syncthreads();
    }

    // ---- epilogue: stream fp32 to slot buffer ----
    int r = lane >> 2, cp2 = (lane & 3) * 2;
    #pragma unroll
    for (int mt = 0; mt < 4; mt++) {
        #pragma unroll
        for (int half = 0; half < 2; half++) {
            int grow = m0 + wm * 64 + mt * 16 + r + half * 8;
            if (grow >= cnt) continue;
            size_t ob = (size_t)(base + grow) * Hn + n0 + wn * 32 + cp2;
            #pragma unroll
            for (int nt = 0; nt < 4; nt++) {
                float v0 = acc[mt][nt][half * 2 + 0];
                float v1 = acc[mt][nt][half * 2 + 1];
                *(float2*)(g_slotout + ob + nt * 8) = make_float2(v0, v1);
            }
        }
    }
}

// ====================== reduce: sum 4 slots per token ======================
__global__ __launch_bounds__(256) void reduce_kernel(float* __restrict__ out) {
    int t = blockIdx.x;
    int s0 = g_tslot[t * 4 + 0], s1 = g_tslot[t * 4 + 1];
    int s2 = g_tslot[t * 4 + 2], s3 = g_tslot[t * 4 + 3];
    const float* p0 = g_slotout + (size_t)s0 * Hn;
    const float* p1 = g_slotout + (size_t)s1 * Hn;
    const float* p2 = g_slotout + (size_t)s2 * Hn;
    const float* p3 = g_slotout + (size_t)s3 * Hn;
    float* o = out + (size_t)t * Hn;
    for (int i = threadIdx.x * 4; i < Hn; i += 256 * 4) {
        float4 a = *(const float4*)(p0 + i);
        float4 b = *(const float4*)(p1 + i);
        float4 c = *(const float4*)(p2 + i);
        float4 d = *(const float4*)(p3 + i);
        *(float4*)(o + i) = make_float4(a.x + b.x + c.x + d.x,
                                        a.y + b.y + c.y + d.y,
                                        a.z + b.z + c.z + d.z,
                                        a.w + b.w + c.w + d.w);
    }
}

// ====================== launcher ======================
extern "C" void kernel_launch(void* const* d_in, const int* in_sizes, int n_in,
                              void* d_out, int out_size) {
    const float* x  = (const float*)d_in[0];
    const float* gw = (const float*)d_in[1];
    const float* wg = (const float*)d_in[2];
    const float* wu = (const float*)d_in[3];
    const float* wd = (const float*)d_in[4];
    float* out = (float*)d_out;

    float* logits_out = nullptr;
    if (out_size >= Tn * Hn + Tn * En) logits_out = out + (size_t)Tn * Hn;

    convert_x_kernel<<<(Tn * Hn) / 1024, 256>>>(x);
    router_kernel<<<Tn / 4, 256>>>(x, gw, logits_out);
    scan_scatter_kernel<<<1, 1024>>>();
    gemm1_kernel<<<dim3(Fn / 64, MAXTILE), 256>>>(wg, wu);
    gemm2_kernel<<<dim3(Hn / 128, MAXTILE), 256>>>(wd);
    reduce_kernel<<<Tn, 256>>>(out);
}

// round 12
// speedup vs baseline: 2.2957x; 1.0520x over previous
#include <cuda_runtime.h>
#include <cuda_bf16.h>
#include <math.h>
#include <stdint.h>

#define Tn 4096
#define Hn 2048
#define En 32
#define Fn 768
#define TOPK 4
#define NSLOT (Tn * TOPK)
#define MAXTILE 160

// ====================== asm helpers ======================
__device__ __forceinline__ uint32_t smem_u32(const void* p) {
    uint32_t a;
    asm("{ .reg .u64 t; cvta.to.shared.u64 t, %1; cvt.u32.u64 %0, t; }"
        : "=r"(a) : "l"(p));
    return a;
}

#define LDSM_X4(r0, r1, r2, r3, a) \
    asm volatile("ldmatrix.sync.aligned.m8n8.x4.shared.b16 {%0,%1,%2,%3}, [%4];" \
                 : "=r"(r0), "=r"(r1), "=r"(r2), "=r"(r3) : "r"(a))
#define LDSM_X4_T(r0, r1, r2, r3, a) \
    asm volatile("ldmatrix.sync.aligned.m8n8.x4.trans.shared.b16 {%0,%1,%2,%3}, [%4];" \
                 : "=r"(r0), "=r"(r1), "=r"(r2), "=r"(r3) : "r"(a))

#define MMA_BF16(d, a, b0, b1) \
    asm volatile("mma.sync.aligned.m16n8k16.row.col.f32.bf16.bf16.f32 " \
                 "{%0,%1,%2,%3}, {%4,%5,%6,%7}, {%8,%9}, {%0,%1,%2,%3};" \
                 : "+f"((d)[0]), "+f"((d)[1]), "+f"((d)[2]), "+f"((d)[3]) \
                 : "r"((a)[0]), "r"((a)[1]), "r"((a)[2]), "r"((a)[3]), \
                   "r"(b0), "r"(b1))

// ====================== device scratch (~215 MB) ======================
__device__ int   g_counts[En];
__device__ int   g_offsets[En];
__device__ int   g_cursor[En];
__device__ int   g_topk_idx[NSLOT];
__device__ float g_topk_w[NSLOT];
__device__ int   g_tok[NSLOT];
__device__ float g_tokw[NSLOT];
__device__ int   g_tslot[NSLOT];
__device__ int   g_ntiles;
__device__ int   g_tile_e[MAXTILE];
__device__ int   g_tile_m[MAXTILE];

__device__ __align__(256) __nv_bfloat16 g_xhi[(size_t)Tn * Hn];
__device__ __align__(256) __nv_bfloat16 g_xlo[(size_t)Tn * Hn];
__device__ __align__(256) __nv_bfloat16 g_hdnhi[(size_t)NSLOT * Fn];
__device__ __align__(256) __nv_bfloat16 g_hdnlo[(size_t)NSLOT * Fn];
__device__ __align__(256) float         g_slotout[(size_t)NSLOT * Hn];

// ====================== helpers ======================
__device__ __forceinline__ void split1(float f, __nv_bfloat16& h, __nv_bfloat16& l) {
    h = __float2bfloat16(f);
    l = __float2bfloat16(f - __bfloat162float(h));
}
__device__ __forceinline__ void split2(float a, float b, uint32_t& hp, uint32_t& lp) {
    __nv_bfloat162 h = __floats2bfloat162_rn(a, b);
    float r0 = a - __bfloat162float(__low2bfloat16(h));
    float r1 = b - __bfloat162float(__high2bfloat16(h));
    __nv_bfloat162 l = __floats2bfloat162_rn(r0, r1);
    hp = *(uint32_t*)&h; lp = *(uint32_t*)&l;
}
__device__ __forceinline__ void stsplit4(__nv_bfloat16* ph, __nv_bfloat16* pl,
                                         uint32_t idx, float4 v) {
    uint32_t h0, l0, h1, l1;
    split2(v.x, v.y, h0, l0);
    split2(v.z, v.w, h1, l1);
    *(uint32_t*)(ph + idx)     = h0;
    *(uint32_t*)(ph + idx + 2) = h1;
    *(uint32_t*)(pl + idx)     = l0;
    *(uint32_t*)(pl + idx + 2) = l1;
}

// also clears routing counters (block 0)
__global__ __launch_bounds__(256) void convert_x_kernel(const float* __restrict__ x) {
    if (blockIdx.x == 0 && threadIdx.x < En) {
        g_counts[threadIdx.x] = 0;
        g_cursor[threadIdx.x] = 0;
    }
    size_t i = ((size_t)blockIdx.x * 256 + threadIdx.x) * 4;
    float4 v = *(const float4*)(x + i);
    __nv_bfloat16 h0, l0, h1, l1, h2, l2, h3, l3;
    split1(v.x, h0, l0); split1(v.y, h1, l1);
    split1(v.z, h2, l2); split1(v.w, h3, l3);
    g_xhi[i] = h0; g_xhi[i+1] = h1; g_xhi[i+2] = h2; g_xhi[i+3] = h3;
    g_xlo[i] = l0; g_xlo[i+1] = l1; g_xlo[i+2] = l2; g_xlo[i+3] = l3;
}

// ====================== router: 4 tokens per block ======================
__global__ __launch_bounds__(256) void router_kernel(
    const float* __restrict__ x, const float* __restrict__ gw,
    float* __restrict__ logits_out)
{
    int tb = blockIdx.x * 4;
    int tid = threadIdx.x;
    int warp = tid >> 5, lane = tid & 31;
    __shared__ float sx[4][Hn];
    __shared__ float slog[4][En];

    for (int i = tid; i < 4 * Hn; i += 256)
        ((float*)sx)[i] = x[(size_t)tb * Hn + i];
    __syncthreads();

    for (int e = warp; e < En; e += 8) {
        const float* w = gw + (size_t)e * Hn;
        float a0 = 0.f, a1 = 0.f, a2 = 0.f, a3 = 0.f;
        for (int k = lane; k < Hn; k += 32) {
            float wv = w[k];
            a0 += sx[0][k] * wv;
            a1 += sx[1][k] * wv;
            a2 += sx[2][k] * wv;
            a3 += sx[3][k] * wv;
        }
        #pragma unroll
        for (int o = 16; o > 0; o >>= 1) {
            a0 += __shfl_xor_sync(~0u, a0, o);
            a1 += __shfl_xor_sync(~0u, a1, o);
            a2 += __shfl_xor_sync(~0u, a2, o);
            a3 += __shfl_xor_sync(~0u, a3, o);
        }
        if (lane == 0) {
            slog[0][e] = a0; slog[1][e] = a1;
            slog[2][e] = a2; slog[3][e] = a3;
        }
    }
    __syncthreads();

    if (warp < 4) {
        int t = tb + warp;
        float l = slog[warp][lane];
        if (logits_out) logits_out[(size_t)t * En + lane] = l;
        float m = l;
        #pragma unroll
        for (int o = 16; o > 0; o >>= 1) m = fmaxf(m, __shfl_xor_sync(~0u, m, o));
        float p = __expf(l - m), s = p;
        #pragma unroll
        for (int o = 16; o > 0; o >>= 1) s += __shfl_xor_sync(~0u, s, o);
        p /= s;
        float myp = p, tw[TOPK]; int ti[TOPK]; float wsum = 0.f;
        #pragma unroll
        for (int j = 0; j < TOPK; j++) {
            float v = myp; int idx = lane;
            #pragma unroll
            for (int o = 16; o > 0; o >>= 1) {
                float ov = __shfl_xor_sync(~0u, v, o);
                int   oi = __shfl_xor_sync(~0u, idx, o);
                if (ov > v || (ov == v && oi < idx)) { v = ov; idx = oi; }
            }
            tw[j] = v; ti[j] = idx; wsum += v;
            if (lane == idx) myp = -1.f;
        }
        if (lane < TOPK) {
            int e = ti[lane];
            g_topk_idx[t * TOPK + lane] = e;
            g_topk_w[t * TOPK + lane] = tw[lane] / wsum;
            atomicAdd(&g_counts[e], 1);
        }
    }
}

// ====================== fused scan + scatter (single block) ==============
__global__ __launch_bounds__(1024) void scan_scatter_kernel() {
    __shared__ int soff[En];
    int tid = threadIdx.x;
    if (tid < 32) {
        int c = g_counts[tid], inc = c;
        #pragma unroll
        for (int o = 1; o < 32; o <<= 1) {
            int nv = __shfl_up_sync(~0u, inc, o);
            if (tid >= o) inc += nv;
        }
        g_offsets[tid] = inc - c;
        soff[tid] = inc - c;
        if (tid == 0) {
            int nt = 0;
            for (int e = 0; e < En; e++) {
                int cc = g_counts[e];
                for (int m0 = 0; m0 < cc; m0 += 128) {
                    g_tile_e[nt] = e;
                    g_tile_m[nt] = m0;
                    nt++;
                }
            }
            g_ntiles = nt;
        }
    }
    __syncthreads();
    for (int i = tid; i < NSLOT; i += 1024) {
        int e = g_topk_idx[i];
        int pos = atomicAdd(&g_cursor[e], 1);
        int slot = soff[e] + pos;
        g_tok[slot]  = i >> 2;
        g_tokw[slot] = g_topk_w[i];
        g_tslot[i]   = slot;
    }
}

// A rows padded to 48B (24 bf16): banks r*12 mod 32 distinct per 8 rows
#define A_ROWE 24
#define A_PLANE (128 * A_ROWE)
// gemm1 B rows padded to 144B (72 bf16)
#define B1_ROWE 72
#define B1_PLANE (16 * B1_ROWE)
// gemm2 B rows padded to 272B (136 bf16)
#define B2_ROWE 136
#define B2_PLANE (16 * B2_ROWE)

// ====================== GEMM1: 128x64 tile, 4 warps (64x32 each) =========
__global__ __launch_bounds__(128, 2) void gemm1_kernel(
    const float* __restrict__ wg, const float* __restrict__ wu)
{
    __shared__ __align__(16) __nv_bfloat16 sAh[2][A_PLANE], sAl[2][A_PLANE];
    __shared__ __align__(16) __nv_bfloat16 sGh[2][B1_PLANE], sGl[2][B1_PLANE];
    __shared__ __align__(16) __nv_bfloat16 sUh[2][B1_PLANE], sUl[2][B1_PLANE];
    __shared__ int stok[128];

    int ty = blockIdx.y;
    if (ty >= g_ntiles) return;
    int e = g_tile_e[ty];
    int m0 = g_tile_m[ty];
    int cnt = g_counts[e];
    int base = g_offsets[e];
    int n0 = blockIdx.x * 64;
    int tid = threadIdx.x, wid = tid >> 5, lane = tid & 31;

    {
        int idx = base + m0 + tid;
        stok[tid] = g_tok[idx < NSLOT ? idx : NSLOT - 1];
    }
    __syncthreads();

    // ---- A loader: 2 rows/thread (rows t>>1 and 64+t>>1), 16B halves ----
    int ar0 = tid >> 1, ar1 = 64 + (tid >> 1), acs = tid & 1;
    const __nv_bfloat16* pAh0 = g_xhi + (size_t)stok[ar0] * Hn + acs * 8;
    const __nv_bfloat16* pAl0 = g_xlo + (size_t)stok[ar0] * Hn + acs * 8;
    const __nv_bfloat16* pAh1 = g_xhi + (size_t)stok[ar1] * Hn + acs * 8;
    const __nv_bfloat16* pAl1 = g_xlo + (size_t)stok[ar1] * Hn + acs * 8;
    uint32_t aE0 = (uint32_t)(ar0 * A_ROWE + acs * 8);
    uint32_t aE1 = (uint32_t)(ar1 * A_ROWE + acs * 8);

    // ---- B loader: rows bk0, bk0+8; float4 per row per matrix ----
    int bk0 = tid >> 4, bk1 = bk0 + 8, bn4 = (tid & 15) * 4;
    const float* pG = wg + (size_t)e * Hn * Fn + n0 + bn4;
    const float* pU = wu + (size_t)e * Hn * Fn + n0 + bn4;
    uint32_t bI0 = (uint32_t)(bk0 * B1_ROWE + bn4);
    uint32_t bI1 = (uint32_t)(bk1 * B1_ROWE + bn4);

    // ---- compute maps: 4 warps = 2 (M) x 2 (N); warp tile 64x32 ----
    int wm = wid & 1, wn = wid >> 1;
    uint32_t sAh_b = smem_u32(sAh), sAl_b = smem_u32(sAl);
    uint32_t sGh_b = smem_u32(sGh), sGl_b = smem_u32(sGl);
    uint32_t sUh_b = smem_u32(sUh), sUl_b = smem_u32(sUl);
    uint32_t aoff[4];
    {
        int r = wm * 64 + (lane & 15);
        uint32_t c = (uint32_t)(lane >> 4) * 16;
        #pragma unroll
        for (int mt = 0; mt < 4; mt++) aoff[mt] = (uint32_t)(r + mt * 16) * 48 + c;
    }
    uint32_t rb = (uint32_t)(lane & 15) * 144 + (uint32_t)(lane >> 4) * 16;
    uint32_t boff0 = rb + (uint32_t)wn * 64;
    uint32_t boff1 = boff0 + 32;

    float accG[4][4][4] = {}, accU[4][4][4] = {};

    // ---- prologue: fill buffer 0 ----
    {
        uint4 a0h = *(const uint4*)pAh0, a0l = *(const uint4*)pAl0;
        uint4 a1h = *(const uint4*)pAh1, a1l = *(const uint4*)pAl1;
        float4 vg0 = *(const float4*)(pG + (size_t)bk0 * Fn);
        float4 vg1 = *(const float4*)(pG + (size_t)bk1 * Fn);
        float4 vu0 = *(const float4*)(pU + (size_t)bk0 * Fn);
        float4 vu1 = *(const float4*)(pU + (size_t)bk1 * Fn);
        *(uint4*)(sAh[0] + aE0) = a0h;
        *(uint4*)(sAl[0] + aE0) = a0l;
        *(uint4*)(sAh[0] + aE1) = a1h;
        *(uint4*)(sAl[0] + aE1) = a1l;
        stsplit4(sGh[0], sGl[0], bI0, vg0);
        stsplit4(sGh[0], sGl[0], bI1, vg1);
        stsplit4(sUh[0], sUl[0], bI0, vu0);
        stsplit4(sUh[0], sUl[0], bI1, vu1);
    }
    __syncthreads();

    const int nch = Hn / 16;  // 128
    for (int c = 0; c < nch; c++) {
        int s = c & 1, sn = s ^ 1;
        bool more = (c + 1 < nch);
        uint4 na0h, na0l, na1h, na1l;
        float4 vg0, vg1, vu0, vu1;
        if (more) {
            int k0n = (c + 1) * 16;
            na0h = *(const uint4*)(pAh0 + k0n);
            na0l = *(const uint4*)(pAl0 + k0n);
            na1h = *(const uint4*)(pAh1 + k0n);
            na1l = *(const uint4*)(pAl1 + k0n);
            vg0 = *(const float4*)(pG + (size_t)(k0n + bk0) * Fn);
            vg1 = *(const float4*)(pG + (size_t)(k0n + bk1) * Fn);
            vu0 = *(const float4*)(pU + (size_t)(k0n + bk0) * Fn);
            vu1 = *(const float4*)(pU + (size_t)(k0n + bk1) * Fn);
        }

        uint32_t sAo = (uint32_t)s * (A_PLANE * 2);
        uint32_t sBo = (uint32_t)s * (B1_PLANE * 2);
        uint32_t bgh[2][4], bgl[2][4], buh[2][4], bul[2][4];
        LDSM_X4_T(bgh[0][0], bgh[0][1], bgh[0][2], bgh[0][3], sGh_b + sBo + boff0);
        LDSM_X4_T(bgh[1][0], bgh[1][1], bgh[1][2], bgh[1][3], sGh_b + sBo + boff1);
        LDSM_X4_T(bgl[0][0], bgl[0][1], bgl[0][2], bgl[0][3], sGl_b + sBo + boff0);
        LDSM_X4_T(bgl[1][0], bgl[1][1], bgl[1][2], bgl[1][3], sGl_b + sBo + boff1);
        LDSM_X4_T(buh[0][0], buh[0][1], buh[0][2], buh[0][3], sUh_b + sBo + boff0);
        LDSM_X4_T(buh[1][0], buh[1][1], buh[1][2], buh[1][3], sUh_b + sBo + boff1);
        LDSM_X4_T(bul[0][0], bul[0][1], bul[0][2], bul[0][3], sUl_b + sBo + boff0);
        LDSM_X4_T(bul[1][0], bul[1][1], bul[1][2], bul[1][3], sUl_b + sBo + boff1);
        #pragma unroll
        for (int mt = 0; mt < 4; mt++) {
            uint32_t ah[4], al[4];
            LDSM_X4(ah[0], ah[1], ah[2], ah[3], sAh_b + sAo + aoff[mt]);
            LDSM_X4(al[0], al[1], al[2], al[3], sAl_b + sAo + aoff[mt]);
            #pragma unroll
            for (int nt = 0; nt < 4; nt++) {
                uint32_t* GH = &bgh[nt >> 1][(nt & 1) * 2];
                uint32_t* GL = &bgl[nt >> 1][(nt & 1) * 2];
                uint32_t* UH = &buh[nt >> 1][(nt & 1) * 2];
                uint32_t* UL = &bul[nt >> 1][(nt & 1) * 2];
                MMA_BF16(accG[mt][nt], ah, GH[0], GH[1]);
                MMA_BF16(accG[mt][nt], ah, GL[0], GL[1]);
                MMA_BF16(accG[mt][nt], al, GH[0], GH[1]);
                MMA_BF16(accU[mt][nt], ah, UH[0], UH[1]);
                MMA_BF16(accU[mt][nt], ah, UL[0], UL[1]);
                MMA_BF16(accU[mt][nt], al, UH[0], UH[1]);
            }
        }

        if (more) {
            *(uint4*)(sAh[sn] + aE0) = na0h;
            *(uint4*)(sAl[sn] + aE0) = na0l;
            *(uint4*)(sAh[sn] + aE1) = na1h;
            *(uint4*)(sAl[sn] + aE1) = na1l;
            stsplit4(sGh[sn], sGl[sn], bI0, vg0);
            stsplit4(sGh[sn], sGl[sn], bI1, vg1);
            stsplit4(sUh[sn], sUl[sn], bI0, vu0);
            stsplit4(sUh[sn], sUl[sn], bI1, vu1);
        }
        __syncthreads();
    }

    // ---- epilogue: h = w * silu(g) * u -> hdn hi/lo (bf16x2 stores) ----
    int r = lane >> 2, cp2 = (lane & 3) * 2;
    #pragma unroll
    for (int mt = 0; mt < 4; mt++) {
        #pragma unroll
        for (int half = 0; half < 2; half++) {
            int grow = m0 + wm * 64 + mt * 16 + r + half * 8;
            if (grow >= cnt) continue;
            int slot = base + grow;
            float wgt = g_tokw[slot];
            size_t ob = (size_t)slot * Fn + n0 + wn * 32 + cp2;
            #pragma unroll
            for (int nt = 0; nt < 4; nt++) {
                float g0 = accG[mt][nt][half * 2 + 0];
                float g1 = accG[mt][nt][half * 2 + 1];
                float u0 = accU[mt][nt][half * 2 + 0];
                float u1 = accU[mt][nt][half * 2 + 1];
                float h0 = wgt * (g0 / (1.f + __expf(-g0))) * u0;
                float h1 = wgt * (g1 / (1.f + __expf(-g1))) * u1;
                uint32_t hp, lp;
                split2(h0, h1, hp, lp);
                *(uint32_t*)(g_hdnhi + ob + nt * 8) = hp;
                *(uint32_t*)(g_hdnlo + ob + nt * 8) = lp;
            }
        }
    }
}

// ====================== GEMM2: 128x128 tile, 4 warps (64x64 each) ========
__global__ __launch_bounds__(128, 2) void gemm2_kernel(const float* __restrict__ wd) {
    __shared__ __align__(16) __nv_bfloat16 sAh[2][A_PLANE], sAl[2][A_PLANE];
    __shared__ __align__(16) __nv_bfloat16 sBh[2][B2_PLANE], sBl[2][B2_PLANE];

    int ty = blockIdx.y;
    if (ty >= g_ntiles) return;
    int e = g_tile_e[ty];
    int m0 = g_tile_m[ty];
    int cnt = g_counts[e];
    int base = g_offsets[e];
    int n0 = blockIdx.x * 128;
    int tid = threadIdx.x, wid = tid >> 5, lane = tid & 31;

    // ---- A loader: 2 rows/thread ----
    int ar0 = tid >> 1, ar1 = 64 + (tid >> 1), acs = tid & 1;
    int sl0 = base + m0 + ar0; if (sl0 >= NSLOT) sl0 = NSLOT - 1;
    int sl1 = base + m0 + ar1; if (sl1 >= NSLOT) sl1 = NSLOT - 1;
    const __nv_bfloat16* pAh0 = g_hdnhi + (size_t)sl0 * Fn + acs * 8;
    const __nv_bfloat16* pAl0 = g_hdnlo + (size_t)sl0 * Fn + acs * 8;
    const __nv_bfloat16* pAh1 = g_hdnhi + (size_t)sl1 * Fn + acs * 8;
    const __nv_bfloat16* pAl1 = g_hdnlo + (size_t)sl1 * Fn + acs * 8;
    uint32_t aE0 = (uint32_t)(ar0 * A_ROWE + acs * 8);
    uint32_t aE1 = (uint32_t)(ar1 * A_ROWE + acs * 8);

    // ---- B loader: rows bk0, bk0+8; 2 col-halves each ----
    int bk0 = tid >> 4, bk1 = bk0 + 8, bn4 = (tid & 15) * 4;
    const float* pB = wd + (size_t)e * Fn * Hn + n0 + bn4;
    uint32_t bI0 = (uint32_t)(bk0 * B2_ROWE + bn4);
    uint32_t bI1 = (uint32_t)(bk1 * B2_ROWE + bn4);

    int wm = wid & 1, wn = wid >> 1;
    uint32_t sAh_b = smem_u32(sAh), sAl_b = smem_u32(sAl);
    uint32_t sBh_b = smem_u32(sBh), sBl_b = smem_u32(sBl);
    uint32_t aoff[4];
    {
        int r = wm * 64 + (lane & 15);
        uint32_t c = (uint32_t)(lane >> 4) * 16;
        #pragma unroll
        for (int mt = 0; mt < 4; mt++) aoff[mt] = (uint32_t)(r + mt * 16) * 48 + c;
    }
    uint32_t boff[4];
    {
        uint32_t rb = (uint32_t)(lane & 15) * 272 + (uint32_t)(lane >> 4) * 16;
        #pragma unroll
        for (int p = 0; p < 4; p++) boff[p] = rb + (uint32_t)wn * 128 + p * 32;
    }

    float acc[4][8][4] = {};

    // ---- prologue ----
    {
        uint4 a0h = *(const uint4*)pAh0, a0l = *(const uint4*)pAl0;
        uint4 a1h = *(const uint4*)pAh1, a1l = *(const uint4*)pAl1;
        float4 v00 = *(const float4*)(pB + (size_t)bk0 * Hn);
        float4 v01 = *(const float4*)(pB + (size_t)bk0 * Hn + 64);
        float4 v10 = *(const float4*)(pB + (size_t)bk1 * Hn);
        float4 v11 = *(const float4*)(pB + (size_t)bk1 * Hn + 64);
        *(uint4*)(sAh[0] + aE0) = a0h;
        *(uint4*)(sAl[0] + aE0) = a0l;
        *(uint4*)(sAh[0] + aE1) = a1h;
        *(uint4*)(sAl[0] + aE1) = a1l;
        stsplit4(sBh[0], sBl[0], bI0, v00);
        stsplit4(sBh[0], sBl[0], bI0 + 64, v01);
        stsplit4(sBh[0], sBl[0], bI1, v10);
        stsplit4(sBh[0], sBl[0], bI1 + 64, v11);
    }
    __syncthreads();

    const int nch = Fn / 16;  // 48
    for (int c = 0; c < nch; c++) {
        int s = c & 1, sn = s ^ 1;
        bool more = (c + 1 < nch);
        uint4 na0h, na0l, na1h, na1l;
        float4 v00, v01, v10, v11;
        if (more) {
            int k0n = (c + 1) * 16;
            na0h = *(const uint4*)(pAh0 + k0n);
            na0l = *(const uint4*)(pAl0 + k0n);
            na1h = *(const uint4*)(pAh1 + k0n);
            na1l = *(const uint4*)(pAl1 + k0n);
            v00 = *(const float4*)(pB + (size_t)(k0n + bk0) * Hn);
            v01 = *(const float4*)(pB + (size_t)(k0n + bk0) * Hn + 64);
            v10 = *(const float4*)(pB + (size_t)(k0n + bk1) * Hn);
            v11 = *(const float4*)(pB + (size_t)(k0n + bk1) * Hn + 64);
        }

        uint32_t sAo = (uint32_t)s * (A_PLANE * 2);
        uint32_t sBo = (uint32_t)s * (B2_PLANE * 2);
        uint32_t bh[4][4], bl[4][4];
        #pragma unroll
        for (int p = 0; p < 4; p++) {
            LDSM_X4_T(bh[p][0], bh[p][1], bh[p][2], bh[p][3], sBh_b + sBo + boff[p]);
            LDSM_X4_T(bl[p][0], bl[p][1], bl[p][2], bl[p][3], sBl_b + sBo + boff[p]);
        }
        #pragma unroll
        for (int mt = 0; mt < 4; mt++) {
            uint32_t ah[4], al[4];
            LDSM_X4(ah[0], ah[1], ah[2], ah[3], sAh_b + sAo + aoff[mt]);
            LDSM_X4(al[0], al[1], al[2], al[3], sAl_b + sAo + aoff[mt]);
            #pragma unroll
            for (int nt = 0; nt < 8; nt++) {
                uint32_t* BH = &bh[nt >> 1][(nt & 1) * 2];
                uint32_t* BL = &bl[nt >> 1][(nt & 1) * 2];
                MMA_BF16(acc[mt][nt], ah, BH[0], BH[1]);
                MMA_BF16(acc[mt][nt], ah, BL[0], BL[1]);
                MMA_BF16(acc[mt][nt], al, BH[0], BH[1]);
            }
        }

        if (more) {
            *(uint4*)(sAh[sn] + aE0) = na0h;
            *(uint4*)(sAl[sn] + aE0) = na0l;
            *(uint4*)(sAh[sn] + aE1) = na1h;
            *(uint4*)(sAl[sn] + aE1) = na1l;
            stsplit4(sBh[sn], sBl[sn], bI0, v00);
            stsplit4(sBh[sn], sBl[sn], bI0 + 64, v01);
            stsplit4(sBh[sn], sBl[sn], bI1, v10);
            stsplit4(sBh[sn], sBl[sn], bI1 + 64, v11);
        }
        __syncthreads();
    }

    // ---- epilogue: stream fp32 to slot buffer ----
    int r = lane >> 2, cp2 = (lane & 3) * 2;
    #pragma unroll
    for (int mt = 0; mt < 4; mt++) {
        #pragma unroll
        for (int half = 0; half < 2; half++) {
            int grow = m0 + wm * 64 + mt * 16 + r + half * 8;
            if (grow >= cnt) continue;
            size_t ob = (size_t)(base + grow) * Hn + n0 + wn * 64 + cp2;
            #pragma unroll
            for (int nt = 0; nt < 8; nt++) {
                float v0 = acc[mt][nt][half * 2 + 0];
                float v1 = acc[mt][nt][half * 2 + 1];
                *(float2*)(g_slotout + ob + nt * 8) = make_float2(v0, v1);
            }
        }
    }
}

// ====================== reduce: sum 4 slots per token ======================
__global__ __launch_bounds__(256) void reduce_kernel(float* __restrict__ out) {
    int t = blockIdx.x;
    int s0 = g_tslot[t * 4 + 0], s1 = g_tslot[t * 4 + 1];
    int s2 = g_tslot[t * 4 + 2], s3 = g_tslot[t * 4 + 3];
    const float* p0 = g_slotout + (size_t)s0 * Hn;
    const float* p1 = g_slotout + (size_t)s1 * Hn;
    const float* p2 = g_slotout + (size_t)s2 * Hn;
    const float* p3 = g_slotout + (size_t)s3 * Hn;
    float* o = out + (size_t)t * Hn;
    for (int i = threadIdx.x * 4; i < Hn; i += 256 * 4) {
        float4 a = *(const float4*)(p0 + i);
        float4 b = *(const float4*)(p1 + i);
        float4 c = *(const float4*)(p2 + i);
        float4 d = *(const float4*)(p3 + i);
        *(float4*)(o + i) = make_float4(a.x + b.x + c.x + d.x,
                                        a.y + b.y + c.y + d.y,
                                        a.z + b.z + c.z + d.z,
                                        a.w + b.w + c.w + d.w);
    }
}

// ====================== launcher ======================
extern "C" void kernel_launch(void* const* d_in, const int* in_sizes, int n_in,
                              void* d_out, int out_size) {
    const float* x  = (const float*)d_in[0];
    const float* gw = (const float*)d_in[1];
    const float* wg = (const float*)d_in[2];
    const float* wu = (const float*)d_in[3];
    const float* wd = (const float*)d_in[4];
    float* out = (float*)d_out;

    float* logits_out = nullptr;
    if (out_size >= Tn * Hn + Tn * En) logits_out = out + (size_t)Tn * Hn;

    convert_x_kernel<<<(Tn * Hn) / 1024, 256>>>(x);
    router_kernel<<<Tn / 4, 256>>>(x, gw, logits_out);
    scan_scatter_kernel<<<1, 1024>>>();
    gemm1_kernel<<<dim3(Fn / 64, MAXTILE), 128>>>(wg, wu);
    gemm2_kernel<<<dim3(Hn / 128, MAXTILE), 128>>>(wd);
    reduce_kernel<<<Tn, 256>>>(out);
}

// round 13
// speedup vs baseline: 2.4677x; 1.0749x over previous
#include <cuda_runtime.h>
#include <cuda_fp16.h>
#include <math.h>
#include <stdint.h>

#define Tn 4096
#define Hn 2048
#define En 32
#define Fn 768
#define TOPK 4
#define NSLOT (Tn * TOPK)
#define MAXTILE 160

// ====================== asm helpers ======================
__device__ __forceinline__ uint32_t smem_u32(const void* p) {
    uint32_t a;
    asm("{ .reg .u64 t; cvta.to.shared.u64 t, %1; cvt.u32.u64 %0, t; }"
        : "=r"(a) : "l"(p));
    return a;
}

#define LDSM_X4(r0, r1, r2, r3, a) \
    asm volatile("ldmatrix.sync.aligned.m8n8.x4.shared.b16 {%0,%1,%2,%3}, [%4];" \
                 : "=r"(r0), "=r"(r1), "=r"(r2), "=r"(r3) : "r"(a))
#define LDSM_X4_T(r0, r1, r2, r3, a) \
    asm volatile("ldmatrix.sync.aligned.m8n8.x4.trans.shared.b16 {%0,%1,%2,%3}, [%4];" \
                 : "=r"(r0), "=r"(r1), "=r"(r2), "=r"(r3) : "r"(a))

#define MMA_FP16(d, a, b0, b1) \
    asm volatile("mma.sync.aligned.m16n8k16.row.col.f32.f16.f16.f32 " \
                 "{%0,%1,%2,%3}, {%4,%5,%6,%7}, {%8,%9}, {%0,%1,%2,%3};" \
                 : "+f"((d)[0]), "+f"((d)[1]), "+f"((d)[2]), "+f"((d)[3]) \
                 : "r"((a)[0]), "r"((a)[1]), "r"((a)[2]), "r"((a)[3]), \
                   "r"(b0), "r"(b1))

__device__ __forceinline__ uint32_t f22h(float a, float b) {
    __half2 h = __floats2half2_rn(a, b);
    return *(uint32_t*)&h;
}

// ====================== device scratch (~180 MB) ======================
__device__ int   g_counts[En];
__device__ int   g_offsets[En];
__device__ int   g_cursor[En];
__device__ int   g_topk_idx[NSLOT];
__device__ float g_topk_w[NSLOT];
__device__ int   g_tok[NSLOT];
__device__ float g_tokw[NSLOT];
__device__ int   g_tslot[NSLOT];
__device__ int   g_ntiles;
__device__ int   g_tile_e[MAXTILE];
__device__ int   g_tile_m[MAXTILE];

__device__ __align__(256) __half g_xh[(size_t)Tn * Hn];       // 16 MB
__device__ __align__(256) __half g_hdnh[(size_t)NSLOT * Fn];  // 24 MB
__device__ __align__(256) float  g_slotout[(size_t)NSLOT * Hn]; // 134 MB

// ====================== convert + clear counters ======================
__global__ __launch_bounds__(256) void convert_x_kernel(const float* __restrict__ x) {
    if (blockIdx.x == 0 && threadIdx.x < En) {
        g_counts[threadIdx.x] = 0;
        g_cursor[threadIdx.x] = 0;
    }
    size_t i = ((size_t)blockIdx.x * 256 + threadIdx.x) * 4;
    float4 v = *(const float4*)(x + i);
    uint2 u;
    u.x = f22h(v.x, v.y);
    u.y = f22h(v.z, v.w);
    *(uint2*)(g_xh + i) = u;
}

// ====================== router: 4 tokens per block ======================
__global__ __launch_bounds__(256) void router_kernel(
    const float* __restrict__ x, const float* __restrict__ gw,
    float* __restrict__ logits_out)
{
    int tb = blockIdx.x * 4;
    int tid = threadIdx.x;
    int warp = tid >> 5, lane = tid & 31;
    __shared__ float sx[4][Hn];
    __shared__ float slog[4][En];

    for (int i = tid; i < 4 * Hn; i += 256)
        ((float*)sx)[i] = x[(size_t)tb * Hn + i];
    __syncthreads();

    for (int e = warp; e < En; e += 8) {
        const float* w = gw + (size_t)e * Hn;
        float a0 = 0.f, a1 = 0.f, a2 = 0.f, a3 = 0.f;
        for (int k = lane; k < Hn; k += 32) {
            float wv = w[k];
            a0 += sx[0][k] * wv;
            a1 += sx[1][k] * wv;
            a2 += sx[2][k] * wv;
            a3 += sx[3][k] * wv;
        }
        #pragma unroll
        for (int o = 16; o > 0; o >>= 1) {
            a0 += __shfl_xor_sync(~0u, a0, o);
            a1 += __shfl_xor_sync(~0u, a1, o);
            a2 += __shfl_xor_sync(~0u, a2, o);
            a3 += __shfl_xor_sync(~0u, a3, o);
        }
        if (lane == 0) {
            slog[0][e] = a0; slog[1][e] = a1;
            slog[2][e] = a2; slog[3][e] = a3;
        }
    }
    __syncthreads();

    if (warp < 4) {
        int t = tb + warp;
        float l = slog[warp][lane];
        if (logits_out) logits_out[(size_t)t * En + lane] = l;
        float m = l;
        #pragma unroll
        for (int o = 16; o > 0; o >>= 1) m = fmaxf(m, __shfl_xor_sync(~0u, m, o));
        float p = __expf(l - m), s = p;
        #pragma unroll
        for (int o = 16; o > 0; o >>= 1) s += __shfl_xor_sync(~0u, s, o);
        p /= s;
        float myp = p, tw[TOPK]; int ti[TOPK]; float wsum = 0.f;
        #pragma unroll
        for (int j = 0; j < TOPK; j++) {
            float v = myp; int idx = lane;
            #pragma unroll
            for (int o = 16; o > 0; o >>= 1) {
                float ov = __shfl_xor_sync(~0u, v, o);
                int   oi = __shfl_xor_sync(~0u, idx, o);
                if (ov > v || (ov == v && oi < idx)) { v = ov; idx = oi; }
            }
            tw[j] = v; ti[j] = idx; wsum += v;
            if (lane == idx) myp = -1.f;
        }
        if (lane < TOPK) {
            int e = ti[lane];
            g_topk_idx[t * TOPK + lane] = e;
            g_topk_w[t * TOPK + lane] = tw[lane] / wsum;
            atomicAdd(&g_counts[e], 1);
        }
    }
}

// ====================== fused scan + scatter (single block) ==============
__global__ __launch_bounds__(1024) void scan_scatter_kernel() {
    __shared__ int soff[En];
    int tid = threadIdx.x;
    if (tid < 32) {
        int c = g_counts[tid], inc = c;
        #pragma unroll
        for (int o = 1; o < 32; o <<= 1) {
            int nv = __shfl_up_sync(~0u, inc, o);
            if (tid >= o) inc += nv;
        }
        g_offsets[tid] = inc - c;
        soff[tid] = inc - c;
        if (tid == 0) {
            int nt = 0;
            for (int e = 0; e < En; e++) {
                int cc = g_counts[e];
                for (int m0 = 0; m0 < cc; m0 += 128) {
                    g_tile_e[nt] = e;
                    g_tile_m[nt] = m0;
                    nt++;
                }
            }
            g_ntiles = nt;
        }
    }
    __syncthreads();
    for (int i = tid; i < NSLOT; i += 1024) {
        int e = g_topk_idx[i];
        int pos = atomicAdd(&g_cursor[e], 1);
        int slot = soff[e] + pos;
        g_tok[slot]  = i >> 2;
        g_tokw[slot] = g_topk_w[i];
        g_tslot[i]   = slot;
    }
}

// A rows: 16 fp16 (32B) padded to 48B (24 elems); banks r*12 mod 32 distinct
#define A_ROWE 24
#define A_PLANE (128 * A_ROWE)
// gemm1 B rows: 64 fp16 (128B) padded to 144B (72 elems); banks r*36 -> r*4
#define B1_ROWE 72
#define B1_PLANE (16 * B1_ROWE)
// gemm2 B rows: 128 fp16 (256B) padded to 272B (136 elems); banks r*68 -> r*4
#define B2_ROWE 136
#define B2_PLANE (16 * B2_ROWE)

// ====================== GEMM1: CTA 128x64, 4 warps (64x32) ===============
__global__ __launch_bounds__(128, 2) void gemm1_kernel(
    const float* __restrict__ wg, const float* __restrict__ wu)
{
    __shared__ __align__(16) __half sA[2][A_PLANE];
    __shared__ __align__(16) __half sG[2][B1_PLANE], sU[2][B1_PLANE];
    __shared__ int stok[128];

    int ty = blockIdx.y;
    if (ty >= g_ntiles) return;
    int e = g_tile_e[ty];
    int m0 = g_tile_m[ty];
    int cnt = g_counts[e];
    int base = g_offsets[e];
    int n0 = blockIdx.x * 64;
    int tid = threadIdx.x, wid = tid >> 5, lane = tid & 31;

    {
        int idx = base + m0 + tid;
        stok[tid] = g_tok[idx < NSLOT ? idx : NSLOT - 1];
    }
    __syncthreads();

    // ---- A loader: 1 row/thread, 2x16B ----
    const __half* pA = g_xh + (size_t)stok[tid] * Hn;
    uint32_t aE = (uint32_t)(tid * A_ROWE);

    // ---- B loader: row bk, cols bn..bn+7 (8 floats) per matrix ----
    int bk = tid & 15, bn = (tid >> 4) * 8;
    const float* pG = wg + (size_t)e * Hn * Fn + n0 + bn;
    const float* pU = wu + (size_t)e * Hn * Fn + n0 + bn;
    uint32_t bI = (uint32_t)(bk * B1_ROWE + bn);

    // ---- compute maps: 4 warps = 2M x 2N, warp tile 64x32 ----
    int wm = wid & 1, wn = wid >> 1;
    uint32_t sA_b = smem_u32(sA), sG_b = smem_u32(sG), sU_b = smem_u32(sU);
    uint32_t aoff[4];
    {
        int r = wm * 64 + (lane & 15);
        uint32_t c = (uint32_t)(lane >> 4) * 16;
        #pragma unroll
        for (int mt = 0; mt < 4; mt++) aoff[mt] = (uint32_t)(r + mt * 16) * 48 + c;
    }
    uint32_t boff0 = (uint32_t)(lane & 15) * 144 + (uint32_t)(lane >> 4) * 16 +
                     (uint32_t)wn * 64;
    uint32_t boff1 = boff0 + 32;

    float accG[4][4][4] = {}, accU[4][4][4] = {};

    // ---- prologue: buffer 0 ----
    {
        uint4 a0 = *(const uint4*)pA;
        uint4 a1 = *(const uint4*)(pA + 8);
        float4 g0 = *(const float4*)(pG + (size_t)bk * Fn);
        float4 g1 = *(const float4*)(pG + (size_t)bk * Fn + 4);
        float4 u0 = *(const float4*)(pU + (size_t)bk * Fn);
        float4 u1 = *(const float4*)(pU + (size_t)bk * Fn + 4);
        *(uint4*)(sA[0] + aE) = a0;
        *(uint4*)(sA[0] + aE + 8) = a1;
        *(uint4*)(sG[0] + bI) = make_uint4(f22h(g0.x, g0.y), f22h(g0.z, g0.w),
                                           f22h(g1.x, g1.y), f22h(g1.z, g1.w));
        *(uint4*)(sU[0] + bI) = make_uint4(f22h(u0.x, u0.y), f22h(u0.z, u0.w),
                                           f22h(u1.x, u1.y), f22h(u1.z, u1.w));
    }
    __syncthreads();

    const int nch = Hn / 16;  // 128
    for (int c = 0; c < nch; c++) {
        int s = c & 1, sn = s ^ 1;
        bool more = (c + 1 < nch);
        uint4 na0, na1;
        float4 g0, g1, u0, u1;
        if (more) {
            int k0n = (c + 1) * 16;
            na0 = *(const uint4*)(pA + k0n);
            na1 = *(const uint4*)(pA + k0n + 8);
            size_t ko = (size_t)(k0n + bk) * Fn;
            g0 = *(const float4*)(pG + ko);
            g1 = *(const float4*)(pG + ko + 4);
            u0 = *(const float4*)(pU + ko);
            u1 = *(const float4*)(pU + ko + 4);
        }

        uint32_t sAo = (uint32_t)s * (A_PLANE * 2);
        uint32_t sBo = (uint32_t)s * (B1_PLANE * 2);
        uint32_t bg[2][4], bu[2][4];
        LDSM_X4_T(bg[0][0], bg[0][1], bg[0][2], bg[0][3], sG_b + sBo + boff0);
        LDSM_X4_T(bg[1][0], bg[1][1], bg[1][2], bg[1][3], sG_b + sBo + boff1);
        LDSM_X4_T(bu[0][0], bu[0][1], bu[0][2], bu[0][3], sU_b + sBo + boff0);
        LDSM_X4_T(bu[1][0], bu[1][1], bu[1][2], bu[1][3], sU_b + sBo + boff1);
        #pragma unroll
        for (int mt = 0; mt < 4; mt++) {
            uint32_t ah[4];
            LDSM_X4(ah[0], ah[1], ah[2], ah[3], sA_b + sAo + aoff[mt]);
            #pragma unroll
            for (int nt = 0; nt < 4; nt++) {
                uint32_t* G = &bg[nt >> 1][(nt & 1) * 2];
                uint32_t* U = &bu[nt >> 1][(nt & 1) * 2];
                MMA_FP16(accG[mt][nt], ah, G[0], G[1]);
                MMA_FP16(accU[mt][nt], ah, U[0], U[1]);
            }
        }

        if (more) {
            *(uint4*)(sA[sn] + aE) = na0;
            *(uint4*)(sA[sn] + aE + 8) = na1;
            *(uint4*)(sG[sn] + bI) = make_uint4(f22h(g0.x, g0.y), f22h(g0.z, g0.w),
                                                f22h(g1.x, g1.y), f22h(g1.z, g1.w));
            *(uint4*)(sU[sn] + bI) = make_uint4(f22h(u0.x, u0.y), f22h(u0.z, u0.w),
                                                f22h(u1.x, u1.y), f22h(u1.z, u1.w));
        }
        __syncthreads();
    }

    // ---- epilogue: h = w * silu(g) * u -> hdn fp16 ----
    int r = lane >> 2, cp2 = (lane & 3) * 2;
    #pragma unroll
    for (int mt = 0; mt < 4; mt++) {
        #pragma unroll
        for (int half = 0; half < 2; half++) {
            int grow = m0 + wm * 64 + mt * 16 + r + half * 8;
            if (grow >= cnt) continue;
            int slot = base + grow;
            float wgt = g_tokw[slot];
            size_t ob = (size_t)slot * Fn + n0 + wn * 32 + cp2;
            #pragma unroll
            for (int nt = 0; nt < 4; nt++) {
                float g0 = accG[mt][nt][half * 2 + 0];
                float g1 = accG[mt][nt][half * 2 + 1];
                float u0 = accU[mt][nt][half * 2 + 0];
                float u1 = accU[mt][nt][half * 2 + 1];
                float h0 = wgt * (g0 / (1.f + __expf(-g0))) * u0;
                float h1 = wgt * (g1 / (1.f + __expf(-g1))) * u1;
                *(uint32_t*)(g_hdnh + ob + nt * 8) = f22h(h0, h1);
            }
        }
    }
}

// ====================== GEMM2: CTA 128x128, 4 warps (64x64) ==============
__global__ __launch_bounds__(128, 2) void gemm2_kernel(const float* __restrict__ wd) {
    __shared__ __align__(16) __half sA[2][A_PLANE];
    __shared__ __align__(16) __half sB[2][B2_PLANE];

    int ty = blockIdx.y;
    if (ty >= g_ntiles) return;
    int e = g_tile_e[ty];
    int m0 = g_tile_m[ty];
    int cnt = g_counts[e];
    int base = g_offsets[e];
    int n0 = blockIdx.x * 128;
    int tid = threadIdx.x, wid = tid >> 5, lane = tid & 31;

    // ---- A loader: 1 row/thread ----
    int sl = base + m0 + tid; if (sl >= NSLOT) sl = NSLOT - 1;
    const __half* pA = g_hdnh + (size_t)sl * Fn;
    uint32_t aE = (uint32_t)(tid * A_ROWE);

    // ---- B loader: row bk, cols bn..bn+15 (16 floats) ----
    int bk = tid & 15, bn = (tid >> 4) * 16;
    const float* pB = wd + (size_t)e * Fn * Hn + n0 + bn;
    uint32_t bI = (uint32_t)(bk * B2_ROWE + bn);

    int wm = wid & 1, wn = wid >> 1;
    uint32_t sA_b = smem_u32(sA), sB_b = smem_u32(sB);
    uint32_t aoff[4];
    {
        int r = wm * 64 + (lane & 15);
        uint32_t c = (uint32_t)(lane >> 4) * 16;
        #pragma unroll
        for (int mt = 0; mt < 4; mt++) aoff[mt] = (uint32_t)(r + mt * 16) * 48 + c;
    }
    uint32_t boff[4];
    {
        uint32_t rb = (uint32_t)(lane & 15) * 272 + (uint32_t)(lane >> 4) * 16;
        #pragma unroll
        for (int p = 0; p < 4; p++) boff[p] = rb + (uint32_t)wn * 128 + p * 32;
    }

    float acc[4][8][4] = {};

    // ---- prologue ----
    {
        uint4 a0 = *(const uint4*)pA;
        uint4 a1 = *(const uint4*)(pA + 8);
        size_t ko = (size_t)bk * Hn;
        float4 b0 = *(const float4*)(pB + ko);
        float4 b1 = *(const float4*)(pB + ko + 4);
        float4 b2 = *(const float4*)(pB + ko + 8);
        float4 b3 = *(const float4*)(pB + ko + 12);
        *(uint4*)(sA[0] + aE) = a0;
        *(uint4*)(sA[0] + aE + 8) = a1;
        *(uint4*)(sB[0] + bI) = make_uint4(f22h(b0.x, b0.y), f22h(b0.z, b0.w),
                                           f22h(b1.x, b1.y), f22h(b1.z, b1.w));
        *(uint4*)(sB[0] + bI + 8) = make_uint4(f22h(b2.x, b2.y), f22h(b2.z, b2.w),
                                               f22h(b3.x, b3.y), f22h(b3.z, b3.w));
    }
    __syncthreads();

    const int nch = Fn / 16;  // 48
    for (int c = 0; c < nch; c++) {
        int s = c & 1, sn = s ^ 1;
        bool more = (c + 1 < nch);
        uint4 na0, na1;
        float4 b0, b1, b2, b3;
        if (more) {
            int k0n = (c + 1) * 16;
            na0 = *(const uint4*)(pA + k0n);
            na1 = *(const uint4*)(pA + k0n + 8);
            size_t ko = (size_t)(k0n + bk) * Hn;
            b0 = *(const float4*)(pB + ko);
            b1 = *(const float4*)(pB + ko + 4);
            b2 = *(const float4*)(pB + ko + 8);
            b3 = *(const float4*)(pB + ko + 12);
        }

        uint32_t sAo = (uint32_t)s * (A_PLANE * 2);
        uint32_t sBo = (uint32_t)s * (B2_PLANE * 2);
        uint32_t bh[4][4];
        #pragma unroll
        for (int p = 0; p < 4; p++)
            LDSM_X4_T(bh[p][0], bh[p][1], bh[p][2], bh[p][3], sB_b + sBo + boff[p]);
        #pragma unroll
        for (int mt = 0; mt < 4; mt++) {
            uint32_t ah[4];
            LDSM_X4(ah[0], ah[1], ah[2], ah[3], sA_b + sAo + aoff[mt]);
            #pragma unroll
            for (int nt = 0; nt < 8; nt++) {
                uint32_t* B = &bh[nt >> 1][(nt & 1) * 2];
                MMA_FP16(acc[mt][nt], ah, B[0], B[1]);
            }
        }

        if (more) {
            *(uint4*)(sA[sn] + aE) = na0;
            *(uint4*)(sA[sn] + aE + 8) = na1;
            *(uint4*)(sB[sn] + bI) = make_uint4(f22h(b0.x, b0.y), f22h(b0.z, b0.w),
                                                f22h(b1.x, b1.y), f22h(b1.z, b1.w));
            *(uint4*)(sB[sn] + bI + 8) = make_uint4(f22h(b2.x, b2.y), f22h(b2.z, b2.w),
                                                    f22h(b3.x, b3.y), f22h(b3.z, b3.w));
        }
        __syncthreads();
    }

    // ---- epilogue: stream fp32 to slot buffer ----
    int r = lane >> 2, cp2 = (lane & 3) * 2;
    #pragma unroll
    for (int mt = 0; mt < 4; mt++) {
        #pragma unroll
        for (int half = 0; half < 2; half++) {
            int grow = m0 + wm * 64 + mt * 16 + r + half * 8;
            if (grow >= cnt) continue;
            size_t ob = (size_t)(base + grow) * Hn + n0 + wn * 64 + cp2;
            #pragma unroll
            for (int nt = 0; nt < 8; nt++) {
                float v0 = acc[mt][nt][half * 2 + 0];
                float v1 = acc[mt][nt][half * 2 + 1];
                *(float2*)(g_slotout + ob + nt * 8) = make_float2(v0, v1);
            }
        }
    }
}

// ====================== reduce: sum 4 slots per token ======================
__global__ __launch_bounds__(256) void reduce_kernel(float* __restrict__ out) {
    int t = blockIdx.x;
    int s0 = g_tslot[t * 4 + 0], s1 = g_tslot[t * 4 + 1];
    int s2 = g_tslot[t * 4 + 2], s3 = g_tslot[t * 4 + 3];
    const float* p0 = g_slotout + (size_t)s0 * Hn;
    const float* p1 = g_slotout + (size_t)s1 * Hn;
    const float* p2 = g_slotout + (size_t)s2 * Hn;
    const float* p3 = g_slotout + (size_t)s3 * Hn;
    float* o = out + (size_t)t * Hn;
    for (int i = threadIdx.x * 4; i < Hn; i += 256 * 4) {
        float4 a = *(const float4*)(p0 + i);
        float4 b = *(const float4*)(p1 + i);
        float4 c = *(const float4*)(p2 + i);
        float4 d = *(const float4*)(p3 + i);
        *(float4*)(o + i) = make_float4(a.x + b.x + c.x + d.x,
                                        a.y + b.y + c.y + d.y,
                                        a.z + b.z + c.z + d.z,
                                        a.w + b.w + c.w + d.w);
    }
}

// ====================== launcher ======================
extern "C" void kernel_launch(void* const* d_in, const int* in_sizes, int n_in,
                              void* d_out, int out_size) {
    const float* x  = (const float*)d_in[0];
    const float* gw = (const float*)d_in[1];
    const float* wg = (const float*)d_in[2];
    const float* wu = (const float*)d_in[3];
    const float* wd = (const float*)d_in[4];
    float* out = (float*)d_out;

    float* logits_out = nullptr;
    if (out_size >= Tn * Hn + Tn * En) logits_out = out + (size_t)Tn * Hn;

    convert_x_kernel<<<(Tn * Hn) / 1024, 256>>>(x);
    router_kernel<<<Tn / 4, 256>>>(x, gw, logits_out);
    scan_scatter_kernel<<<1, 1024>>>();
    gemm1_kernel<<<dim3(Fn / 64, MAXTILE), 128>>>(wg, wu);
    gemm2_kernel<<<dim3(Hn / 128, MAXTILE), 128>>>(wd);
    reduce_kernel<<<Tn, 256>>>(out);
}

// round 14
// speedup vs baseline: 3.2538x; 1.3186x over previous
#include <cuda_runtime.h>
#include <cuda_fp16.h>
#include <math.h>
#include <stdint.h>

#define Tn 4096
#define Hn 2048
#define En 32
#define Fn 768
#define TOPK 4
#define NSLOT (Tn * TOPK)
#define MAXTILE 160

// ====================== asm helpers ======================
__device__ __forceinline__ uint32_t smem_u32(const void* p) {
    uint32_t a;
    asm("{ .reg .u64 t; cvta.to.shared.u64 t, %1; cvt.u32.u64 %0, t; }"
        : "=r"(a) : "l"(p));
    return a;
}

#define LDSM_X4(r0, r1, r2, r3, a) \
    asm volatile("ldmatrix.sync.aligned.m8n8.x4.shared.b16 {%0,%1,%2,%3}, [%4];" \
                 : "=r"(r0), "=r"(r1), "=r"(r2), "=r"(r3) : "r"(a))
#define LDSM_X4_T(r0, r1, r2, r3, a) \
    asm volatile("ldmatrix.sync.aligned.m8n8.x4.trans.shared.b16 {%0,%1,%2,%3}, [%4];" \
                 : "=r"(r0), "=r"(r1), "=r"(r2), "=r"(r3) : "r"(a))

#define MMA_FP16(d, a, b0, b1) \
    asm volatile("mma.sync.aligned.m16n8k16.row.col.f32.f16.f16.f32 " \
                 "{%0,%1,%2,%3}, {%4,%5,%6,%7}, {%8,%9}, {%0,%1,%2,%3};" \
                 : "+f"((d)[0]), "+f"((d)[1]), "+f"((d)[2]), "+f"((d)[3]) \
                 : "r"((a)[0]), "r"((a)[1]), "r"((a)[2]), "r"((a)[3]), \
                   "r"(b0), "r"(b1))

__device__ __forceinline__ uint32_t f22h(float a, float b) {
    __half2 h = __floats2half2_rn(a, b);
    return *(uint32_t*)&h;
}

// ====================== device scratch (~180 MB) ======================
__device__ int   g_counts[En];
__device__ int   g_offsets[En];
__device__ int   g_cursor[En];
__device__ int   g_topk_idx[NSLOT];
__device__ float g_topk_w[NSLOT];
__device__ int   g_tok[NSLOT];
__device__ float g_tokw[NSLOT];
__device__ int   g_tslot[NSLOT];
__device__ int   g_ntiles;
__device__ int   g_tile_e[MAXTILE];
__device__ int   g_tile_m[MAXTILE];

__device__ __align__(256) __half g_xh[(size_t)Tn * Hn];
__device__ __align__(256) __half g_hdnh[(size_t)NSLOT * Fn];
__device__ __align__(256) float  g_slotout[(size_t)NSLOT * Hn];

// ====================== convert + clear counters ======================
__global__ __launch_bounds__(256) void convert_x_kernel(const float* __restrict__ x) {
    if (blockIdx.x == 0 && threadIdx.x < En) {
        g_counts[threadIdx.x] = 0;
        g_cursor[threadIdx.x] = 0;
    }
    size_t i = ((size_t)blockIdx.x * 256 + threadIdx.x) * 4;
    float4 v = *(const float4*)(x + i);
    uint2 u;
    u.x = f22h(v.x, v.y);
    u.y = f22h(v.z, v.w);
    *(uint2*)(g_xh + i) = u;
}

// ====================== router: 4 tokens per block ======================
__global__ __launch_bounds__(256) void router_kernel(
    const float* __restrict__ x, const float* __restrict__ gw,
    float* __restrict__ logits_out)
{
    int tb = blockIdx.x * 4;
    int tid = threadIdx.x;
    int warp = tid >> 5, lane = tid & 31;
    __shared__ float sx[4][Hn];
    __shared__ float slog[4][En];

    for (int i = tid; i < 4 * Hn; i += 256)
        ((float*)sx)[i] = x[(size_t)tb * Hn + i];
    __syncthreads();

    for (int e = warp; e < En; e += 8) {
        const float* w = gw + (size_t)e * Hn;
        float a0 = 0.f, a1 = 0.f, a2 = 0.f, a3 = 0.f;
        for (int k = lane; k < Hn; k += 32) {
            float wv = w[k];
            a0 += sx[0][k] * wv;
            a1 += sx[1][k] * wv;
            a2 += sx[2][k] * wv;
            a3 += sx[3][k] * wv;
        }
        #pragma unroll
        for (int o = 16; o > 0; o >>= 1) {
            a0 += __shfl_xor_sync(~0u, a0, o);
            a1 += __shfl_xor_sync(~0u, a1, o);
            a2 += __shfl_xor_sync(~0u, a2, o);
            a3 += __shfl_xor_sync(~0u, a3, o);
        }
        if (lane == 0) {
            slog[0][e] = a0; slog[1][e] = a1;
            slog[2][e] = a2; slog[3][e] = a3;
        }
    }
    __syncthreads();

    if (warp < 4) {
        int t = tb + warp;
        float l = slog[warp][lane];
        if (logits_out) logits_out[(size_t)t * En + lane] = l;
        float m = l;
        #pragma unroll
        for (int o = 16; o > 0; o >>= 1) m = fmaxf(m, __shfl_xor_sync(~0u, m, o));
        float p = __expf(l - m), s = p;
        #pragma unroll
        for (int o = 16; o > 0; o >>= 1) s += __shfl_xor_sync(~0u, s, o);
        p /= s;
        float myp = p, tw[TOPK]; int ti[TOPK]; float wsum = 0.f;
        #pragma unroll
        for (int j = 0; j < TOPK; j++) {
            float v = myp; int idx = lane;
            #pragma unroll
            for (int o = 16; o > 0; o >>= 1) {
                float ov = __shfl_xor_sync(~0u, v, o);
                int   oi = __shfl_xor_sync(~0u, idx, o);
                if (ov > v || (ov == v && oi < idx)) { v = ov; idx = oi; }
            }
            tw[j] = v; ti[j] = idx; wsum += v;
            if (lane == idx) myp = -1.f;
        }
        if (lane < TOPK) {
            int e = ti[lane];
            g_topk_idx[t * TOPK + lane] = e;
            g_topk_w[t * TOPK + lane] = tw[lane] / wsum;
            atomicAdd(&g_counts[e], 1);
        }
    }
}

// ====================== fused scan + scatter (single block) ==============
__global__ __launch_bounds__(1024) void scan_scatter_kernel() {
    __shared__ int soff[En];
    int tid = threadIdx.x;
    if (tid < 32) {
        int c = g_counts[tid], inc = c;
        #pragma unroll
        for (int o = 1; o < 32; o <<= 1) {
            int nv = __shfl_up_sync(~0u, inc, o);
            if (tid >= o) inc += nv;
        }
        g_offsets[tid] = inc - c;
        soff[tid] = inc - c;
        if (tid == 0) {
            int nt = 0;
            for (int e = 0; e < En; e++) {
                int cc = g_counts[e];
                for (int m0 = 0; m0 < cc; m0 += 128) {
                    g_tile_e[nt] = e;
                    g_tile_m[nt] = m0;
                    nt++;
                }
            }
            g_ntiles = nt;
        }
    }
    __syncthreads();
    for (int i = tid; i < NSLOT; i += 1024) {
        int e = g_topk_idx[i];
        int pos = atomicAdd(&g_cursor[e], 1);
        int slot = soff[e] + pos;
        g_tok[slot]  = i >> 2;
        g_tokw[slot] = g_topk_w[i];
        g_tslot[i]   = slot;
    }
}

// A big-chunk rows: 64 fp16 (128B) + 16B pad = 144B (72 elems); r*36 mod 32 distinct
#define A_ROWE 72
#define A_PLANE (128 * A_ROWE)      // 18 KB
// gemm1 B rows: 64 fp16 + pad = 144B
#define B1_ROWE 72
#define B1_PLANE (16 * B1_ROWE)     // 2.25 KB
// gemm2 B rows: 128 fp16 + pad = 272B
#define B2_ROWE 136
#define B2_PLANE (16 * B2_ROWE)     // 4.25 KB

// ====================== GEMM1: CTA 128x64, 4 warps (64x32) ===============
__global__ __launch_bounds__(128, 2) void gemm1_kernel(
    const float* __restrict__ wg, const float* __restrict__ wu)
{
    __shared__ __align__(16) __half sA[2][A_PLANE];        // 36 KB
    __shared__ __align__(16) __half sG[2][B1_PLANE], sU[2][B1_PLANE]; // 9 KB
    __shared__ int stok[128];

    int ty = blockIdx.y;
    if (ty >= g_ntiles) return;
    int e = g_tile_e[ty];
    int m0 = g_tile_m[ty];
    int cnt = g_counts[e];
    int base = g_offsets[e];
    int n0 = blockIdx.x * 64;
    int tid = threadIdx.x, wid = tid >> 5, lane = tid & 31;

    {
        int idx = base + m0 + tid;
        stok[tid] = g_tok[idx < NSLOT ? idx : NSLOT - 1];
    }
    __syncthreads();

    // A loader: coalesced, 8 threads/row; thread handles (i*16 + tid>>3, (tid&7)*8)
    int aRow8 = tid >> 3, aC = (tid & 7) * 8;
    // B loader: 2 f4 per matrix; row i*8 + (tid>>4), col (tid&15)*4
    int bRowW = tid >> 4, bC4 = (tid & 15) * 4;
    const float* pG = wg + (size_t)e * Hn * Fn + n0 + bC4;
    const float* pU = wu + (size_t)e * Hn * Fn + n0 + bC4;

    // compute maps: 4 warps = 2M x 2N, warp tile 64x32
    int wm = wid & 1, wn = wid >> 1;
    uint32_t sA_b = smem_u32(sA), sG_b = smem_u32(sG), sU_b = smem_u32(sU);
    uint32_t aoff[4];
    {
        int r = wm * 64 + (lane & 15);
        uint32_t c = (uint32_t)(lane >> 4) * 16;
        #pragma unroll
        for (int mt = 0; mt < 4; mt++) aoff[mt] = (uint32_t)(r + mt * 16) * 144 + c;
    }
    uint32_t boff0 = (uint32_t)(lane & 15) * 144 + (uint32_t)(lane >> 4) * 16 +
                     (uint32_t)wn * 64;
    uint32_t boff1 = boff0 + 32;

    float accG[4][4][4] = {}, accU[4][4][4] = {};

    // ---- prologue: A big-chunk 0 + B chunk 0 ----
    #pragma unroll
    for (int i = 0; i < 8; i++) {
        int row = i * 16 + aRow8;
        uint4 v = *(const uint4*)(g_xh + (size_t)stok[row] * Hn + aC);
        *(uint4*)(sA[0] + row * A_ROWE + aC) = v;
    }
    #pragma unroll
    for (int i = 0; i < 2; i++) {
        int row = i * 8 + bRowW;
        float4 g = *(const float4*)(pG + (size_t)row * Fn);
        float4 u = *(const float4*)(pU + (size_t)row * Fn);
        *(uint2*)(sG[0] + row * B1_ROWE + bC4) = make_uint2(f22h(g.x, g.y), f22h(g.z, g.w));
        *(uint2*)(sU[0] + row * B1_ROWE + bC4) = make_uint2(f22h(u.x, u.y), f22h(u.z, u.w));
    }
    __syncthreads();

    const int nch = Hn / 16;   // 128
    const int nbig = Hn / 64;  // 32
    uint4 aR[8];
    float4 gR[2], uR[2];

    for (int c = 0; c < nch; c++) {
        int bc = c >> 2, sc = c & 3;
        int s = c & 1, sn = s ^ 1;
        int ba = bc & 1, ban = ba ^ 1;
        bool more = (c + 1 < nch);
        bool abig = (sc == 0) && (bc + 1 < nbig);

        if (abig) {
            int kb = (bc + 1) * 64;
            #pragma unroll
            for (int i = 0; i < 8; i++) {
                int row = i * 16 + aRow8;
                aR[i] = *(const uint4*)(g_xh + (size_t)stok[row] * Hn + kb + aC);
            }
        }
        if (more) {
            int k0n = (c + 1) * 16;
            #pragma unroll
            for (int i = 0; i < 2; i++) {
                size_t ro = (size_t)(k0n + i * 8 + bRowW) * Fn;
                gR[i] = *(const float4*)(pG + ro);
                uR[i] = *(const float4*)(pU + ro);
            }
        }

        // ---- MMA on sA[ba] (k-offset sc*32B) and sG/sU[s] ----
        uint32_t sAo = (uint32_t)ba * (A_PLANE * 2) + (uint32_t)sc * 32;
        uint32_t sBo = (uint32_t)s * (B1_PLANE * 2);
        uint32_t bg[2][4], bu[2][4];
        LDSM_X4_T(bg[0][0], bg[0][1], bg[0][2], bg[0][3], sG_b + sBo + boff0);
        LDSM_X4_T(bg[1][0], bg[1][1], bg[1][2], bg[1][3], sG_b + sBo + boff1);
        LDSM_X4_T(bu[0][0], bu[0][1], bu[0][2], bu[0][3], sU_b + sBo + boff0);
        LDSM_X4_T(bu[1][0], bu[1][1], bu[1][2], bu[1][3], sU_b + sBo + boff1);
        #pragma unroll
        for (int mt = 0; mt < 4; mt++) {
            uint32_t ah[4];
            LDSM_X4(ah[0], ah[1], ah[2], ah[3], sA_b + sAo + aoff[mt]);
            #pragma unroll
            for (int nt = 0; nt < 4; nt++) {
                uint32_t* G = &bg[nt >> 1][(nt & 1) * 2];
                uint32_t* U = &bu[nt >> 1][(nt & 1) * 2];
                MMA_FP16(accG[mt][nt], ah, G[0], G[1]);
                MMA_FP16(accU[mt][nt], ah, U[0], U[1]);
            }
        }

        if (more) {
            #pragma unroll
            for (int i = 0; i < 2; i++) {
                int row = i * 8 + bRowW;
                *(uint2*)(sG[sn] + row * B1_ROWE + bC4) =
                    make_uint2(f22h(gR[i].x, gR[i].y), f22h(gR[i].z, gR[i].w));
                *(uint2*)(sU[sn] + row * B1_ROWE + bC4) =
                    make_uint2(f22h(uR[i].x, uR[i].y), f22h(uR[i].z, uR[i].w));
            }
        }
        if (sc == 3 && bc + 1 < nbig) {
            #pragma unroll
            for (int i = 0; i < 8; i++) {
                int row = i * 16 + aRow8;
                *(uint4*)(sA[ban] + row * A_ROWE + aC) = aR[i];
            }
        }
        __syncthreads();
    }

    // ---- epilogue: h = w * silu(g) * u -> hdn fp16 ----
    int r = lane >> 2, cp2 = (lane & 3) * 2;
    #pragma unroll
    for (int mt = 0; mt < 4; mt++) {
        #pragma unroll
        for (int half = 0; half < 2; half++) {
            int grow = m0 + wm * 64 + mt * 16 + r + half * 8;
            if (grow >= cnt) continue;
            int slot = base + grow;
            float wgt = g_tokw[slot];
            size_t ob = (size_t)slot * Fn + n0 + wn * 32 + cp2;
            #pragma unroll
            for (int nt = 0; nt < 4; nt++) {
                float g0 = accG[mt][nt][half * 2 + 0];
                float g1 = accG[mt][nt][half * 2 + 1];
                float u0 = accU[mt][nt][half * 2 + 0];
                float u1 = accU[mt][nt][half * 2 + 1];
                float h0 = wgt * (g0 / (1.f + __expf(-g0))) * u0;
                float h1 = wgt * (g1 / (1.f + __expf(-g1))) * u1;
                *(uint32_t*)(g_hdnh + ob + nt * 8) = f22h(h0, h1);
            }
        }
    }
}

// ====================== GEMM2: CTA 128x128, 4 warps (64x64) ==============
__global__ __launch_bounds__(128, 2) void gemm2_kernel(const float* __restrict__ wd) {
    __shared__ __align__(16) __half sA[2][A_PLANE];   // 36 KB
    __shared__ __align__(16) __half sB[2][B2_PLANE];  // 8.5 KB

    int ty = blockIdx.y;
    if (ty >= g_ntiles) return;
    int e = g_tile_e[ty];
    int m0 = g_tile_m[ty];
    int cnt = g_counts[e];
    int base = g_offsets[e];
    int n0 = blockIdx.x * 128;
    int tid = threadIdx.x, wid = tid >> 5, lane = tid & 31;

    // A rows are contiguous slots
    int aRow8 = tid >> 3, aC = (tid & 7) * 8;
    // B: 4 f4 per thread; row i*4 + (tid>>5), col (tid&31)*4
    int bRowW = tid >> 5, bC4 = (tid & 31) * 4;
    const float* pB = wd + (size_t)e * Fn * Hn + n0 + bC4;

    int wm = wid & 1, wn = wid >> 1;
    uint32_t sA_b = smem_u32(sA), sB_b = smem_u32(sB);
    uint32_t aoff[4];
    {
        int r = wm * 64 + (lane & 15);
        uint32_t c = (uint32_t)(lane >> 4) * 16;
        #pragma unroll
        for (int mt = 0; mt < 4; mt++) aoff[mt] = (uint32_t)(r + mt * 16) * 144 + c;
    }
    uint32_t boff[4];
    {
        uint32_t rb = (uint32_t)(lane & 15) * 272 + (uint32_t)(lane >> 4) * 16;
        #pragma unroll
        for (int p = 0; p < 4; p++) boff[p] = rb + (uint32_t)wn * 128 + p * 32;
    }

    float acc[4][8][4] = {};

    // ---- prologue ----
    #pragma unroll
    for (int i = 0; i < 8; i++) {
        int row = i * 16 + aRow8;
        int sl = base + m0 + row; if (sl >= NSLOT) sl = NSLOT - 1;
        uint4 v = *(const uint4*)(g_hdnh + (size_t)sl * Fn + aC);
        *(uint4*)(sA[0] + row * A_ROWE + aC) = v;
    }
    #pragma unroll
    for (int i = 0; i < 4; i++) {
        int row = i * 4 + bRowW;
        float4 b = *(const float4*)(pB + (size_t)row * Hn);
        *(uint2*)(sB[0] + row * B2_ROWE + bC4) = make_uint2(f22h(b.x, b.y), f22h(b.z, b.w));
    }
    __syncthreads();

    const int nch = Fn / 16;   // 48
    const int nbig = Fn / 64;  // 12
    uint4 aR[8];
    float4 bR[4];

    for (int c = 0; c < nch; c++) {
        int bc = c >> 2, sc = c & 3;
        int s = c & 1, sn = s ^ 1;
        int ba = bc & 1, ban = ba ^ 1;
        bool more = (c + 1 < nch);
        bool abig = (sc == 0) && (bc + 1 < nbig);

        if (abig) {
            int kb = (bc + 1) * 64;
            #pragma unroll
            for (int i = 0; i < 8; i++) {
                int row = i * 16 + aRow8;
                int sl = base + m0 + row; if (sl >= NSLOT) sl = NSLOT - 1;
                aR[i] = *(const uint4*)(g_hdnh + (size_t)sl * Fn + kb + aC);
            }
        }
        if (more) {
            int k0n = (c + 1) * 16;
            #pragma unroll
            for (int i = 0; i < 4; i++)
                bR[i] = *(const float4*)(pB + (size_t)(k0n + i * 4 + bRowW) * Hn);
        }

        uint32_t sAo = (uint32_t)ba * (A_PLANE * 2) + (uint32_t)sc * 32;
        uint32_t sBo = (uint32_t)s * (B2_PLANE * 2);
        uint32_t bh[4][4];
        #pragma unroll
        for (int p = 0; p < 4; p++)
            LDSM_X4_T(bh[p][0], bh[p][1], bh[p][2], bh[p][3], sB_b + sBo + boff[p]);
        #pragma unroll
        for (int mt = 0; mt < 4; mt++) {
            uint32_t ah[4];
            LDSM_X4(ah[0], ah[1], ah[2], ah[3], sA_b + sAo + aoff[mt]);
            #pragma unroll
            for (int nt = 0; nt < 8; nt++) {
                uint32_t* B = &bh[nt >> 1][(nt & 1) * 2];
                MMA_FP16(acc[mt][nt], ah, B[0], B[1]);
            }
        }

        if (more) {
            #pragma unroll
            for (int i = 0; i < 4; i++) {
                int row = i * 4 + bRowW;
                *(uint2*)(sB[sn] + row * B2_ROWE + bC4) =
                    make_uint2(f22h(bR[i].x, bR[i].y), f22h(bR[i].z, bR[i].w));
            }
        }
        if (sc == 3 && bc + 1 < nbig) {
            #pragma unroll
            for (int i = 0; i < 8; i++) {
                int row = i * 16 + aRow8;
                *(uint4*)(sA[ban] + row * A_ROWE + aC) = aR[i];
            }
        }
        __syncthreads();
    }

    // ---- epilogue: stream fp32 to slot buffer ----
    int r = lane >> 2, cp2 = (lane & 3) * 2;
    #pragma unroll
    for (int mt = 0; mt < 4; mt++) {
        #pragma unroll
        for (int half = 0; half < 2; half++) {
            int grow = m0 + wm * 64 + mt * 16 + r + half * 8;
            if (grow >= cnt) continue;
            size_t ob = (size_t)(base + grow) * Hn + n0 + wn * 64 + cp2;
            #pragma unroll
            for (int nt = 0; nt < 8; nt++) {
                float v0 = acc[mt][nt][half * 2 + 0];
                float v1 = acc[mt][nt][half * 2 + 1];
                *(float2*)(g_slotout + ob + nt * 8) = make_float2(v0, v1);
            }
        }
    }
}

// ====================== reduce: sum 4 slots per token ======================
__global__ __launch_bounds__(256) void reduce_kernel(float* __restrict__ out) {
    int t = blockIdx.x;
    int s0 = g_tslot[t * 4 + 0], s1 = g_tslot[t * 4 + 1];
    int s2 = g_tslot[t * 4 + 2], s3 = g_tslot[t * 4 + 3];
    const float* p0 = g_slotout + (size_t)s0 * Hn;
    const float* p1 = g_slotout + (size_t)s1 * Hn;
    const float* p2 = g_slotout + (size_t)s2 * Hn;
    const float* p3 = g_slotout + (size_t)s3 * Hn;
    float* o = out + (size_t)t * Hn;
    for (int i = threadIdx.x * 4; i < Hn; i += 256 * 4) {
        float4 a = *(const float4*)(p0 + i);
        float4 b = *(const float4*)(p1 + i);
        float4 c = *(const float4*)(p2 + i);
        float4 d = *(const float4*)(p3 + i);
        *(float4*)(o + i) = make_float4(a.x + b.x + c.x + d.x,
                                        a.y + b.y + c.y + d.y,
                                        a.z + b.z + c.z + d.z,
                                        a.w + b.w + c.w + d.w);
    }
}

// ====================== launcher ======================
extern "C" void kernel_launch(void* const* d_in, const int* in_sizes, int n_in,
                              void* d_out, int out_size) {
    const float* x  = (const float*)d_in[0];
    const float* gw = (const float*)d_in[1];
    const float* wg = (const float*)d_in[2];
    const float* wu = (const float*)d_in[3];
    const float* wd = (const float*)d_in[4];
    float* out = (float*)d_out;

    float* logits_out = nullptr;
    if (out_size >= Tn * Hn + Tn * En) logits_out = out + (size_t)Tn * Hn;

    convert_x_kernel<<<(Tn * Hn) / 1024, 256>>>(x);
    router_kernel<<<Tn / 4, 256>>>(x, gw, logits_out);
    scan_scatter_kernel<<<1, 1024>>>();
    gemm1_kernel<<<dim3(Fn / 64, MAXTILE), 128>>>(wg, wu);
    gemm2_kernel<<<dim3(Hn / 128, MAXTILE), 128>>>(wd);
    reduce_kernel<<<Tn, 256>>>(out);
}

// round 15
// speedup vs baseline: 3.2681x; 1.0044x over previous
#include <cuda_runtime.h>
#include <cuda_fp16.h>
#include <math.h>
#include <stdint.h>

#define Tn 4096
#define Hn 2048
#define En 32
#define Fn 768
#define TOPK 4
#define NSLOT (Tn * TOPK)
#define MAXTILE 160

// ====================== asm helpers ======================
__device__ __forceinline__ uint32_t smem_u32(const void* p) {
    uint32_t a;
    asm("{ .reg .u64 t; cvta.to.shared.u64 t, %1; cvt.u32.u64 %0, t; }"
        : "=r"(a) : "l"(p));
    return a;
}

#define LDSM_X4(r0, r1, r2, r3, a) \
    asm volatile("ldmatrix.sync.aligned.m8n8.x4.shared.b16 {%0,%1,%2,%3}, [%4];" \
                 : "=r"(r0), "=r"(r1), "=r"(r2), "=r"(r3) : "r"(a))
#define LDSM_X4_T(r0, r1, r2, r3, a) \
    asm volatile("ldmatrix.sync.aligned.m8n8.x4.trans.shared.b16 {%0,%1,%2,%3}, [%4];" \
                 : "=r"(r0), "=r"(r1), "=r"(r2), "=r"(r3) : "r"(a))

#define MMA_FP16(d, a, b0, b1) \
    asm volatile("mma.sync.aligned.m16n8k16.row.col.f32.f16.f16.f32 " \
                 "{%0,%1,%2,%3}, {%4,%5,%6,%7}, {%8,%9}, {%0,%1,%2,%3};" \
                 : "+f"((d)[0]), "+f"((d)[1]), "+f"((d)[2]), "+f"((d)[3]) \
                 : "r"((a)[0]), "r"((a)[1]), "r"((a)[2]), "r"((a)[3]), \
                   "r"(b0), "r"(b1))

__device__ __forceinline__ uint32_t f22h(float a, float b) {
    __half2 h = __floats2half2_rn(a, b);
    return *(uint32_t*)&h;
}

// ====================== device scratch (~180 MB) ======================
__device__ int   g_counts[En];
__device__ int   g_offsets[En];
__device__ int   g_cursor[En];
__device__ int   g_topk_idx[NSLOT];
__device__ float g_topk_w[NSLOT];
__device__ int   g_tok[NSLOT];
__device__ float g_tokw[NSLOT];
__device__ int   g_tslot[NSLOT];
__device__ int   g_ntiles;
__device__ int   g_tile_e[MAXTILE];
__device__ int   g_tile_m[MAXTILE];

__device__ __align__(256) __half g_xh[(size_t)Tn * Hn];
__device__ __align__(256) __half g_hdnh[(size_t)NSLOT * Fn];
__device__ __align__(256) float  g_slotout[(size_t)NSLOT * Hn];

// ====================== convert + clear counters ======================
__global__ __launch_bounds__(256) void convert_x_kernel(const float* __restrict__ x) {
    if (blockIdx.x == 0 && threadIdx.x < En) {
        g_counts[threadIdx.x] = 0;
        g_cursor[threadIdx.x] = 0;
    }
    size_t i = ((size_t)blockIdx.x * 256 + threadIdx.x) * 4;
    float4 v = *(const float4*)(x + i);
    uint2 u;
    u.x = f22h(v.x, v.y);
    u.y = f22h(v.z, v.w);
    *(uint2*)(g_xh + i) = u;
}

// ====================== router: 4 tokens per block ======================
__global__ __launch_bounds__(256) void router_kernel(
    const float* __restrict__ x, const float* __restrict__ gw,
    float* __restrict__ logits_out)
{
    int tb = blockIdx.x * 4;
    int tid = threadIdx.x;
    int warp = tid >> 5, lane = tid & 31;
    __shared__ float sx[4][Hn];
    __shared__ float slog[4][En];

    for (int i = tid; i < 4 * Hn; i += 256)
        ((float*)sx)[i] = x[(size_t)tb * Hn + i];
    __syncthreads();

    for (int e = warp; e < En; e += 8) {
        const float* w = gw + (size_t)e * Hn;
        float a0 = 0.f, a1 = 0.f, a2 = 0.f, a3 = 0.f;
        for (int k = lane; k < Hn; k += 32) {
            float wv = w[k];
            a0 += sx[0][k] * wv;
            a1 += sx[1][k] * wv;
            a2 += sx[2][k] * wv;
            a3 += sx[3][k] * wv;
        }
        #pragma unroll
        for (int o = 16; o > 0; o >>= 1) {
            a0 += __shfl_xor_sync(~0u, a0, o);
            a1 += __shfl_xor_sync(~0u, a1, o);
            a2 += __shfl_xor_sync(~0u, a2, o);
            a3 += __shfl_xor_sync(~0u, a3, o);
        }
        if (lane == 0) {
            slog[0][e] = a0; slog[1][e] = a1;
            slog[2][e] = a2; slog[3][e] = a3;
        }
    }
    __syncthreads();

    if (warp < 4) {
        int t = tb + warp;
        float l = slog[warp][lane];
        if (logits_out) logits_out[(size_t)t * En + lane] = l;
        float m = l;
        #pragma unroll
        for (int o = 16; o > 0; o >>= 1) m = fmaxf(m, __shfl_xor_sync(~0u, m, o));
        float p = __expf(l - m), s = p;
        #pragma unroll
        for (int o = 16; o > 0; o >>= 1) s += __shfl_xor_sync(~0u, s, o);
        p /= s;
        float myp = p, tw[TOPK]; int ti[TOPK]; float wsum = 0.f;
        #pragma unroll
        for (int j = 0; j < TOPK; j++) {
            float v = myp; int idx = lane;
            #pragma unroll
            for (int o = 16; o > 0; o >>= 1) {
                float ov = __shfl_xor_sync(~0u, v, o);
                int   oi = __shfl_xor_sync(~0u, idx, o);
                if (ov > v || (ov == v && oi < idx)) { v = ov; idx = oi; }
            }
            tw[j] = v; ti[j] = idx; wsum += v;
            if (lane == idx) myp = -1.f;
        }
        if (lane < TOPK) {
            int e = ti[lane];
            g_topk_idx[t * TOPK + lane] = e;
            g_topk_w[t * TOPK + lane] = tw[lane] / wsum;
            atomicAdd(&g_counts[e], 1);
        }
    }
}

// ====================== fused scan + scatter (single block) ==============
__global__ __launch_bounds__(1024) void scan_scatter_kernel() {
    __shared__ int soff[En];
    int tid = threadIdx.x;
    if (tid < 32) {
        int c = g_counts[tid], inc = c;
        #pragma unroll
        for (int o = 1; o < 32; o <<= 1) {
            int nv = __shfl_up_sync(~0u, inc, o);
            if (tid >= o) inc += nv;
        }
        g_offsets[tid] = inc - c;
        soff[tid] = inc - c;
        if (tid == 0) {
            int nt = 0;
            for (int e = 0; e < En; e++) {
                int cc = g_counts[e];
                for (int m0 = 0; m0 < cc; m0 += 128) {
                    g_tile_e[nt] = e;
                    g_tile_m[nt] = m0;
                    nt++;
                }
            }
            g_ntiles = nt;
        }
    }
    __syncthreads();
    for (int i = tid; i < NSLOT; i += 1024) {
        int e = g_topk_idx[i];
        int pos = atomicAdd(&g_cursor[e], 1);
        int slot = soff[e] + pos;
        g_tok[slot]  = i >> 2;
        g_tokw[slot] = g_topk_w[i];
        g_tslot[i]   = slot;
    }
}

// A big-chunk rows: 64 fp16 (128B) + 16B pad = 144B (72 elems)
#define A_ROWE 72
#define A_PLANE (128 * A_ROWE)      // 18 KB
#define B1_ROWE 72
#define B1_PLANE (16 * B1_ROWE)     // 2.25 KB
#define B2_ROWE 136
#define B2_PLANE (16 * B2_ROWE)     // 4.25 KB

// ====================== GEMM1: CTA 128x64, 8 warps (64x16) ===============
__global__ __launch_bounds__(256, 2) void gemm1_kernel(
    const float* __restrict__ wg, const float* __restrict__ wu)
{
    __shared__ __align__(16) __half sA[2][A_PLANE];                   // 36 KB
    __shared__ __align__(16) __half sG[2][B1_PLANE], sU[2][B1_PLANE]; // 9 KB
    __shared__ int stok[128];

    int ty = blockIdx.y;
    if (ty >= g_ntiles) return;
    int e = g_tile_e[ty];
    int m0 = g_tile_m[ty];
    int cnt = g_counts[e];
    int base = g_offsets[e];
    int n0 = blockIdx.x * 64;
    int tid = threadIdx.x, wid = tid >> 5, lane = tid & 31;

    if (tid < 128) {
        int idx = base + m0 + tid;
        stok[tid] = g_tok[idx < NSLOT ? idx : NSLOT - 1];
    }
    __syncthreads();

    // A loader: 8 thr/row; thread covers rows {i*32 + tid>>3}, col (tid&7)*8
    int aRow8 = tid >> 3, aC = (tid & 7) * 8;
    // B loader: 16 rows x 64 cols fp32 per matrix; 1 float4/thread/matrix
    int bRow = tid >> 4, bC4 = (tid & 15) * 4;
    const float* pG = wg + (size_t)e * Hn * Fn + n0 + bC4;
    const float* pU = wu + (size_t)e * Hn * Fn + n0 + bC4;

    // compute maps: 8 warps = 2M x 4N; warp tile 64x16
    int wm = wid & 1, wn = wid >> 1;
    uint32_t sA_b = smem_u32(sA), sG_b = smem_u32(sG), sU_b = smem_u32(sU);
    uint32_t aoff[4];
    {
        int r = wm * 64 + (lane & 15);
        uint32_t c = (uint32_t)(lane >> 4) * 16;
        #pragma unroll
        for (int mt = 0; mt < 4; mt++) aoff[mt] = (uint32_t)(r + mt * 16) * 144 + c;
    }
    uint32_t boff = (uint32_t)(lane & 15) * 144 + (uint32_t)(lane >> 4) * 16 +
                    (uint32_t)wn * 32;

    float accG[4][2][4] = {}, accU[4][2][4] = {};

    // ---- prologue: A big-chunk 0 + B chunk 0 ----
    #pragma unroll
    for (int i = 0; i < 4; i++) {
        int row = i * 32 + aRow8;
        uint4 v = *(const uint4*)(g_xh + (size_t)stok[row] * Hn + aC);
        *(uint4*)(sA[0] + row * A_ROWE + aC) = v;
    }
    {
        float4 g = *(const float4*)(pG + (size_t)bRow * Fn);
        float4 u = *(const float4*)(pU + (size_t)bRow * Fn);
        *(uint2*)(sG[0] + bRow * B1_ROWE + bC4) = make_uint2(f22h(g.x, g.y), f22h(g.z, g.w));
        *(uint2*)(sU[0] + bRow * B1_ROWE + bC4) = make_uint2(f22h(u.x, u.y), f22h(u.z, u.w));
    }
    __syncthreads();

    const int nch = Hn / 16;   // 128
    const int nbig = Hn / 64;  // 32
    uint4 aR[4];
    float4 gR, uR;

    for (int c = 0; c < nch; c++) {
        int bc = c >> 2, sc = c & 3;
        int s = c & 1, sn = s ^ 1;
        int ba = bc & 1, ban = ba ^ 1;
        bool more = (c + 1 < nch);
        bool abig = (sc == 0) && (bc + 1 < nbig);

        if (abig) {
            int kb = (bc + 1) * 64;
            #pragma unroll
            for (int i = 0; i < 4; i++) {
                int row = i * 32 + aRow8;
                aR[i] = *(const uint4*)(g_xh + (size_t)stok[row] * Hn + kb + aC);
            }
        }
        if (more) {
            size_t ro = (size_t)((c + 1) * 16 + bRow) * Fn;
            gR = *(const float4*)(pG + ro);
            uR = *(const float4*)(pU + ro);
        }

        uint32_t sAo = (uint32_t)ba * (A_PLANE * 2) + (uint32_t)sc * 32;
        uint32_t sBo = (uint32_t)s * (B1_PLANE * 2);
        uint32_t bg[4], bu[4];
        LDSM_X4_T(bg[0], bg[1], bg[2], bg[3], sG_b + sBo + boff);
        LDSM_X4_T(bu[0], bu[1], bu[2], bu[3], sU_b + sBo + boff);
        #pragma unroll
        for (int mt = 0; mt < 4; mt++) {
            uint32_t ah[4];
            LDSM_X4(ah[0], ah[1], ah[2], ah[3], sA_b + sAo + aoff[mt]);
            #pragma unroll
            for (int nt = 0; nt < 2; nt++) {
                MMA_FP16(accG[mt][nt], ah, bg[nt * 2], bg[nt * 2 + 1]);
                MMA_FP16(accU[mt][nt], ah, bu[nt * 2], bu[nt * 2 + 1]);
            }
        }

        if (more) {
            *(uint2*)(sG[sn] + bRow * B1_ROWE + bC4) =
                make_uint2(f22h(gR.x, gR.y), f22h(gR.z, gR.w));
            *(uint2*)(sU[sn] + bRow * B1_ROWE + bC4) =
                make_uint2(f22h(uR.x, uR.y), f22h(uR.z, uR.w));
        }
        if (sc == 3 && bc + 1 < nbig) {
            #pragma unroll
            for (int i = 0; i < 4; i++) {
                int row = i * 32 + aRow8;
                *(uint4*)(sA[ban] + row * A_ROWE + aC) = aR[i];
            }
        }
        __syncthreads();
    }

    // ---- epilogue: h = w * silu(g) * u -> hdn fp16 ----
    int r = lane >> 2, cp2 = (lane & 3) * 2;
    #pragma unroll
    for (int mt = 0; mt < 4; mt++) {
        #pragma unroll
        for (int half = 0; half < 2; half++) {
            int grow = m0 + wm * 64 + mt * 16 + r + half * 8;
            if (grow >= cnt) continue;
            int slot = base + grow;
            float wgt = g_tokw[slot];
            size_t ob = (size_t)slot * Fn + n0 + wn * 16 + cp2;
            #pragma unroll
            for (int nt = 0; nt < 2; nt++) {
                float g0 = accG[mt][nt][half * 2 + 0];
                float g1 = accG[mt][nt][half * 2 + 1];
                float u0 = accU[mt][nt][half * 2 + 0];
                float u1 = accU[mt][nt][half * 2 + 1];
                float h0 = wgt * (g0 / (1.f + __expf(-g0))) * u0;
                float h1 = wgt * (g1 / (1.f + __expf(-g1))) * u1;
                *(uint32_t*)(g_hdnh + ob + nt * 8) = f22h(h0, h1);
            }
        }
    }
}

// ====================== GEMM2: CTA 128x128, 8 warps (64x32) ==============
__global__ __launch_bounds__(256, 2) void gemm2_kernel(const float* __restrict__ wd) {
    __shared__ __align__(16) __half sA[2][A_PLANE];   // 36 KB
    __shared__ __align__(16) __half sB[2][B2_PLANE];  // 8.5 KB

    int ty = blockIdx.y;
    if (ty >= g_ntiles) return;
    int e = g_tile_e[ty];
    int m0 = g_tile_m[ty];
    int cnt = g_counts[e];
    int base = g_offsets[e];
    int n0 = blockIdx.x * 128;
    int tid = threadIdx.x, wid = tid >> 5, lane = tid & 31;

    int aRow8 = tid >> 3, aC = (tid & 7) * 8;
    int aSlot[4];
    #pragma unroll
    for (int i = 0; i < 4; i++) {
        int sl = base + m0 + i * 32 + aRow8;
        aSlot[i] = sl < NSLOT ? sl : NSLOT - 1;
    }
    // B: 16 rows x 128 cols fp32; 2 float4/thread (col halves)
    int bRow = tid >> 4, bC4 = (tid & 15) * 4;
    const float* pB = wd + (size_t)e * Fn * Hn + n0 + bC4;

    int wm = wid & 1, wn = wid >> 1;
    uint32_t sA_b = smem_u32(sA), sB_b = smem_u32(sB);
    uint32_t aoff[4];
    {
        int r = wm * 64 + (lane & 15);
        uint32_t c = (uint32_t)(lane >> 4) * 16;
        #pragma unroll
        for (int mt = 0; mt < 4; mt++) aoff[mt] = (uint32_t)(r + mt * 16) * 144 + c;
    }
    uint32_t boff[2];
    {
        uint32_t rb = (uint32_t)(lane & 15) * 272 + (uint32_t)(lane >> 4) * 16;
        boff[0] = rb + (uint32_t)wn * 64;
        boff[1] = rb + (uint32_t)wn * 64 + 32;
    }

    float acc[4][4][4] = {};

    // ---- prologue ----
    #pragma unroll
    for (int i = 0; i < 4; i++) {
        int row = i * 32 + aRow8;
        uint4 v = *(const uint4*)(g_hdnh + (size_t)aSlot[i] * Fn + aC);
        *(uint4*)(sA[0] + row * A_ROWE + aC) = v;
    }
    {
        float4 b0 = *(const float4*)(pB + (size_t)bRow * Hn);
        float4 b1 = *(const float4*)(pB + (size_t)bRow * Hn + 64);
        *(uint2*)(sB[0] + bRow * B2_ROWE + bC4) = make_uint2(f22h(b0.x, b0.y), f22h(b0.z, b0.w));
        *(uint2*)(sB[0] + bRow * B2_ROWE + bC4 + 64) = make_uint2(f22h(b1.x, b1.y), f22h(b1.z, b1.w));
    }
    __syncthreads();

    const int nch = Fn / 16;   // 48
    const int nbig = Fn / 64;  // 12
    uint4 aR[4];
    float4 bR0, bR1;

    for (int c = 0; c < nch; c++) {
        int bc = c >> 2, sc = c & 3;
        int s = c & 1, sn = s ^ 1;
        int ba = bc & 1, ban = ba ^ 1;
        bool more = (c + 1 < nch);
        bool abig = (sc == 0) && (bc + 1 < nbig);

        if (abig) {
            int kb = (bc + 1) * 64;
            #pragma unroll
            for (int i = 0; i < 4; i++)
                aR[i] = *(const uint4*)(g_hdnh + (size_t)aSlot[i] * Fn + kb + aC);
        }
        if (more) {
            size_t ro = (size_t)((c + 1) * 16 + bRow) * Hn;
            bR0 = *(const float4*)(pB + ro);
            bR1 = *(const float4*)(pB + ro + 64);
        }

        uint32_t sAo = (uint32_t)ba * (A_PLANE * 2) + (uint32_t)sc * 32;
        uint32_t sBo = (uint32_t)s * (B2_PLANE * 2);
        uint32_t bh[2][4];
        #pragma unroll
        for (int p = 0; p < 2; p++)
            LDSM_X4_T(bh[p][0], bh[p][1], bh[p][2], bh[p][3], sB_b + sBo + boff[p]);
        #pragma unroll
        for (int mt = 0; mt < 4; mt++) {
            uint32_t ah[4];
            LDSM_X4(ah[0], ah[1], ah[2], ah[3], sA_b + sAo + aoff[mt]);
            #pragma unroll
            for (int nt = 0; nt < 4; nt++) {
                uint32_t* B = &bh[nt >> 1][(nt & 1) * 2];
                MMA_FP16(acc[mt][nt], ah, B[0], B[1]);
            }
        }

        if (more) {
            *(uint2*)(sB[sn] + bRow * B2_ROWE + bC4) =
                make_uint2(f22h(bR0.x, bR0.y), f22h(bR0.z, bR0.w));
            *(uint2*)(sB[sn] + bRow * B2_ROWE + bC4 + 64) =
                make_uint2(f22h(bR1.x, bR1.y), f22h(bR1.z, bR1.w));
        }
        if (sc == 3 && bc + 1 < nbig) {
            #pragma unroll
            for (int i = 0; i < 4; i++) {
                int row = i * 32 + aRow8;
                *(uint4*)(sA[ban] + row * A_ROWE + aC) = aR[i];
            }
        }
        __syncthreads();
    }

    // ---- epilogue: stream fp32 to slot buffer ----
    int r = lane >> 2, cp2 = (lane & 3) * 2;
    #pragma unroll
    for (int mt = 0; mt < 4; mt++) {
        #pragma unroll
        for (int half = 0; half < 2; half++) {
            int grow = m0 + wm * 64 + mt * 16 + r + half * 8;
            if (grow >= cnt) continue;
            size_t ob = (size_t)(base + grow) * Hn + n0 + wn * 32 + cp2;
            #pragma unroll
            for (int nt = 0; nt < 4; nt++) {
                float v0 = acc[mt][nt][half * 2 + 0];
                float v1 = acc[mt][nt][half * 2 + 1];
                *(float2*)(g_slotout + ob + nt * 8) = make_float2(v0, v1);
            }
        }
    }
}

// ====================== reduce: sum 4 slots per token ======================
__global__ __launch_bounds__(256) void reduce_kernel(float* __restrict__ out) {
    int t = blockIdx.x;
    int s0 = g_tslot[t * 4 + 0], s1 = g_tslot[t * 4 + 1];
    int s2 = g_tslot[t * 4 + 2], s3 = g_tslot[t * 4 + 3];
    const float* p0 = g_slotout + (size_t)s0 * Hn;
    const float* p1 = g_slotout + (size_t)s1 * Hn;
    const float* p2 = g_slotout + (size_t)s2 * Hn;
    const float* p3 = g_slotout + (size_t)s3 * Hn;
    float* o = out + (size_t)t * Hn;
    for (int i = threadIdx.x * 4; i < Hn; i += 256 * 4) {
        float4 a = *(const float4*)(p0 + i);
        float4 b = *(const float4*)(p1 + i);
        float4 c = *(const float4*)(p2 + i);
        float4 d = *(const float4*)(p3 + i);
        *(float4*)(o + i) = make_float4(a.x + b.x + c.x + d.x,
                                        a.y + b.y + c.y + d.y,
                                        a.z + b.z + c.z + d.z,
                                        a.w + b.w + c.w + d.w);
    }
}

// ====================== launcher ======================
extern "C" void kernel_launch(void* const* d_in, const int* in_sizes, int n_in,
                              void* d_out, int out_size) {
    const float* x  = (const float*)d_in[0];
    const float* gw = (const float*)d_in[1];
    const float* wg = (const float*)d_in[2];
    const float* wu = (const float*)d_in[3];
    const float* wd = (const float*)d_in[4];
    float* out = (float*)d_out;

    float* logits_out = nullptr;
    if (out_size >= Tn * Hn + Tn * En) logits_out = out + (size_t)Tn * Hn;

    convert_x_kernel<<<(Tn * Hn) / 1024, 256>>>(x);
    router_kernel<<<Tn / 4, 256>>>(x, gw, logits_out);
    scan_scatter_kernel<<<1, 1024>>>();
    gemm1_kernel<<<dim3(Fn / 64, MAXTILE), 256>>>(wg, wu);
    gemm2_kernel<<<dim3(Hn / 128, MAXTILE), 256>>>(wd);
    reduce_kernel<<<Tn, 256>>>(out);
}

// round 16
// speedup vs baseline: 4.1975x; 1.2844x over previous
#include <cuda_runtime.h>
#include <cuda_fp16.h>
#include <math.h>
#include <stdint.h>

#define Tn 4096
#define Hn 2048
#define En 32
#define Fn 768
#define TOPK 4
#define NSLOT (Tn * TOPK)
#define MAXTILE 160

// ====================== asm helpers ======================
__device__ __forceinline__ uint32_t smem_u32(const void* p) {
    uint32_t a;
    asm("{ .reg .u64 t; cvta.to.shared.u64 t, %1; cvt.u32.u64 %0, t; }"
        : "=r"(a) : "l"(p));
    return a;
}
__device__ __forceinline__ void cpa16(uint32_t dst, const void* src) {
    asm volatile("cp.async.cg.shared.global [%0], [%1], 16;"
                 :: "r"(dst), "l"(src) : "memory");
}
#define CP_COMMIT() asm volatile("cp.async.commit_group;" ::: "memory")
#define CP_WAIT0()  asm volatile("cp.async.wait_group 0;" ::: "memory")

#define LDSM_X4(r0, r1, r2, r3, a) \
    asm volatile("ldmatrix.sync.aligned.m8n8.x4.shared.b16 {%0,%1,%2,%3}, [%4];" \
                 : "=r"(r0), "=r"(r1), "=r"(r2), "=r"(r3) : "r"(a))
#define LDSM_X4_T(r0, r1, r2, r3, a) \
    asm volatile("ldmatrix.sync.aligned.m8n8.x4.trans.shared.b16 {%0,%1,%2,%3}, [%4];" \
                 : "=r"(r0), "=r"(r1), "=r"(r2), "=r"(r3) : "r"(a))

#define MMA_FP16(d, a, b0, b1) \
    asm volatile("mma.sync.aligned.m16n8k16.row.col.f32.f16.f16.f32 " \
                 "{%0,%1,%2,%3}, {%4,%5,%6,%7}, {%8,%9}, {%0,%1,%2,%3};" \
                 : "+f"((d)[0]), "+f"((d)[1]), "+f"((d)[2]), "+f"((d)[3]) \
                 : "r"((a)[0]), "r"((a)[1]), "r"((a)[2]), "r"((a)[3]), \
                   "r"(b0), "r"(b1))

__device__ __forceinline__ uint32_t f22h(float a, float b) {
    __half2 h = __floats2half2_rn(a, b);
    return *(uint32_t*)&h;
}

// ====================== device scratch (~180 MB) ======================
__device__ int   g_counts[En];
__device__ int   g_offsets[En];
__device__ int   g_cursor[En];
__device__ int   g_topk_idx[NSLOT];
__device__ float g_topk_w[NSLOT];
__device__ int   g_tok[NSLOT];
__device__ float g_tokw[NSLOT];
__device__ int   g_tslot[NSLOT];
__device__ int   g_ntiles;
__device__ int   g_tile_e[MAXTILE];
__device__ int   g_tile_m[MAXTILE];

__device__ __align__(256) __half g_xh[(size_t)Tn * Hn];
__device__ __align__(256) __half g_hdnh[(size_t)NSLOT * Fn];
__device__ __align__(256) float  g_slotout[(size_t)NSLOT * Hn];

// ====================== convert + clear counters ======================
__global__ __launch_bounds__(256) void convert_x_kernel(const float* __restrict__ x) {
    if (blockIdx.x == 0 && threadIdx.x < En) {
        g_counts[threadIdx.x] = 0;
        g_cursor[threadIdx.x] = 0;
    }
    size_t i = ((size_t)blockIdx.x * 256 + threadIdx.x) * 4;
    float4 v = *(const float4*)(x + i);
    uint2 u;
    u.x = f22h(v.x, v.y);
    u.y = f22h(v.z, v.w);
    *(uint2*)(g_xh + i) = u;
}

// ====================== router: 4 tokens per block ======================
__global__ __launch_bounds__(256) void router_kernel(
    const float* __restrict__ x, const float* __restrict__ gw,
    float* __restrict__ logits_out)
{
    int tb = blockIdx.x * 4;
    int tid = threadIdx.x;
    int warp = tid >> 5, lane = tid & 31;
    __shared__ float sx[4][Hn];
    __shared__ float slog[4][En];

    for (int i = tid; i < 4 * Hn; i += 256)
        ((float*)sx)[i] = x[(size_t)tb * Hn + i];
    __syncthreads();

    for (int e = warp; e < En; e += 8) {
        const float* w = gw + (size_t)e * Hn;
        float a0 = 0.f, a1 = 0.f, a2 = 0.f, a3 = 0.f;
        for (int k = lane; k < Hn; k += 32) {
            float wv = w[k];
            a0 += sx[0][k] * wv;
            a1 += sx[1][k] * wv;
            a2 += sx[2][k] * wv;
            a3 += sx[3][k] * wv;
        }
        #pragma unroll
        for (int o = 16; o > 0; o >>= 1) {
            a0 += __shfl_xor_sync(~0u, a0, o);
            a1 += __shfl_xor_sync(~0u, a1, o);
            a2 += __shfl_xor_sync(~0u, a2, o);
            a3 += __shfl_xor_sync(~0u, a3, o);
        }
        if (lane == 0) {
            slog[0][e] = a0; slog[1][e] = a1;
            slog[2][e] = a2; slog[3][e] = a3;
        }
    }
    __syncthreads();

    if (warp < 4) {
        int t = tb + warp;
        float l = slog[warp][lane];
        if (logits_out) logits_out[(size_t)t * En + lane] = l;
        float m = l;
        #pragma unroll
        for (int o = 16; o > 0; o >>= 1) m = fmaxf(m, __shfl_xor_sync(~0u, m, o));
        float p = __expf(l - m), s = p;
        #pragma unroll
        for (int o = 16; o > 0; o >>= 1) s += __shfl_xor_sync(~0u, s, o);
        p /= s;
        float myp = p, tw[TOPK]; int ti[TOPK]; float wsum = 0.f;
        #pragma unroll
        for (int j = 0; j < TOPK; j++) {
            float v = myp; int idx = lane;
            #pragma unroll
            for (int o = 16; o > 0; o >>= 1) {
                float ov = __shfl_xor_sync(~0u, v, o);
                int   oi = __shfl_xor_sync(~0u, idx, o);
                if (ov > v || (ov == v && oi < idx)) { v = ov; idx = oi; }
            }
            tw[j] = v; ti[j] = idx; wsum += v;
            if (lane == idx) myp = -1.f;
        }
        if (lane < TOPK) {
            int e = ti[lane];
            g_topk_idx[t * TOPK + lane] = e;
            g_topk_w[t * TOPK + lane] = tw[lane] / wsum;
            atomicAdd(&g_counts[e], 1);
        }
    }
}

// ====================== fused scan + scatter (single block) ==============
__global__ __launch_bounds__(1024) void scan_scatter_kernel() {
    __shared__ int soff[En];
    int tid = threadIdx.x;
    if (tid < 32) {
        int c = g_counts[tid], inc = c;
        #pragma unroll
        for (int o = 1; o < 32; o <<= 1) {
            int nv = __shfl_up_sync(~0u, inc, o);
            if (tid >= o) inc += nv;
        }
        g_offsets[tid] = inc - c;
        soff[tid] = inc - c;
        if (tid == 0) {
            int nt = 0;
            for (int e = 0; e < En; e++) {
                int cc = g_counts[e];
                for (int m0 = 0; m0 < cc; m0 += 128) {
                    g_tile_e[nt] = e;
                    g_tile_m[nt] = m0;
                    nt++;
                }
            }
            g_ntiles = nt;
        }
    }
    __syncthreads();
    for (int i = tid; i < NSLOT; i += 1024) {
        int e = g_topk_idx[i];
        int pos = atomicAdd(&g_cursor[e], 1);
        int slot = soff[e] + pos;
        g_tok[slot]  = i >> 2;
        g_tokw[slot] = g_topk_w[i];
        g_tslot[i]   = slot;
    }
}

// A big-chunk rows: 64 fp16 (128B) + 16B pad = 144B (72 elems)
#define A_ROWE 72
#define A_PLANE (128 * A_ROWE)      // 18 KB per buffer
#define B1_ROWE 72
#define B1_PLANE (16 * B1_ROWE)
#define B2_ROWE 136
#define B2_PLANE (16 * B2_ROWE)

// ====================== GEMM1: CTA 128x64, 8 warps (64x16) ===============
__global__ __launch_bounds__(256, 2) void gemm1_kernel(
    const float* __restrict__ wg, const float* __restrict__ wu)
{
    __shared__ __align__(16) __half sA[2][A_PLANE];
    __shared__ __align__(16) __half sG[2][B1_PLANE], sU[2][B1_PLANE];
    __shared__ int stok[128];

    int ty = blockIdx.y;
    if (ty >= g_ntiles) return;
    int e = g_tile_e[ty];
    int m0 = g_tile_m[ty];
    int cnt = g_counts[e];
    int base = g_offsets[e];
    int n0 = blockIdx.x * 64;
    int tid = threadIdx.x, wid = tid >> 5, lane = tid & 31;

    if (tid < 128) {
        int idx = base + m0 + tid;
        stok[tid] = g_tok[idx < NSLOT ? idx : NSLOT - 1];
    }
    __syncthreads();

    // A loader: 8 thr/row; 4 cp.async per thread per big-chunk
    int aRow8 = tid >> 3, aC = (tid & 7) * 8;
    uint32_t sA_b = smem_u32(sA);
    const __half* pAr[4];
    uint32_t aDst[4];
    #pragma unroll
    for (int i = 0; i < 4; i++) {
        int row = i * 32 + aRow8;
        pAr[i] = g_xh + (size_t)stok[row] * Hn + aC;
        aDst[i] = (uint32_t)(row * A_ROWE + aC) * 2;
    }
    // B loader: 16 rows x 64 cols fp32 per matrix; 1 float4/thread/matrix
    int bRow = tid >> 4, bC4 = (tid & 15) * 4;
    const float* pG = wg + (size_t)e * Hn * Fn + n0 + bC4;
    const float* pU = wu + (size_t)e * Hn * Fn + n0 + bC4;

    // compute maps: 8 warps = 2M x 4N; warp tile 64x16
    int wm = wid & 1, wn = wid >> 1;
    uint32_t sG_b = smem_u32(sG), sU_b = smem_u32(sU);
    uint32_t aoff[4];
    {
        int r = wm * 64 + (lane & 15);
        uint32_t c = (uint32_t)(lane >> 4) * 16;
        #pragma unroll
        for (int mt = 0; mt < 4; mt++) aoff[mt] = (uint32_t)(r + mt * 16) * 144 + c;
    }
    uint32_t boff = (uint32_t)(lane & 15) * 144 + (uint32_t)(lane >> 4) * 16 +
                    (uint32_t)wn * 32;

    float accG[4][2][4] = {}, accU[4][2][4] = {};

    const int nch = Hn / 16;   // 128
    const int nbig = Hn / 64;  // 32
    float4 gset[2], uset[2];

    // ---- prologue ----
    // A big-chunk 0 via cp.async
    #pragma unroll
    for (int i = 0; i < 4; i++) cpa16(sA_b + aDst[i], pAr[i]);
    CP_COMMIT();
    // B chunk 0: load + convert + STS into buffer 0
    {
        float4 g = *(const float4*)(pG + (size_t)bRow * Fn);
        float4 u = *(const float4*)(pU + (size_t)bRow * Fn);
        *(uint2*)(sG[0] + bRow * B1_ROWE + bC4) = make_uint2(f22h(g.x, g.y), f22h(g.z, g.w));
        *(uint2*)(sU[0] + bRow * B1_ROWE + bC4) = make_uint2(f22h(u.x, u.y), f22h(u.z, u.w));
    }
    // B chunk 1 into register set 1
    {
        size_t ro = (size_t)(16 + bRow) * Fn;
        gset[1] = *(const float4*)(pG + ro);
        uset[1] = *(const float4*)(pU + ro);
    }
    CP_WAIT0();
    __syncthreads();

    for (int c = 0; c < nch; c++) {
        int bc = c >> 2, sc = c & 3;
        int ba = bc & 1, ban = ba ^ 1;
        // 1) B LDG distance-2 into set[c&1]
        if (c + 2 < nch) {
            size_t ro = (size_t)((c + 2) * 16 + bRow) * Fn;
            gset[c & 1] = *(const float4*)(pG + ro);
            uset[c & 1] = *(const float4*)(pU + ro);
        }
        // 2) A cp.async for next big-chunk at sc==0
        if (sc == 0 && bc + 1 < nbig) {
            int kb = (bc + 1) * 64;
            #pragma unroll
            for (int i = 0; i < 4; i++)
                cpa16(sA_b + ban * (A_PLANE * 2) + aDst[i], pAr[i] + kb);
            CP_COMMIT();
        }
        // 3) MMA on chunk c
        uint32_t sAo = (uint32_t)ba * (A_PLANE * 2) + (uint32_t)sc * 32;
        uint32_t sBo = (uint32_t)(c & 1) * (B1_PLANE * 2);
        uint32_t bg[4], bu[4];
        LDSM_X4_T(bg[0], bg[1], bg[2], bg[3], sG_b + sBo + boff);
        LDSM_X4_T(bu[0], bu[1], bu[2], bu[3], sU_b + sBo + boff);
        #pragma unroll
        for (int mt = 0; mt < 4; mt++) {
            uint32_t ah[4];
            LDSM_X4(ah[0], ah[1], ah[2], ah[3], sA_b + sAo + aoff[mt]);
            #pragma unroll
            for (int nt = 0; nt < 2; nt++) {
                MMA_FP16(accG[mt][nt], ah, bg[nt * 2], bg[nt * 2 + 1]);
                MMA_FP16(accU[mt][nt], ah, bu[nt * 2], bu[nt * 2 + 1]);
            }
        }
        // 4) STS chunk c+1 from set[(c+1)&1] into buffer (c+1)&1
        if (c + 1 < nch) {
            int sb = (c + 1) & 1;
            *(uint2*)(sG[sb] + bRow * B1_ROWE + bC4) =
                make_uint2(f22h(gset[sb].x, gset[sb].y), f22h(gset[sb].z, gset[sb].w));
            *(uint2*)(sU[sb] + bRow * B1_ROWE + bC4) =
                make_uint2(f22h(uset[sb].x, uset[sb].y), f22h(uset[sb].z, uset[sb].w));
        }
        // 5) wait for A async before switching big-chunk buffers
        if (sc == 3) CP_WAIT0();
        __syncthreads();
    }

    // ---- epilogue: h = w * silu(g) * u -> hdn fp16 ----
    int r = lane >> 2, cp2 = (lane & 3) * 2;
    #pragma unroll
    for (int mt = 0; mt < 4; mt++) {
        #pragma unroll
        for (int half = 0; half < 2; half++) {
            int grow = m0 + wm * 64 + mt * 16 + r + half * 8;
            if (grow >= cnt) continue;
            int slot = base + grow;
            float wgt = g_tokw[slot];
            size_t ob = (size_t)slot * Fn + n0 + wn * 16 + cp2;
            #pragma unroll
            for (int nt = 0; nt < 2; nt++) {
                float g0 = accG[mt][nt][half * 2 + 0];
                float g1 = accG[mt][nt][half * 2 + 1];
                float u0 = accU[mt][nt][half * 2 + 0];
                float u1 = accU[mt][nt][half * 2 + 1];
                float h0 = wgt * (g0 / (1.f + __expf(-g0))) * u0;
                float h1 = wgt * (g1 / (1.f + __expf(-g1))) * u1;
                *(uint32_t*)(g_hdnh + ob + nt * 8) = f22h(h0, h1);
            }
        }
    }
}

// ====================== GEMM2: CTA 128x128, 8 warps (64x32) ==============
__global__ __launch_bounds__(256, 2) void gemm2_kernel(const float* __restrict__ wd) {
    __shared__ __align__(16) __half sA[2][A_PLANE];
    __shared__ __align__(16) __half sB[2][B2_PLANE];

    int ty = blockIdx.y;
    if (ty >= g_ntiles) return;
    int e = g_tile_e[ty];
    int m0 = g_tile_m[ty];
    int cnt = g_counts[e];
    int base = g_offsets[e];
    int n0 = blockIdx.x * 128;
    int tid = threadIdx.x, wid = tid >> 5, lane = tid & 31;

    int aRow8 = tid >> 3, aC = (tid & 7) * 8;
    uint32_t sA_b = smem_u32(sA);
    const __half* pAr[4];
    uint32_t aDst[4];
    #pragma unroll
    for (int i = 0; i < 4; i++) {
        int row = i * 32 + aRow8;
        int sl = base + m0 + row; if (sl >= NSLOT) sl = NSLOT - 1;
        pAr[i] = g_hdnh + (size_t)sl * Fn + aC;
        aDst[i] = (uint32_t)(row * A_ROWE + aC) * 2;
    }
    // B: 16 rows x 128 cols fp32; 2 float4/thread
    int bRow = tid >> 4, bC4 = (tid & 15) * 4;
    const float* pB = wd + (size_t)e * Fn * Hn + n0 + bC4;

    int wm = wid & 1, wn = wid >> 1;
    uint32_t sB_b = smem_u32(sB);
    uint32_t aoff[4];
    {
        int r = wm * 64 + (lane & 15);
        uint32_t c = (uint32_t)(lane >> 4) * 16;
        #pragma unroll
        for (int mt = 0; mt < 4; mt++) aoff[mt] = (uint32_t)(r + mt * 16) * 144 + c;
    }
    uint32_t boff[2];
    {
        uint32_t rb = (uint32_t)(lane & 15) * 272 + (uint32_t)(lane >> 4) * 16;
        boff[0] = rb + (uint32_t)wn * 64;
        boff[1] = rb + (uint32_t)wn * 64 + 32;
    }

    float acc[4][4][4] = {};

    const int nch = Fn / 16;   // 48
    const int nbig = Fn / 64;  // 12
    float4 bset0[2], bset1[2];

    // ---- prologue ----
    #pragma unroll
    for (int i = 0; i < 4; i++) cpa16(sA_b + aDst[i], pAr[i]);
    CP_COMMIT();
    {
        float4 b0 = *(const float4*)(pB + (size_t)bRow * Hn);
        float4 b1 = *(const float4*)(pB + (size_t)bRow * Hn + 64);
        *(uint2*)(sB[0] + bRow * B2_ROWE + bC4) = make_uint2(f22h(b0.x, b0.y), f22h(b0.z, b0.w));
        *(uint2*)(sB[0] + bRow * B2_ROWE + bC4 + 64) = make_uint2(f22h(b1.x, b1.y), f22h(b1.z, b1.w));
    }
    {
        size_t ro = (size_t)(16 + bRow) * Hn;
        bset0[1] = *(const float4*)(pB + ro);
        bset1[1] = *(const float4*)(pB + ro + 64);
    }
    CP_WAIT0();
    __syncthreads();

    for (int c = 0; c < nch; c++) {
        int bc = c >> 2, sc = c & 3;
        int ba = bc & 1, ban = ba ^ 1;
        if (c + 2 < nch) {
            size_t ro = (size_t)((c + 2) * 16 + bRow) * Hn;
            bset0[c & 1] = *(const float4*)(pB + ro);
            bset1[c & 1] = *(const float4*)(pB + ro + 64);
        }
        if (sc == 0 && bc + 1 < nbig) {
            int kb = (bc + 1) * 64;
            #pragma unroll
            for (int i = 0; i < 4; i++)
                cpa16(sA_b + ban * (A_PLANE * 2) + aDst[i], pAr[i] + kb);
            CP_COMMIT();
        }

        uint32_t sAo = (uint32_t)ba * (A_PLANE * 2) + (uint32_t)sc * 32;
        uint32_t sBo = (uint32_t)(c & 1) * (B2_PLANE * 2);
        uint32_t bh[2][4];
        #pragma unroll
        for (int p = 0; p < 2; p++)
            LDSM_X4_T(bh[p][0], bh[p][1], bh[p][2], bh[p][3], sB_b + sBo + boff[p]);
        #pragma unroll
        for (int mt = 0; mt < 4; mt++) {
            uint32_t ah[4];
            LDSM_X4(ah[0], ah[1], ah[2], ah[3], sA_b + sAo + aoff[mt]);
            #pragma unroll
            for (int nt = 0; nt < 4; nt++) {
                uint32_t* B = &bh[nt >> 1][(nt & 1) * 2];
                MMA_FP16(acc[mt][nt], ah, B[0], B[1]);
            }
        }

        if (c + 1 < nch) {
            int sb = (c + 1) & 1;
            *(uint2*)(sB[sb] + bRow * B2_ROWE + bC4) =
                make_uint2(f22h(bset0[sb].x, bset0[sb].y), f22h(bset0[sb].z, bset0[sb].w));
            *(uint2*)(sB[sb] + bRow * B2_ROWE + bC4 + 64) =
                make_uint2(f22h(bset1[sb].x, bset1[sb].y), f22h(bset1[sb].z, bset1[sb].w));
        }
        if (sc == 3) CP_WAIT0();
        __syncthreads();
    }

    // ---- epilogue: stream fp32 to slot buffer ----
    int r = lane >> 2, cp2 = (lane & 3) * 2;
    #pragma unroll
    for (int mt = 0; mt < 4; mt++) {
        #pragma unroll
        for (int half = 0; half < 2; half++) {
            int grow = m0 + wm * 64 + mt * 16 + r + half * 8;
            if (grow >= cnt) continue;
            size_t ob = (size_t)(base + grow) * Hn + n0 + wn * 32 + cp2;
            #pragma unroll
            for (int nt = 0; nt < 4; nt++) {
                float v0 = acc[mt][nt][half * 2 + 0];
                float v1 = acc[mt][nt][half * 2 + 1];
                *(float2*)(g_slotout + ob + nt * 8) = make_float2(v0, v1);
            }
        }
    }
}

// ====================== reduce: sum 4 slots per token ======================
__global__ __launch_bounds__(256) void reduce_kernel(float* __restrict__ out) {
    int t = blockIdx.x;
    int s0 = g_tslot[t * 4 + 0], s1 = g_tslot[t * 4 + 1];
    int s2 = g_tslot[t * 4 + 2], s3 = g_tslot[t * 4 + 3];
    const float* p0 = g_slotout + (size_t)s0 * Hn;
    const float* p1 = g_slotout + (size_t)s1 * Hn;
    const float* p2 = g_slotout + (size_t)s2 * Hn;
    const float* p3 = g_slotout + (size_t)s3 * Hn;
    float* o = out + (size_t)t * Hn;
    for (int i = threadIdx.x * 4; i < Hn; i += 256 * 4) {
        float4 a = *(const float4*)(p0 + i);
        float4 b = *(const float4*)(p1 + i);
        float4 c = *(const float4*)(p2 + i);
        float4 d = *(const float4*)(p3 + i);
        *(float4*)(o + i) = make_float4(a.x + b.x + c.x + d.x,
                                        a.y + b.y + c.y + d.y,
                                        a.z + b.z + c.z + d.z,
                                        a.w + b.w + c.w + d.w);
    }
}

// ====================== launcher ======================
extern "C" void kernel_launch(void* const* d_in, const int* in_sizes, int n_in,
                              void* d_out, int out_size) {
    const float* x  = (const float*)d_in[0];
    const float* gw = (const float*)d_in[1];
    const float* wg = (const float*)d_in[2];
    const float* wu = (const float*)d_in[3];
    const float* wd = (const float*)d_in[4];
    float* out = (float*)d_out;

    float* logits_out = nullptr;
    if (out_size >= Tn * Hn + Tn * En) logits_out = out + (size_t)Tn * Hn;

    convert_x_kernel<<<(Tn * Hn) / 1024, 256>>>(x);
    router_kernel<<<Tn / 4, 256>>>(x, gw, logits_out);
    scan_scatter_kernel<<<1, 1024>>>();
    gemm1_kernel<<<dim3(Fn / 64, MAXTILE), 256>>>(wg, wu);
    gemm2_kernel<<<dim3(Hn / 128, MAXTILE), 256>>>(wd);
    reduce_kernel<<<Tn, 256>>>(out);
}

// round 17
// speedup vs baseline: 4.4974x; 1.0714x over previous
#include <cuda_runtime.h>
#include <cuda_fp16.h>
#include <math.h>
#include <stdint.h>

#define Tn 4096
#define Hn 2048
#define En 32
#define Fn 768
#define TOPK 4
#define NSLOT (Tn * TOPK)
#define MAXTILE 160

// ====================== asm helpers ======================
__device__ __forceinline__ uint32_t smem_u32(const void* p) {
    uint32_t a;
    asm("{ .reg .u64 t; cvta.to.shared.u64 t, %1; cvt.u32.u64 %0, t; }"
        : "=r"(a) : "l"(p));
    return a;
}
__device__ __forceinline__ void cpa16(uint32_t dst, const void* src) {
    asm volatile("cp.async.cg.shared.global [%0], [%1], 16;"
                 :: "r"(dst), "l"(src) : "memory");
}
#define CP_COMMIT() asm volatile("cp.async.commit_group;" ::: "memory")
#define CP_WAIT0()  asm volatile("cp.async.wait_group 0;" ::: "memory")

#define LDSM_X4(r0, r1, r2, r3, a) \
    asm volatile("ldmatrix.sync.aligned.m8n8.x4.shared.b16 {%0,%1,%2,%3}, [%4];" \
                 : "=r"(r0), "=r"(r1), "=r"(r2), "=r"(r3) : "r"(a))
#define LDSM_X4_T(r0, r1, r2, r3, a) \
    asm volatile("ldmatrix.sync.aligned.m8n8.x4.trans.shared.b16 {%0,%1,%2,%3}, [%4];" \
                 : "=r"(r0), "=r"(r1), "=r"(r2), "=r"(r3) : "r"(a))

#define MMA_FP16(d, a, b0, b1) \
    asm volatile("mma.sync.aligned.m16n8k16.row.col.f32.f16.f16.f32 " \
                 "{%0,%1,%2,%3}, {%4,%5,%6,%7}, {%8,%9}, {%0,%1,%2,%3};" \
                 : "+f"((d)[0]), "+f"((d)[1]), "+f"((d)[2]), "+f"((d)[3]) \
                 : "r"((a)[0]), "r"((a)[1]), "r"((a)[2]), "r"((a)[3]), \
                   "r"(b0), "r"(b1))

__device__ __forceinline__ uint32_t f22h(float a, float b) {
    __half2 h = __floats2half2_rn(a, b);
    return *(uint32_t*)&h;
}

// ====================== device scratch (~180 MB) ======================
__device__ int   g_counts[En];
__device__ int   g_offsets[En];
__device__ int   g_cursor[En];
__device__ int   g_topk_idx[NSLOT];
__device__ float g_topk_w[NSLOT];
__device__ int   g_tok[NSLOT];
__device__ float g_tokw[NSLOT];
__device__ int   g_tslot[NSLOT];
__device__ int   g_ntiles;
__device__ int   g_tile_e[MAXTILE];
__device__ int   g_tile_m[MAXTILE];

__device__ __align__(256) __half g_xh[(size_t)Tn * Hn];
__device__ __align__(256) __half g_hdnh[(size_t)NSLOT * Fn];
__device__ __align__(256) float  g_slotout[(size_t)NSLOT * Hn];

// ====================== convert + clear counters ======================
__global__ __launch_bounds__(256) void convert_x_kernel(const float* __restrict__ x) {
    if (blockIdx.x == 0 && threadIdx.x < En) {
        g_counts[threadIdx.x] = 0;
        g_cursor[threadIdx.x] = 0;
    }
    size_t i = ((size_t)blockIdx.x * 256 + threadIdx.x) * 4;
    float4 v = *(const float4*)(x + i);
    uint2 u;
    u.x = f22h(v.x, v.y);
    u.y = f22h(v.z, v.w);
    *(uint2*)(g_xh + i) = u;
}

// ====================== router: 4 tokens per block ======================
__global__ __launch_bounds__(256) void router_kernel(
    const float* __restrict__ x, const float* __restrict__ gw,
    float* __restrict__ logits_out)
{
    int tb = blockIdx.x * 4;
    int tid = threadIdx.x;
    int warp = tid >> 5, lane = tid & 31;
    __shared__ float sx[4][Hn];
    __shared__ float slog[4][En];

    for (int i = tid; i < 4 * Hn; i += 256)
        ((float*)sx)[i] = x[(size_t)tb * Hn + i];
    __syncthreads();

    for (int e = warp; e < En; e += 8) {
        const float* w = gw + (size_t)e * Hn;
        float a0 = 0.f, a1 = 0.f, a2 = 0.f, a3 = 0.f;
        for (int k = lane; k < Hn; k += 32) {
            float wv = w[k];
            a0 += sx[0][k] * wv;
            a1 += sx[1][k] * wv;
            a2 += sx[2][k] * wv;
            a3 += sx[3][k] * wv;
        }
        #pragma unroll
        for (int o = 16; o > 0; o >>= 1) {
            a0 += __shfl_xor_sync(~0u, a0, o);
            a1 += __shfl_xor_sync(~0u, a1, o);
            a2 += __shfl_xor_sync(~0u, a2, o);
            a3 += __shfl_xor_sync(~0u, a3, o);
        }
        if (lane == 0) {
            slog[0][e] = a0; slog[1][e] = a1;
            slog[2][e] = a2; slog[3][e] = a3;
        }
    }
    __syncthreads();

    if (warp < 4) {
        int t = tb + warp;
        float l = slog[warp][lane];
        if (logits_out) logits_out[(size_t)t * En + lane] = l;
        float m = l;
        #pragma unroll
        for (int o = 16; o > 0; o >>= 1) m = fmaxf(m, __shfl_xor_sync(~0u, m, o));
        float p = __expf(l - m), s = p;
        #pragma unroll
        for (int o = 16; o > 0; o >>= 1) s += __shfl_xor_sync(~0u, s, o);
        p /= s;
        float myp = p, tw[TOPK]; int ti[TOPK]; float wsum = 0.f;
        #pragma unroll
        for (int j = 0; j < TOPK; j++) {
            float v = myp; int idx = lane;
            #pragma unroll
            for (int o = 16; o > 0; o >>= 1) {
                float ov = __shfl_xor_sync(~0u, v, o);
                int   oi = __shfl_xor_sync(~0u, idx, o);
                if (ov > v || (ov == v && oi < idx)) { v = ov; idx = oi; }
            }
            tw[j] = v; ti[j] = idx; wsum += v;
            if (lane == idx) myp = -1.f;
        }
        if (lane < TOPK) {
            int e = ti[lane];
            g_topk_idx[t * TOPK + lane] = e;
            g_topk_w[t * TOPK + lane] = tw[lane] / wsum;
            atomicAdd(&g_counts[e], 1);
        }
    }
}

// ====================== fused scan + scatter (single block) ==============
__global__ __launch_bounds__(1024) void scan_scatter_kernel() {
    __shared__ int soff[En];
    int tid = threadIdx.x;
    if (tid < 32) {
        int c = g_counts[tid], inc = c;
        #pragma unroll
        for (int o = 1; o < 32; o <<= 1) {
            int nv = __shfl_up_sync(~0u, inc, o);
            if (tid >= o) inc += nv;
        }
        g_offsets[tid] = inc - c;
        soff[tid] = inc - c;
        if (tid == 0) {
            int nt = 0;
            for (int e = 0; e < En; e++) {
                int cc = g_counts[e];
                for (int m0 = 0; m0 < cc; m0 += 128) {
                    g_tile_e[nt] = e;
                    g_tile_m[nt] = m0;
                    nt++;
                }
            }
            g_ntiles = nt;
        }
    }
    __syncthreads();
    for (int i = tid; i < NSLOT; i += 1024) {
        int e = g_topk_idx[i];
        int pos = atomicAdd(&g_cursor[e], 1);
        int slot = soff[e] + pos;
        g_tok[slot]  = i >> 2;
        g_tokw[slot] = g_topk_w[i];
        g_tslot[i]   = slot;
    }
}

// A big-chunk: K=32 fp16 = 64B + 16B pad = 80B rows (40 elems)
#define A_ROWE 40
#define A_PLANE (128 * A_ROWE)      // 10240 B per buffer
// B stages: 16 rows each
#define B1_ROWE 72
#define B1_PLANE (16 * B1_ROWE)     // 2304 B
#define B2_ROWE 136
#define B2_PLANE (16 * B2_ROWE)     // 4352 B

// ====================== GEMM1: CTA 128x64, 8 warps (64x16) ===============
__global__ __launch_bounds__(256, 2) void gemm1_kernel(
    const float* __restrict__ wg, const float* __restrict__ wu)
{
    __shared__ __align__(16) __half sA[2][A_PLANE];                   // 20.5 KB
    __shared__ __align__(16) __half sG[4][B1_PLANE], sU[4][B1_PLANE]; // 18 KB
    __shared__ int stok[128];

    int ty = blockIdx.y;
    if (ty >= g_ntiles) return;
    int e = g_tile_e[ty];
    int m0 = g_tile_m[ty];
    int cnt = g_counts[e];
    int base = g_offsets[e];
    int n0 = blockIdx.x * 64;
    int tid = threadIdx.x, wid = tid >> 5, lane = tid & 31;

    if (tid < 128) {
        int idx = base + m0 + tid;
        stok[tid] = g_tok[idx < NSLOT ? idx : NSLOT - 1];
    }
    __syncthreads();

    // A loader: 4 thr/row (K=32 -> 64B/row), 2 cp.async per thread
    int aRow4 = tid >> 2, aC = (tid & 3) * 8;
    uint32_t sA_b = smem_u32(sA);
    const __half* pAr[2];
    uint32_t aDst[2];
    #pragma unroll
    for (int i = 0; i < 2; i++) {
        int row = i * 64 + aRow4;
        pAr[i] = g_xh + (size_t)stok[row] * Hn + aC;
        aDst[i] = (uint32_t)(row * A_ROWE + aC) * 2;
    }
    // B loader: 1 float4 per thread per matrix per chunk
    int bRow = tid >> 4, bC4 = (tid & 15) * 4;
    const float* pG = wg + (size_t)e * Hn * Fn + n0 + bC4;
    const float* pU = wu + (size_t)e * Hn * Fn + n0 + bC4;

    // compute maps: 8 warps = 2M x 4N; warp tile 64x16
    int wm = wid & 1, wn = wid >> 1;
    uint32_t sG_b = smem_u32(sG), sU_b = smem_u32(sU);
    uint32_t aoff[4];
    {
        int r = wm * 64 + (lane & 15);
        uint32_t c = (uint32_t)(lane >> 4) * 16;
        #pragma unroll
        for (int mt = 0; mt < 4; mt++) aoff[mt] = (uint32_t)(r + mt * 16) * 80 + c;
    }
    uint32_t boff = (uint32_t)(lane & 15) * 144 + (uint32_t)(lane >> 4) * 16 +
                    (uint32_t)wn * 32;

    float accG[4][2][4] = {}, accU[4][2][4] = {};

    const int nch = Hn / 16;   // 128
    const int nchp = nch / 2;  // 64 iterations
    float4 gset[2], uset[2];

    // ---- prologue ----
    #pragma unroll
    for (int i = 0; i < 2; i++) cpa16(sA_b + aDst[i], pAr[i]);
    CP_COMMIT();
    // STS chunks 0,1 directly
    #pragma unroll
    for (int q = 0; q < 2; q++) {
        size_t ro = (size_t)(q * 16 + bRow) * Fn;
        float4 g = *(const float4*)(pG + ro);
        float4 u = *(const float4*)(pU + ro);
        *(uint2*)(sG[q] + bRow * B1_ROWE + bC4) = make_uint2(f22h(g.x, g.y), f22h(g.z, g.w));
        *(uint2*)(sU[q] + bRow * B1_ROWE + bC4) = make_uint2(f22h(u.x, u.y), f22h(u.z, u.w));
    }
    // regs <- chunks 2,3
    #pragma unroll
    for (int q = 0; q < 2; q++) {
        size_t ro = (size_t)((2 + q) * 16 + bRow) * Fn;
        gset[q] = *(const float4*)(pG + ro);
        uset[q] = *(const float4*)(pU + ro);
    }
    CP_WAIT0();
    __syncthreads();

    for (int p = 0; p < nchp; p++) {
        int ba = p & 1, ban = ba ^ 1;
        // 1) STS chunks 2p+2, 2p+3 from regs
        if (p + 1 < nchp) {
            #pragma unroll
            for (int q = 0; q < 2; q++) {
                int buf = (2 * p + 2 + q) & 3;
                *(uint2*)(sG[buf] + bRow * B1_ROWE + bC4) =
                    make_uint2(f22h(gset[q].x, gset[q].y), f22h(gset[q].z, gset[q].w));
                *(uint2*)(sU[buf] + bRow * B1_ROWE + bC4) =
                    make_uint2(f22h(uset[q].x, uset[q].y), f22h(uset[q].z, uset[q].w));
            }
        }
        // 2) LDG chunks 2p+4, 2p+5 into regs
        if (p + 2 < nchp) {
            #pragma unroll
            for (int q = 0; q < 2; q++) {
                size_t ro = (size_t)((2 * p + 4 + q) * 16 + bRow) * Fn;
                gset[q] = *(const float4*)(pG + ro);
                uset[q] = *(const float4*)(pU + ro);
            }
        }
        // 3) cp.async A big-chunk p+1
        if (p + 1 < nchp) {
            int kb = (p + 1) * 32;
            #pragma unroll
            for (int i = 0; i < 2; i++)
                cpa16(sA_b + ban * (A_PLANE * 2) + aDst[i], pAr[i] + kb);
            CP_COMMIT();
        }
        // 4) compute chunks 2p, 2p+1
        #pragma unroll
        for (int sc = 0; sc < 2; sc++) {
            uint32_t sAo = (uint32_t)ba * (A_PLANE * 2) + (uint32_t)sc * 32;
            uint32_t sBo = (uint32_t)((2 * p + sc) & 3) * (B1_PLANE * 2);
            uint32_t bg[4], bu[4];
            LDSM_X4_T(bg[0], bg[1], bg[2], bg[3], sG_b + sBo + boff);
            LDSM_X4_T(bu[0], bu[1], bu[2], bu[3], sU_b + sBo + boff);
            #pragma unroll
            for (int mt = 0; mt < 4; mt++) {
                uint32_t ah[4];
                LDSM_X4(ah[0], ah[1], ah[2], ah[3], sA_b + sAo + aoff[mt]);
                #pragma unroll
                for (int nt = 0; nt < 2; nt++) {
                    MMA_FP16(accG[mt][nt], ah, bg[nt * 2], bg[nt * 2 + 1]);
                    MMA_FP16(accU[mt][nt], ah, bu[nt * 2], bu[nt * 2 + 1]);
                }
            }
        }
        // 5) wait + barrier
        if (p + 1 < nchp) CP_WAIT0();
        __syncthreads();
    }

    // ---- epilogue: h = w * silu(g) * u -> hdn fp16 ----
    int r = lane >> 2, cp2 = (lane & 3) * 2;
    #pragma unroll
    for (int mt = 0; mt < 4; mt++) {
        #pragma unroll
        for (int half = 0; half < 2; half++) {
            int grow = m0 + wm * 64 + mt * 16 + r + half * 8;
            if (grow >= cnt) continue;
            int slot = base + grow;
            float wgt = g_tokw[slot];
            size_t ob = (size_t)slot * Fn + n0 + wn * 16 + cp2;
            #pragma unroll
            for (int nt = 0; nt < 2; nt++) {
                float g0 = accG[mt][nt][half * 2 + 0];
                float g1 = accG[mt][nt][half * 2 + 1];
                float u0 = accU[mt][nt][half * 2 + 0];
                float u1 = accU[mt][nt][half * 2 + 1];
                float h0 = wgt * (g0 / (1.f + __expf(-g0))) * u0;
                float h1 = wgt * (g1 / (1.f + __expf(-g1))) * u1;
                *(uint32_t*)(g_hdnh + ob + nt * 8) = f22h(h0, h1);
            }
        }
    }
}

// ====================== GEMM2: CTA 128x128, 8 warps (64x32) ==============
__global__ __launch_bounds__(256, 2) void gemm2_kernel(const float* __restrict__ wd) {
    __shared__ __align__(16) __half sA[2][A_PLANE];   // 20.5 KB
    __shared__ __align__(16) __half sB[4][B2_PLANE];  // 17 KB

    int ty = blockIdx.y;
    if (ty >= g_ntiles) return;
    int e = g_tile_e[ty];
    int m0 = g_tile_m[ty];
    int cnt = g_counts[e];
    int base = g_offsets[e];
    int n0 = blockIdx.x * 128;
    int tid = threadIdx.x, wid = tid >> 5, lane = tid & 31;

    int aRow4 = tid >> 2, aC = (tid & 3) * 8;
    uint32_t sA_b = smem_u32(sA);
    const __half* pAr[2];
    uint32_t aDst[2];
    #pragma unroll
    for (int i = 0; i < 2; i++) {
        int row = i * 64 + aRow4;
        int sl = base + m0 + row; if (sl >= NSLOT) sl = NSLOT - 1;
        pAr[i] = g_hdnh + (size_t)sl * Fn + aC;
        aDst[i] = (uint32_t)(row * A_ROWE + aC) * 2;
    }
    int bRow = tid >> 4, bC4 = (tid & 15) * 4;
    const float* pB = wd + (size_t)e * Fn * Hn + n0 + bC4;

    int wm = wid & 1, wn = wid >> 1;
    uint32_t sB_b = smem_u32(sB);
    uint32_t aoff[4];
    {
        int r = wm * 64 + (lane & 15);
        uint32_t c = (uint32_t)(lane >> 4) * 16;
        #pragma unroll
        for (int mt = 0; mt < 4; mt++) aoff[mt] = (uint32_t)(r + mt * 16) * 80 + c;
    }
    uint32_t boff[2];
    {
        uint32_t rb = (uint32_t)(lane & 15) * 272 + (uint32_t)(lane >> 4) * 16;
        boff[0] = rb + (uint32_t)wn * 64;
        boff[1] = rb + (uint32_t)wn * 64 + 32;
    }

    float acc[4][4][4] = {};

    const int nch = Fn / 16;   // 48
    const int nchp = nch / 2;  // 24
    float4 bs0[2], bs1[2];

    // ---- prologue ----
    #pragma unroll
    for (int i = 0; i < 2; i++) cpa16(sA_b + aDst[i], pAr[i]);
    CP_COMMIT();
    #pragma unroll
    for (int q = 0; q < 2; q++) {
        size_t ro = (size_t)(q * 16 + bRow) * Hn;
        float4 b0 = *(const float4*)(pB + ro);
        float4 b1 = *(const float4*)(pB + ro + 64);
        *(uint2*)(sB[q] + bRow * B2_ROWE + bC4) = make_uint2(f22h(b0.x, b0.y), f22h(b0.z, b0.w));
        *(uint2*)(sB[q] + bRow * B2_ROWE + bC4 + 64) = make_uint2(f22h(b1.x, b1.y), f22h(b1.z, b1.w));
    }
    #pragma unroll
    for (int q = 0; q < 2; q++) {
        size_t ro = (size_t)((2 + q) * 16 + bRow) * Hn;
        bs0[q] = *(const float4*)(pB + ro);
        bs1[q] = *(const float4*)(pB + ro + 64);
    }
    CP_WAIT0();
    __syncthreads();

    for (int p = 0; p < nchp; p++) {
        int ba = p & 1, ban = ba ^ 1;
        if (p + 1 < nchp) {
            #pragma unroll
            for (int q = 0; q < 2; q++) {
                int buf = (2 * p + 2 + q) & 3;
                *(uint2*)(sB[buf] + bRow * B2_ROWE + bC4) =
                    make_uint2(f22h(bs0[q].x, bs0[q].y), f22h(bs0[q].z, bs0[q].w));
                *(uint2*)(sB[buf] + bRow * B2_ROWE + bC4 + 64) =
                    make_uint2(f22h(bs1[q].x, bs1[q].y), f22h(bs1[q].z, bs1[q].w));
            }
        }
        if (p + 2 < nchp) {
            #pragma unroll
            for (int q = 0; q < 2; q++) {
                size_t ro = (size_t)((2 * p + 4 + q) * 16 + bRow) * Hn;
                bs0[q] = *(const float4*)(pB + ro);
                bs1[q] = *(const float4*)(pB + ro + 64);
            }
        }
        if (p + 1 < nchp) {
            int kb = (p + 1) * 32;
            #pragma unroll
            for (int i = 0; i < 2; i++)
                cpa16(sA_b + ban * (A_PLANE * 2) + aDst[i], pAr[i] + kb);
            CP_COMMIT();
        }
        #pragma unroll
        for (int sc = 0; sc < 2; sc++) {
            uint32_t sAo = (uint32_t)ba * (A_PLANE * 2) + (uint32_t)sc * 32;
            uint32_t sBo = (uint32_t)((2 * p + sc) & 3) * (B2_PLANE * 2);
            uint32_t bh[2][4];
            #pragma unroll
            for (int q = 0; q < 2; q++)
                LDSM_X4_T(bh[q][0], bh[q][1], bh[q][2], bh[q][3], sB_b + sBo + boff[q]);
            #pragma unroll
            for (int mt = 0; mt < 4; mt++) {
                uint32_t ah[4];
                LDSM_X4(ah[0], ah[1], ah[2], ah[3], sA_b + sAo + aoff[mt]);
                #pragma unroll
                for (int nt = 0; nt < 4; nt++) {
                    uint32_t* B = &bh[nt >> 1][(nt & 1) * 2];
                    MMA_FP16(acc[mt][nt], ah, B[0], B[1]);
                }
            }
        }
        if (p + 1 < nchp) CP_WAIT0();
        __syncthreads();
    }

    // ---- epilogue: stream fp32 to slot buffer ----
    int r = lane >> 2, cp2 = (lane & 3) * 2;
    #pragma unroll
    for (int mt = 0; mt < 4; mt++) {
        #pragma unroll
        for (int half = 0; half < 2; half++) {
            int grow = m0 + wm * 64 + mt * 16 + r + half * 8;
            if (grow >= cnt) continue;
            size_t ob = (size_t)(base + grow) * Hn + n0 + wn * 32 + cp2;
            #pragma unroll
            for (int nt = 0; nt < 4; nt++) {
                float v0 = acc[mt][nt][half * 2 + 0];
                float v1 = acc[mt][nt][half * 2 + 1];
                *(float2*)(g_slotout + ob + nt * 8) = make_float2(v0, v1);
            }
        }
    }
}

// ====================== reduce: sum 4 slots per token ======================
__global__ __launch_bounds__(256) void reduce_kernel(float* __restrict__ out) {
    int t = blockIdx.x;
    int s0 = g_tslot[t * 4 + 0], s1 = g_tslot[t * 4 + 1];
    int s2 = g_tslot[t * 4 + 2], s3 = g_tslot[t * 4 + 3];
    const float* p0 = g_slotout + (size_t)s0 * Hn;
    const float* p1 = g_slotout + (size_t)s1 * Hn;
    const float* p2 = g_slotout + (size_t)s2 * Hn;
    const float* p3 = g_slotout + (size_t)s3 * Hn;
    float* o = out + (size_t)t * Hn;
    for (int i = threadIdx.x * 4; i < Hn; i += 256 * 4) {
        float4 a = *(const float4*)(p0 + i);
        float4 b = *(const float4*)(p1 + i);
        float4 c = *(const float4*)(p2 + i);
        float4 d = *(const float4*)(p3 + i);
        *(float4*)(o + i) = make_float4(a.x + b.x + c.x + d.x,
                                        a.y + b.y + c.y + d.y,
                                        a.z + b.z + c.z + d.z,
                                        a.w + b.w + c.w + d.w);
    }
}

// ====================== launcher ======================
extern "C" void kernel_launch(void* const* d_in, const int* in_sizes, int n_in,
                              void* d_out, int out_size) {
    const float* x  = (const float*)d_in[0];
    const float* gw = (const float*)d_in[1];
    const float* wg = (const float*)d_in[2];
    const float* wu = (const float*)d_in[3];
    const float* wd = (const float*)d_in[4];
    float* out = (float*)d_out;

    float* logits_out = nullptr;
    if (out_size >= Tn * Hn + Tn * En) logits_out = out + (size_t)Tn * Hn;

    convert_x_kernel<<<(Tn * Hn) / 1024, 256>>>(x);
    router_kernel<<<Tn / 4, 256>>>(x, gw, logits_out);
    scan_scatter_kernel<<<1, 1024>>>();
    gemm1_kernel<<<dim3(Fn / 64, MAXTILE), 256>>>(wg, wu);
    gemm2_kernel<<<dim3(Hn / 128, MAXTILE), 256>>>(wd);
    reduce_kernel<<<Tn, 256>>>(out);
}